// round 11
// baseline (speedup 1.0000x reference)
#include <cuda_runtime.h>

#define BB 8
#define NP 4096
#define KNN 20
#define ROWS (BB*NP)          // 32768
#define EDGES (ROWS*KNN)      // 655360

typedef unsigned long long ull;

// ---------------- scratch (device globals; no allocations allowed) ----------
static __device__ float    g_dist[(size_t)BB * NP * NP];        // 512 MB (positive d2)
static __device__ int      g_idx[ROWS * KNN];
static __device__ float    g_hA[(size_t)EDGES * 64];            // 160 MB
static __device__ float    g_hB[(size_t)EDGES * 64];            // 160 MB
static __device__ float    g_x1[(size_t)ROWS * 64];
static __device__ float    g_x2[(size_t)ROWS * 64];
static __device__ float    g_x3[(size_t)ROWS * 64];
static __device__ float    g_cat[(size_t)ROWS * 192];
static __device__ unsigned g_hmaxEnc[BB * 1024];
static __device__ unsigned g_hminEnc[BB * 1024];
static __device__ float    g_gmaxv[BB * 1024];
static __device__ float    g_gterm[BB * 512];
static __device__ double   g_sum[8][1024];
static __device__ double   g_sqs[8][1024];

__device__ __forceinline__ float lrelu(float v) { return v > 0.f ? v : 0.2f * v; }
__device__ __forceinline__ unsigned fenc(float f) {
    unsigned u = __float_as_uint(f);
    return (u & 0x80000000u) ? ~u : (u | 0x80000000u);
}
__device__ __forceinline__ float fdec(unsigned u) {
    return (u & 0x80000000u) ? __uint_as_float(u & 0x7fffffffu) : __uint_as_float(~u);
}

// ---- packed f32x2 helpers ----------------------------------------------------
__device__ __forceinline__ ull dup2(float v) {
    ull r; asm("mov.b64 %0, {%1, %1};" : "=l"(r) : "f"(v)); return r;
}
__device__ __forceinline__ ull add2(ull a, ull b) {
    ull r; asm("add.rn.f32x2 %0, %1, %2;" : "=l"(r) : "l"(a), "l"(b)); return r;
}
__device__ __forceinline__ void fma2(ull& d, ull a, ull b) {
    asm("fma.rn.f32x2 %0, %1, %2, %0;" : "+l"(d) : "l"(a), "l"(b));
}
__device__ __forceinline__ void unpack2(ull p, float& lo, float& hi) {
    asm("mov.b64 {%0, %1}, %2;" : "=f"(lo), "=f"(hi) : "l"(p));
}
__device__ __forceinline__ ull umin64(ull a, ull b) { return a < b ? a : b; }

extern __shared__ float dsm[];

// ---------------- zero stats/atomics (must run every replay) ----------------
__global__ void dg_zero_kernel() {
    int i = blockIdx.x * 256 + threadIdx.x;
    if (i < 8192) {
        (&g_sum[0][0])[i] = 0.0;
        (&g_sqs[0][0])[i] = 0.0;
        g_hmaxEnc[i] = 0u;
        g_hminEnc[i] = 0xFFFFFFFFu;
    }
}

// ---------------- kNN on raw xyz: register-resident exact top-20 ------------
__global__ __launch_bounds__(256) void dg_knn_small(const float* __restrict__ x) {
    int q = blockIdx.x, b = q >> 12, i = q & 4095;
    const float* xb = x + (size_t)b * 3 * NP;
    int tid = threadIdx.x, lane = tid & 31, wid = tid >> 5;
    float qx = xb[i], qy = xb[NP + i], qz = xb[2 * NP + i];
    ull key[16];
    #pragma unroll
    for (int u = 0; u < 16; u++) {
        int j = u * 256 + tid;
        float dx = xb[j] - qx, dy = xb[NP + j] - qy, dz = xb[2 * NP + j] - qz;
        float d = dx * dx + dy * dy + dz * dz;
        key[u] = ((ull)__float_as_uint(d) << 32) | (unsigned)j;
    }
    __shared__ ull wmin[8];
    __shared__ ull winner;
    for (int r = 0; r < KNN; r++) {
        ull m = key[0];
        #pragma unroll
        for (int u = 1; u < 16; u++) m = umin64(m, key[u]);
        #pragma unroll
        for (int s = 16; s > 0; s >>= 1) m = umin64(m, __shfl_xor_sync(0xffffffffu, m, s));
        if (lane == 0) wmin[wid] = m;
        __syncthreads();
        if (tid == 0) {
            ull mm = wmin[0];
            #pragma unroll
            for (int w = 1; w < 8; w++) mm = umin64(mm, wmin[w]);
            winner = mm;
            g_idx[q * KNN + r] = (int)(mm & 0xffffffffu);
        }
        __syncthreads();
        ull wn = winner;
        #pragma unroll
        for (int u = 0; u < 16; u++) if (key[u] == wn) key[u] = ~0ull;
        __syncthreads();
    }
}

// ---------------- top-20 select from precomputed positive dist row ----------
__global__ __launch_bounds__(256) void dg_select_kernel() {
    size_t q = blockIdx.x;
    const float* row = g_dist + q * NP;
    int tid = threadIdx.x, lane = tid & 31, wid = tid >> 5;
    ull key[16];
    #pragma unroll
    for (int u = 0; u < 4; u++) {
        int j0 = u * 1024 + tid * 4;
        float4 v = *(const float4*)(row + j0);
        key[u*4+0] = ((ull)__float_as_uint(v.x) << 32) | (unsigned)(j0 + 0);
        key[u*4+1] = ((ull)__float_as_uint(v.y) << 32) | (unsigned)(j0 + 1);
        key[u*4+2] = ((ull)__float_as_uint(v.z) << 32) | (unsigned)(j0 + 2);
        key[u*4+3] = ((ull)__float_as_uint(v.w) << 32) | (unsigned)(j0 + 3);
    }
    __shared__ ull wmin[8];
    __shared__ ull winner;
    for (int r = 0; r < KNN; r++) {
        ull m = key[0];
        #pragma unroll
        for (int u = 1; u < 16; u++) m = umin64(m, key[u]);
        #pragma unroll
        for (int s = 16; s > 0; s >>= 1) m = umin64(m, __shfl_xor_sync(0xffffffffu, m, s));
        if (lane == 0) wmin[wid] = m;
        __syncthreads();
        if (tid == 0) {
            ull mm = wmin[0];
            #pragma unroll
            for (int w = 1; w < 8; w++) mm = umin64(mm, wmin[w]);
            winner = mm;
            g_idx[q * KNN + r] = (int)(mm & 0xffffffffu);
        }
        __syncthreads();
        ull wn = winner;
        #pragma unroll
        for (int u = 0; u < 16; u++) if (key[u] == wn) key[u] = ~0ull;
        __syncthreads();
    }
}

// ---------------- pairwise +||a-b||^2, 128x128 tile, f32x2 inner loop --------
__global__ __launch_bounds__(256) void dg_sqdist128(const float* __restrict__ X,
                                                    float* __restrict__ C) {
    int bz = blockIdx.z;
    const float* A = X + (size_t)bz * NP * 64;
    float* Cb = C + (size_t)bz * NP * NP;
    float* As = dsm;              // [64][132]
    float* Bs = dsm + 64 * 132;   // [64][132] (negated)
    int m0 = blockIdx.y * 128, n0 = blockIdx.x * 128;
    int tid = threadIdx.x;
    {
        int r = tid >> 1, cb = (tid & 1) * 32;
        const float4* pa = (const float4*)(A + (size_t)(m0 + r) * 64 + cb);
        const float4* pb = (const float4*)(A + (size_t)(n0 + r) * 64 + cb);
        #pragma unroll
        for (int i = 0; i < 8; i++) {
            float4 va = pa[i], vb = pb[i];
            int c = cb + i * 4;
            As[(c+0)*132 + r] = va.x; As[(c+1)*132 + r] = va.y;
            As[(c+2)*132 + r] = va.z; As[(c+3)*132 + r] = va.w;
            Bs[(c+0)*132 + r] = -vb.x; Bs[(c+1)*132 + r] = -vb.y;
            Bs[(c+2)*132 + r] = -vb.z; Bs[(c+3)*132 + r] = -vb.w;
        }
    }
    __syncthreads();
    int tx = tid & 15, ty = tid >> 4;
    ull acc2[8][4] = {};
    const ull* BsU = (const ull*)Bs;
    #pragma unroll 4
    for (int k = 0; k < 64; k++) {
        float4 a0 = *(const float4*)&As[k*132 + ty*8];
        float4 a1 = *(const float4*)&As[k*132 + ty*8 + 4];
        const longlong2* pb = (const longlong2*)(BsU + (size_t)k*66 + tx*4);
        longlong2 nbA = pb[0], nbB = pb[1];
        ull nb[4] = {(ull)nbA.x, (ull)nbA.y, (ull)nbB.x, (ull)nbB.y};
        float a[8] = {a0.x, a0.y, a0.z, a0.w, a1.x, a1.y, a1.z, a1.w};
        #pragma unroll
        for (int i = 0; i < 8; i++) {
            ull ad = dup2(a[i]);
            #pragma unroll
            for (int j = 0; j < 4; j++) {
                ull d = add2(ad, nb[j]);
                fma2(acc2[i][j], d, d);
            }
        }
    }
    #pragma unroll
    for (int i = 0; i < 8; i++) {
        float v[8];
        #pragma unroll
        for (int j = 0; j < 4; j++) unpack2(acc2[i][j], v[2*j], v[2*j+1]);
        size_t rowOff = (size_t)(m0 + ty*8 + i) * NP + n0 + tx*8;
        *(float4*)&Cb[rowOff]     = make_float4(v[0], v[1], v[2], v[3]);
        *(float4*)&Cb[rowOff + 4] = make_float4(v[4], v[5], v[6], v[7]);
    }
}

// ---------------- conv1 stats-only (no store) ---------------------------------
__global__ __launch_bounds__(256) void dg_conv1s(const float* __restrict__ x,
                                                 const float* __restrict__ W1) {
    __shared__ float fS[6 * 132];
    __shared__ float Ws[6 * 68];
    __shared__ int qS[128], nbS[128];
    __shared__ float redS[1024], redQ[1024];
    int e0 = blockIdx.x * 128;
    int tid = threadIdx.x;
    if (tid < 128) { int e = e0 + tid; qS[tid] = e / KNN; nbS[tid] = g_idx[e]; }
    for (int l = tid; l < 384; l += 256) {
        int o = l / 6, c = l % 6;
        Ws[c * 68 + o] = W1[l];
    }
    __syncthreads();
    for (int l = tid; l < 1024; l += 256) {
        int r = l >> 3, c = l & 7;
        if (c < 6) {
            int q = qS[r], nb = nbS[r];
            const float* xb = x + (size_t)(q >> 12) * 3 * NP;
            int qi = q & 4095;
            float v = (c < 3) ? (xb[c * NP + nb] - xb[c * NP + qi])
                              : xb[(c - 3) * NP + qi];
            fS[c * 132 + r] = v;
        }
    }
    __syncthreads();
    int tx = tid & 15, ty = tid >> 4;
    float acc[8][4] = {};
    #pragma unroll
    for (int k = 0; k < 6; k++) {
        float a[8], bb[4];
        #pragma unroll
        for (int i = 0; i < 8; i++) a[i] = fS[k*132 + ty*8 + i];
        float4 bv = *(const float4*)&Ws[k*68 + tx*4];
        bb[0]=bv.x; bb[1]=bv.y; bb[2]=bv.z; bb[3]=bv.w;
        #pragma unroll
        for (int i = 0; i < 8; i++)
            #pragma unroll
            for (int j = 0; j < 4; j++)
                acc[i][j] += a[i] * bb[j];
    }
    float s[4] = {}, sq[4] = {};
    #pragma unroll
    for (int i = 0; i < 8; i++)
        #pragma unroll
        for (int j = 0; j < 4; j++) { s[j] += acc[i][j]; sq[j] += acc[i][j]*acc[i][j]; }
    #pragma unroll
    for (int j = 0; j < 4; j++) { redS[ty*64 + tx*4 + j] = s[j]; redQ[ty*64 + tx*4 + j] = sq[j]; }
    __syncthreads();
    if (tid < 64) {
        float S = 0.f, Q = 0.f;
        #pragma unroll
        for (int t = 0; t < 16; t++) { S += redS[t*64 + tid]; Q += redQ[t*64 + tid]; }
        atomicAdd(&g_sum[0][tid], (double)S);
        atomicAdd(&g_sqs[0][tid], (double)Q);
    }
}

// ---------------- fused conv1 -> act0(fin fused) -> econv64(W2) --------------
__global__ __launch_bounds__(256) void dg_econv64f1(const float* __restrict__ x,
                                                    const float* __restrict__ W1,
                                                    const float* __restrict__ W2,
                                                    float* __restrict__ out,
                                                    double invE,
                                                    const float* __restrict__ G1,
                                                    const float* __restrict__ B1) {
    float* fS = dsm;              // [64][132]
    float* Ws = dsm + 64 * 132;   // [64][68]
    __shared__ float fS6[6 * 132];
    __shared__ float Ws1[6 * 68];
    __shared__ int qS[128], nbS[128];
    __shared__ float scS[64], shS[64];
    int e0 = blockIdx.x * 128;
    int tid = threadIdx.x;
    if (tid < 128) { int e = e0 + tid; qS[tid] = e / KNN; nbS[tid] = g_idx[e]; }
    if (tid < 64) {
        double m = g_sum[0][tid] * invE;
        double vv = g_sqs[0][tid] * invE - m * m;
        float sc = G1[tid] * rsqrtf((float)vv + 1e-5f);
        scS[tid] = sc; shS[tid] = B1[tid] - (float)m * sc;
    }
    for (int l = tid; l < 384; l += 256) {
        int o = l / 6, c = l % 6;
        Ws1[c * 68 + o] = W1[l];
    }
    for (int l = tid; l < 4096; l += 256) {
        int c = l >> 6, n = l & 63;
        Ws[c * 68 + n] = W2[n * 64 + c];
    }
    __syncthreads();
    for (int l = tid; l < 1024; l += 256) {
        int r = l >> 3, c = l & 7;
        if (c < 6) {
            int q = qS[r], nb = nbS[r];
            const float* xb = x + (size_t)(q >> 12) * 3 * NP;
            int qi = q & 4095;
            float v = (c < 3) ? (xb[c * NP + nb] - xb[c * NP + qi])
                              : xb[(c - 3) * NP + qi];
            fS6[c * 132 + r] = v;
        }
    }
    __syncthreads();
    int tx = tid & 15, ty = tid >> 4;
    float h[8][4] = {};
    #pragma unroll
    for (int k = 0; k < 6; k++) {
        float a[8], bb[4];
        #pragma unroll
        for (int i = 0; i < 8; i++) a[i] = fS6[k*132 + ty*8 + i];
        float4 bv = *(const float4*)&Ws1[k*68 + tx*4];
        bb[0]=bv.x; bb[1]=bv.y; bb[2]=bv.z; bb[3]=bv.w;
        #pragma unroll
        for (int i = 0; i < 8; i++)
            #pragma unroll
            for (int j = 0; j < 4; j++)
                h[i][j] += a[i] * bb[j];
    }
    #pragma unroll
    for (int i = 0; i < 8; i++)
        #pragma unroll
        for (int j = 0; j < 4; j++) {
            int col = tx*4 + j, row = ty*8 + i;
            fS[col*132 + row] = lrelu(scS[col]*h[i][j] + shS[col]);
        }
    __syncthreads();
    ull acc2[8][2] = {};
    const ull* WsU = (const ull*)Ws;
    #pragma unroll 4
    for (int k = 0; k < 64; k++) {
        float4 a0 = *(const float4*)&fS[k*132 + ty*8];
        float4 a1 = *(const float4*)&fS[k*132 + ty*8 + 4];
        longlong2 wb = *(const longlong2*)(WsU + (size_t)k*34 + tx*2);
        ull b0 = (ull)wb.x, b1 = (ull)wb.y;
        float a[8] = {a0.x, a0.y, a0.z, a0.w, a1.x, a1.y, a1.z, a1.w};
        #pragma unroll
        for (int i = 0; i < 8; i++) {
            ull ad = dup2(a[i]);
            fma2(acc2[i][0], ad, b0);
            fma2(acc2[i][1], ad, b1);
        }
    }
    float s[4] = {}, sq[4] = {};
    #pragma unroll
    for (int i = 0; i < 8; i++) {
        float v[4];
        unpack2(acc2[i][0], v[0], v[1]);
        unpack2(acc2[i][1], v[2], v[3]);
        size_t rowOff = (size_t)(e0 + ty*8 + i) * 64 + tx*4;
        *(float4*)&out[rowOff] = make_float4(v[0], v[1], v[2], v[3]);
        #pragma unroll
        for (int j = 0; j < 4; j++) { s[j] += v[j]; sq[j] += v[j]*v[j]; }
    }
    __syncthreads();
    float* redS = fS;
    float* redQ = fS + 1024;
    #pragma unroll
    for (int j = 0; j < 4; j++) { redS[ty*64 + tx*4 + j] = s[j]; redQ[ty*64 + tx*4 + j] = sq[j]; }
    __syncthreads();
    if (tid < 64) {
        float S = 0.f, Q = 0.f;
        #pragma unroll
        for (int t = 0; t < 16; t++) { S += redS[t*64 + tid]; Q += redQ[t*64 + tid]; }
        atomicAdd(&g_sum[1][tid], (double)S);
        atomicAdd(&g_sqs[1][tid], (double)Q);
    }
}

// ---------------- edge conv 64 -> 64 (act w/ fused finalize; f32x2 core) -----
__global__ __launch_bounds__(256) void dg_econv64(const float* __restrict__ in,
                                                  float* __restrict__ out,
                                                  const float* __restrict__ W,
                                                  int sIn, int sOut, double invE,
                                                  const float* __restrict__ Gi,
                                                  const float* __restrict__ Bi) {
    float* fS = dsm;
    float* Ws = dsm + 64 * 132;
    __shared__ float scS[64], shS[64];
    int e0 = blockIdx.x * 128;
    int tid = threadIdx.x;
    if (tid < 64) {
        double m = g_sum[sIn][tid] * invE;
        double vv = g_sqs[sIn][tid] * invE - m * m;
        float sc = Gi[tid] * rsqrtf((float)vv + 1e-5f);
        scS[tid] = sc; shS[tid] = Bi[tid] - (float)m * sc;
    }
    for (int l = tid; l < 4096; l += 256) {
        int c = l >> 6, n = l & 63;
        Ws[c * 68 + n] = W[n * 64 + c];
    }
    __syncthreads();
    {
        int r = tid >> 1, cb = (tid & 1) * 32;
        const float4* p = (const float4*)(in + (size_t)(e0 + r) * 64 + cb);
        #pragma unroll
        for (int i = 0; i < 8; i++) {
            float4 v = p[i];
            int c = cb + i * 4;
            fS[(c+0)*132 + r] = lrelu(scS[c+0]*v.x + shS[c+0]);
            fS[(c+1)*132 + r] = lrelu(scS[c+1]*v.y + shS[c+1]);
            fS[(c+2)*132 + r] = lrelu(scS[c+2]*v.z + shS[c+2]);
            fS[(c+3)*132 + r] = lrelu(scS[c+3]*v.w + shS[c+3]);
        }
    }
    __syncthreads();
    int tx = tid & 15, ty = tid >> 4;
    ull acc2[8][2] = {};
    const ull* WsU = (const ull*)Ws;
    #pragma unroll 4
    for (int k = 0; k < 64; k++) {
        float4 a0 = *(const float4*)&fS[k*132 + ty*8];
        float4 a1 = *(const float4*)&fS[k*132 + ty*8 + 4];
        longlong2 wb = *(const longlong2*)(WsU + (size_t)k*34 + tx*2);
        ull b0 = (ull)wb.x, b1 = (ull)wb.y;
        float a[8] = {a0.x, a0.y, a0.z, a0.w, a1.x, a1.y, a1.z, a1.w};
        #pragma unroll
        for (int i = 0; i < 8; i++) {
            ull ad = dup2(a[i]);
            fma2(acc2[i][0], ad, b0);
            fma2(acc2[i][1], ad, b1);
        }
    }
    float s[4] = {}, sq[4] = {};
    #pragma unroll
    for (int i = 0; i < 8; i++) {
        float v[4];
        unpack2(acc2[i][0], v[0], v[1]);
        unpack2(acc2[i][1], v[2], v[3]);
        size_t rowOff = (size_t)(e0 + ty*8 + i) * 64 + tx*4;
        *(float4*)&out[rowOff] = make_float4(v[0], v[1], v[2], v[3]);
        #pragma unroll
        for (int j = 0; j < 4; j++) { s[j] += v[j]; sq[j] += v[j]*v[j]; }
    }
    __syncthreads();
    float* redS = fS;
    float* redQ = fS + 1024;
    #pragma unroll
    for (int j = 0; j < 4; j++) { redS[ty*64 + tx*4 + j] = s[j]; redQ[ty*64 + tx*4 + j] = sq[j]; }
    __syncthreads();
    if (tid < 64) {
        float S = 0.f, Q = 0.f;
        #pragma unroll
        for (int t = 0; t < 16; t++) { S += redS[t*64 + tid]; Q += redQ[t*64 + tid]; }
        atomicAdd(&g_sum[sOut][tid], (double)S);
        atomicAdd(&g_sqs[sOut][tid], (double)Q);
    }
}

// ---------------- edge conv 128 -> 64 as GEMM, gather, f32x2 core ------------
__global__ __launch_bounds__(256) void dg_econv128(const float* __restrict__ xin,
                                                   float* __restrict__ out,
                                                   const float* __restrict__ W,
                                                   int sOut) {
    float* fS = dsm;
    float* Ws = dsm + 64 * 132;
    __shared__ int qS[128], nbS[128];
    int e0 = blockIdx.x * 128;
    int tid = threadIdx.x;
    if (tid < 128) {
        int e = e0 + tid;
        int q = e / KNN;
        qS[tid] = q;
        nbS[tid] = (q >> 12) * NP + g_idx[e];
    }
    __syncthreads();
    int tx = tid & 15, ty = tid >> 4;
    ull acc2[8][2] = {};
    const ull* WsU = (const ull*)Ws;
    for (int kt = 0; kt < 2; kt++) {
        int r = tid >> 1, cb = (tid & 1) * 32;
        int q = qS[r];
        const float4* pq = (const float4*)(xin + (size_t)q * 64 + cb);
        if (kt == 0) {
            const float4* pn = (const float4*)(xin + (size_t)nbS[r] * 64 + cb);
            #pragma unroll
            for (int i = 0; i < 8; i++) {
                float4 vn = pn[i], vq = pq[i];
                int c = cb + i * 4;
                fS[(c+0)*132 + r] = vn.x - vq.x;
                fS[(c+1)*132 + r] = vn.y - vq.y;
                fS[(c+2)*132 + r] = vn.z - vq.z;
                fS[(c+3)*132 + r] = vn.w - vq.w;
            }
        } else {
            #pragma unroll
            for (int i = 0; i < 8; i++) {
                float4 vq = pq[i];
                int c = cb + i * 4;
                fS[(c+0)*132 + r] = vq.x;
                fS[(c+1)*132 + r] = vq.y;
                fS[(c+2)*132 + r] = vq.z;
                fS[(c+3)*132 + r] = vq.w;
            }
        }
        for (int l = tid; l < 4096; l += 256) {
            int c = l >> 6, n = l & 63;
            Ws[c * 68 + n] = W[n * 128 + kt * 64 + c];
        }
        __syncthreads();
        #pragma unroll 4
        for (int k = 0; k < 64; k++) {
            float4 a0 = *(const float4*)&fS[k*132 + ty*8];
            float4 a1 = *(const float4*)&fS[k*132 + ty*8 + 4];
            longlong2 wb = *(const longlong2*)(WsU + (size_t)k*34 + tx*2);
            ull b0 = (ull)wb.x, b1 = (ull)wb.y;
            float a[8] = {a0.x, a0.y, a0.z, a0.w, a1.x, a1.y, a1.z, a1.w};
            #pragma unroll
            for (int i = 0; i < 8; i++) {
                ull ad = dup2(a[i]);
                fma2(acc2[i][0], ad, b0);
                fma2(acc2[i][1], ad, b1);
            }
        }
        __syncthreads();
    }
    float s[4] = {}, sq[4] = {};
    #pragma unroll
    for (int i = 0; i < 8; i++) {
        float v[4];
        unpack2(acc2[i][0], v[0], v[1]);
        unpack2(acc2[i][1], v[2], v[3]);
        size_t rowOff = (size_t)(e0 + ty*8 + i) * 64 + tx*4;
        *(float4*)&out[rowOff] = make_float4(v[0], v[1], v[2], v[3]);
        #pragma unroll
        for (int j = 0; j < 4; j++) { s[j] += v[j]; sq[j] += v[j]*v[j]; }
    }
    float* redS = fS;
    float* redQ = fS + 1024;
    #pragma unroll
    for (int j = 0; j < 4; j++) { redS[ty*64 + tx*4 + j] = s[j]; redQ[ty*64 + tx*4 + j] = sq[j]; }
    __syncthreads();
    if (tid < 64) {
        float S = 0.f, Q = 0.f;
        #pragma unroll
        for (int t = 0; t < 16; t++) { S += redS[t*64 + tid]; Q += redQ[t*64 + tid]; }
        atomicAdd(&g_sum[sOut][tid], (double)S);
        atomicAdd(&g_sqs[sOut][tid], (double)Q);
    }
}

// ---------------- max over k neighbors (finalize fused) ----------------------
__global__ __launch_bounds__(256) void dg_maxk(const float* __restrict__ hraw,
                                               float* __restrict__ xout, int stage,
                                               double invE,
                                               const float* __restrict__ Gi,
                                               const float* __restrict__ Bi) {
    __shared__ float scS[64], shS[64];
    int tid = threadIdx.x;
    if (tid < 64) {
        double m = g_sum[stage][tid] * invE;
        double vv = g_sqs[stage][tid] * invE - m * m;
        float sc = Gi[tid] * rsqrtf((float)vv + 1e-5f);
        scS[tid] = sc; shS[tid] = Bi[tid] - (float)m * sc;
    }
    __syncthreads();
    int t = tid & 63;
    int q = blockIdx.x * 4 + (tid >> 6);
    float s = scS[t], sh = shS[t];
    float m = -3.4e38f;
    for (int j = 0; j < KNN; j++) {
        float v = lrelu(hraw[((size_t)q * KNN + j) * 64 + t] * s + sh);
        m = fmaxf(m, v);
    }
    xout[(size_t)q * 64 + t] = m;
}

// ---------------- concat x1|x2|x3 --------------------------------------------
__global__ void dg_cat_kernel() {
    int i = blockIdx.x * 256 + threadIdx.x;
    if (i >= ROWS * 192) return;
    int r = i / 192, c = i % 192;
    float v = (c < 64)  ? g_x1[(size_t)r * 64 + c]
            : (c < 128) ? g_x2[(size_t)r * 64 + c - 64]
                        : g_x3[(size_t)r * 64 + c - 128];
    g_cat[i] = v;
}

// ---------------- 128x128 tiled GEMM, f32x2 core, fused epilogues ------------
// MODE bit0: act(actStage, finalize fused) on A; bit1: +gterm;
// bit2: stats(statStage); bit3: per-(batch,ch) raw max/min; bit4: skip C store.
template <int MODE>
__global__ __launch_bounds__(256) void dg_gemm128(
    const float* __restrict__ A,
    const float* __restrict__ W, int ldw,
    float* __restrict__ C,
    int Nn, int Kk, int actStage, int statStage,
    double invAct, const float* __restrict__ Ga, const float* __restrict__ Ba) {
    __shared__ float As[32 * 132];
    __shared__ float Ws2[32 * 132];
    __shared__ float scA[512], shA[512];
    int m0 = blockIdx.y * 128, n0 = blockIdx.x * 128;
    int tid = threadIdx.x, tx = tid & 15, ty = tid >> 4;
    if (MODE & 1) {
        for (int c = tid; c < Kk; c += 256) {
            double m = g_sum[actStage][c] * invAct;
            double vv = g_sqs[actStage][c] * invAct - m * m;
            float sc = Ga[c] * rsqrtf((float)vv + 1e-5f);
            scA[c] = sc; shA[c] = Ba[c] - (float)m * sc;
        }
        __syncthreads();
    }
    ull acc2[8][4] = {};
    const ull* WsU = (const ull*)Ws2;
    for (int k0 = 0; k0 < Kk; k0 += 32) {
        int r = tid >> 1, cb = (tid & 1) * 16;
        const float4* pa = (const float4*)(A + (size_t)(m0 + r) * Kk + k0 + cb);
        const float4* pw = (const float4*)(W + (size_t)(n0 + r) * ldw + k0 + cb);
        #pragma unroll
        for (int i = 0; i < 4; i++) {
            float4 v = pa[i];
            int c = cb + i * 4;
            if (MODE & 1) {
                v.x = lrelu(scA[k0+c+0]*v.x + shA[k0+c+0]);
                v.y = lrelu(scA[k0+c+1]*v.y + shA[k0+c+1]);
                v.z = lrelu(scA[k0+c+2]*v.z + shA[k0+c+2]);
                v.w = lrelu(scA[k0+c+3]*v.w + shA[k0+c+3]);
            }
            As[(c+0)*132 + r] = v.x; As[(c+1)*132 + r] = v.y;
            As[(c+2)*132 + r] = v.z; As[(c+3)*132 + r] = v.w;
            float4 w = pw[i];
            Ws2[(c+0)*132 + r] = w.x; Ws2[(c+1)*132 + r] = w.y;
            Ws2[(c+2)*132 + r] = w.z; Ws2[(c+3)*132 + r] = w.w;
        }
        __syncthreads();
        #pragma unroll 4
        for (int k = 0; k < 32; k++) {
            float4 a0 = *(const float4*)&As[k*132 + ty*8];
            float4 a1 = *(const float4*)&As[k*132 + ty*8 + 4];
            const longlong2* pb = (const longlong2*)(WsU + (size_t)k*66 + tx*4);
            longlong2 wbA = pb[0], wbB = pb[1];
            ull wb[4] = {(ull)wbA.x, (ull)wbA.y, (ull)wbB.x, (ull)wbB.y};
            float a[8] = {a0.x, a0.y, a0.z, a0.w, a1.x, a1.y, a1.z, a1.w};
            #pragma unroll
            for (int i = 0; i < 8; i++) {
                ull ad = dup2(a[i]);
                #pragma unroll
                for (int j = 0; j < 4; j++) fma2(acc2[i][j], ad, wb[j]);
            }
        }
        __syncthreads();
    }
    float colS[8] = {}, colQ[8] = {};
    float colMx[8], colMn[8];
    #pragma unroll
    for (int j = 0; j < 8; j++) { colMx[j] = -3.4e38f; colMn[j] = 3.4e38f; }
    #pragma unroll
    for (int i = 0; i < 8; i++) {
        int m = m0 + ty*8 + i;
        float v[8];
        #pragma unroll
        for (int j = 0; j < 4; j++) unpack2(acc2[i][j], v[2*j], v[2*j+1]);
        if (MODE & 2) {
            #pragma unroll
            for (int j = 0; j < 8; j++) v[j] += g_gterm[(m >> 12) * Nn + n0 + tx*8 + j];
        }
        if (!(MODE & 16)) {
            size_t rowOff = (size_t)m * Nn + n0 + tx*8;
            *(float4*)&C[rowOff]     = make_float4(v[0], v[1], v[2], v[3]);
            *(float4*)&C[rowOff + 4] = make_float4(v[4], v[5], v[6], v[7]);
        }
        #pragma unroll
        for (int j = 0; j < 8; j++) {
            colS[j] += v[j]; colQ[j] += v[j]*v[j];
            colMx[j] = fmaxf(colMx[j], v[j]);
            colMn[j] = fminf(colMn[j], v[j]);
        }
    }
    if (MODE & 4) {
        __syncthreads();
        #pragma unroll
        for (int j = 0; j < 8; j++) {
            As[ty*128 + tx*8 + j]  = colS[j];
            Ws2[ty*128 + tx*8 + j] = colQ[j];
        }
        __syncthreads();
        if (tid < 128) {
            float S = 0.f, Q = 0.f;
            #pragma unroll
            for (int t = 0; t < 16; t++) { S += As[t*128 + tid]; Q += Ws2[t*128 + tid]; }
            atomicAdd(&g_sum[statStage][n0 + tid], (double)S);
            atomicAdd(&g_sqs[statStage][n0 + tid], (double)Q);
        }
        if (MODE & 8) {
            __syncthreads();
            #pragma unroll
            for (int j = 0; j < 8; j++) {
                As[ty*128 + tx*8 + j]  = colMx[j];
                Ws2[ty*128 + tx*8 + j] = colMn[j];
            }
            __syncthreads();
            if (tid < 128) {
                float Mx = -3.4e38f, Mn = 3.4e38f;
                #pragma unroll
                for (int t = 0; t < 16; t++) {
                    Mx = fmaxf(Mx, As[t*128 + tid]);
                    Mn = fminf(Mn, Ws2[t*128 + tid]);
                }
                int b = m0 >> 12;
                atomicMax(&g_hmaxEnc[b * 1024 + n0 + tid], fenc(Mx));
                atomicMin(&g_hminEnc[b * 1024 + n0 + tid], fenc(Mn));
            }
        }
    }
}

// ---------------- global-max finalize (fin5 fused) ---------------------------
__global__ __launch_bounds__(1024) void dg_gmaxfin(double invR,
                                                   const float* __restrict__ G6,
                                                   const float* __restrict__ B6) {
    int b = blockIdx.x, e = threadIdx.x;
    double m = g_sum[5][e] * invR;
    double vv = g_sqs[5][e] * invR - m * m;
    float s = G6[e] * rsqrtf((float)vv + 1e-5f);
    float t = B6[e] - (float)m * s;
    float mx = fdec(g_hmaxEnc[b * 1024 + e]);
    float mn = fdec(g_hminEnc[b * 1024 + e]);
    g_gmaxv[b * 1024 + e] = lrelu(s * (s >= 0.f ? mx : mn) + t);
}

// ---------------- gterm[b,o] = sum_e gmax[b,e] * W7[o,e] ---------------------
__global__ __launch_bounds__(512) void dg_gterm_kernel(const float* __restrict__ W7) {
    int b = blockIdx.x, o = threadIdx.x;
    float acc = 0.f;
    for (int e = 0; e < 1024; e++)
        acc += g_gmaxv[b * 1024 + e] * W7[(size_t)o * 1216 + e];
    g_gterm[b * 512 + o] = acc;
}

// ---------------- final classifier (fin7 fused) ------------------------------
__global__ __launch_bounds__(288) void dg_final(const float* __restrict__ W9,
                                                float* __restrict__ out,
                                                double invR,
                                                const float* __restrict__ G8,
                                                const float* __restrict__ B8) {
    __shared__ float a[32 * 257];
    __shared__ float w[9 * 259];
    __shared__ float scS[256], shS[256];
    int tid = threadIdx.x;
    if (tid < 256) {
        double m = g_sum[7][tid] * invR;
        double vv = g_sqs[7][tid] * invR - m * m;
        float sc = G8[tid] * rsqrtf((float)vv + 1e-5f);
        scS[tid] = sc; shS[tid] = B8[tid] - (float)m * sc;
    }
    for (int l = tid; l < 2304; l += 288) {
        int o = l / 256, c = l % 256;
        w[o * 259 + c] = W9[l];
    }
    __syncthreads();
    int r0 = blockIdx.x * 32;
    for (int l = tid; l < 32 * 256; l += 288) {
        int rr = l / 256, c = l % 256;
        float v = g_hB[(size_t)(r0 + rr) * 256 + c];
        a[rr * 257 + c] = lrelu(scS[c] * v + shS[c]);
    }
    __syncthreads();
    int rr = tid / 9, o = tid % 9;
    float acc = 0.f;
    #pragma unroll 16
    for (int c = 0; c < 256; c++) acc += a[rr * 257 + c] * w[o * 259 + c];
    out[(size_t)(r0 + rr) * 9 + o] = acc;
}

// ---------------- host orchestration -----------------------------------------
extern "C" void kernel_launch(void* const* d_in, const int* in_sizes, int n_in,
                              void* d_out, int out_size) {
    const float* x = (const float*)d_in[0];
    const float* W[10] = {0};
    const float* G[9] = {0};
    const float* Bp[9] = {0};
    if (n_in >= 27 && in_sizes[1] == 1) {
        for (int i = 1; i <= 9; i++) W[i] = (const float*)d_in[1 + i];
        for (int i = 1; i <= 8; i++) {
            G[i]  = (const float*)d_in[11 + 2 * (i - 1)];
            Bp[i] = (const float*)d_in[12 + 2 * (i - 1)];
        }
    } else {
        for (int i = 1; i <= 9; i++) W[i] = (const float*)d_in[i];
        for (int i = 1; i <= 8; i++) {
            G[i]  = (const float*)d_in[10 + 2 * (i - 1)];
            Bp[i] = (const float*)d_in[11 + 2 * (i - 1)];
        }
    }
    float* out = (float*)d_out;

    void* tmp;
    cudaGetSymbolAddress(&tmp, g_dist);  float* dist = (float*)tmp;
    cudaGetSymbolAddress(&tmp, g_hA);    float* hA   = (float*)tmp;
    cudaGetSymbolAddress(&tmp, g_hB);    float* hB   = (float*)tmp;
    cudaGetSymbolAddress(&tmp, g_x1);    float* x1   = (float*)tmp;
    cudaGetSymbolAddress(&tmp, g_x2);    float* x2   = (float*)tmp;
    cudaGetSymbolAddress(&tmp, g_x3);    float* x3   = (float*)tmp;
    cudaGetSymbolAddress(&tmp, g_cat);   float* cat  = (float*)tmp;

    const int SQ_SMEM = 2 * 64 * 132 * 4;                 // 67584
    const int EC_SMEM = (64 * 132 + 64 * 68) * 4;         // 51200
    cudaFuncSetAttribute(dg_sqdist128, cudaFuncAttributeMaxDynamicSharedMemorySize, SQ_SMEM);
    cudaFuncSetAttribute(dg_econv64,   cudaFuncAttributeMaxDynamicSharedMemorySize, EC_SMEM);
    cudaFuncSetAttribute(dg_econv64f1, cudaFuncAttributeMaxDynamicSharedMemorySize, EC_SMEM);
    cudaFuncSetAttribute(dg_econv128,  cudaFuncAttributeMaxDynamicSharedMemorySize, EC_SMEM);

    const double invE = 1.0 / (double)EDGES;
    const double invR = 1.0 / (double)ROWS;
    const int EB = EDGES / 128;

    dg_zero_kernel<<<32, 256>>>();                                             // 1
    // ---- block 1 (xyz) ----
    dg_knn_small<<<ROWS, 256>>>(x);                                            // 2
    dg_conv1s<<<EB, 256>>>(x, W[1]);                                           // 3
    dg_econv64f1<<<EB, 256, EC_SMEM>>>(x, W[1], W[2], hB, invE, G[1], Bp[1]);  // 4 (profiled)
    dg_maxk<<<ROWS / 4, 256>>>(hB, x1, 1, invE, G[2], Bp[2]);                  // 5

    // ---- block 2 (x1) ----
    dg_sqdist128<<<dim3(NP / 128, NP / 128, BB), 256, SQ_SMEM>>>(x1, dist);    // 6
    dg_select_kernel<<<ROWS, 256>>>();                                         // 7
    dg_econv128<<<EB, 256, EC_SMEM>>>(x1, hA, W[3], 2);                        // 8
    dg_econv64<<<EB, 256, EC_SMEM>>>(hA, hB, W[4], 2, 3, invE, G[3], Bp[3]);   // 9
    dg_maxk<<<ROWS / 4, 256>>>(hB, x2, 3, invE, G[4], Bp[4]);                  // 10

    // ---- block 3 (x2) ----
    dg_sqdist128<<<dim3(NP / 128, NP / 128, BB), 256, SQ_SMEM>>>(x2, dist);    // 11
    dg_select_kernel<<<ROWS, 256>>>();                                         // 12
    dg_econv128<<<EB, 256, EC_SMEM>>>(x2, hA, W[5], 4);                        // 13
    dg_maxk<<<ROWS / 4, 256>>>(hA, x3, 4, invE, G[5], Bp[5]);                  // 14

    // ---- point MLPs ----
    dg_cat_kernel<<<(ROWS * 192 + 255) / 256, 256>>>();                        // 15
    dg_gemm128<4|8|16><<<dim3(8, ROWS / 128), 256>>>(
        cat, W[6], 192, hA, 1024, 192, -1, 5, 0.0, 0, 0);                      // 16
    dg_gmaxfin<<<BB, 1024>>>(invR, G[6], Bp[6]);                               // 17
    dg_gterm_kernel<<<BB, 512>>>(W[7]);                                        // 18
    dg_gemm128<2|4><<<dim3(4, ROWS / 128), 256>>>(
        cat, W[7] + 1024, 1216, hA, 512, 192, -1, 6, 0.0, 0, 0);               // 19
    dg_gemm128<1|4><<<dim3(2, ROWS / 128), 256>>>(
        hA, W[8], 512, hB, 256, 512, 6, 7, invR, G[7], Bp[7]);                 // 20
    dg_final<<<ROWS / 32, 288>>>(W[9], out, invR, G[8], Bp[8]);                // 21
}

// round 12
// speedup vs baseline: 1.3000x; 1.3000x over previous
#include <cuda_runtime.h>

#define BB 8
#define NP 4096
#define KNN 20
#define ROWS (BB*NP)          // 32768
#define EDGES (ROWS*KNN)      // 655360

typedef unsigned long long ull;

// ---------------- scratch (device globals; no allocations allowed) ----------
static __device__ float    g_negd[(size_t)BB * NP * NP];        // 512 MB
static __device__ int      g_idx[ROWS * KNN];
static __device__ float    g_hA[(size_t)EDGES * 64];            // 160 MB
static __device__ float    g_hB[(size_t)EDGES * 64];            // 160 MB
static __device__ float    g_x1[(size_t)ROWS * 64];
static __device__ float    g_x2[(size_t)ROWS * 64];
static __device__ float    g_x3[(size_t)ROWS * 64];
static __device__ float    g_cat[(size_t)ROWS * 192];
static __device__ unsigned g_hmaxEnc[BB * 1024];
static __device__ unsigned g_hminEnc[BB * 1024];
static __device__ float    g_gmaxv[BB * 1024];
static __device__ float    g_gterm[BB * 512];
static __device__ double   g_sum[8][1024];
static __device__ double   g_sqs[8][1024];

__device__ __forceinline__ float lrelu(float v) { return v > 0.f ? v : 0.2f * v; }
__device__ __forceinline__ unsigned fenc(float f) {
    unsigned u = __float_as_uint(f);
    return (u & 0x80000000u) ? ~u : (u | 0x80000000u);
}
__device__ __forceinline__ float fdec(unsigned u) {
    return (u & 0x80000000u) ? __uint_as_float(u & 0x7fffffffu) : __uint_as_float(~u);
}

// ---- packed f32x2 helpers ----------------------------------------------------
__device__ __forceinline__ ull dup2(float v) {
    ull r; asm("mov.b64 %0, {%1, %1};" : "=l"(r) : "f"(v)); return r;
}
__device__ __forceinline__ ull add2(ull a, ull b) {
    ull r; asm("add.rn.f32x2 %0, %1, %2;" : "=l"(r) : "l"(a), "l"(b)); return r;
}
__device__ __forceinline__ void fma2(ull& d, ull a, ull b) {
    asm("fma.rn.f32x2 %0, %1, %2, %0;" : "+l"(d) : "l"(a), "l"(b));
}
__device__ __forceinline__ void unpack2(ull p, float& lo, float& hi) {
    asm("mov.b64 {%0, %1}, %2;" : "=f"(lo), "=f"(hi) : "l"(p));
}

extern __shared__ float dsm[];

// ---------------- zero stats/atomics (must run every replay) ----------------
__global__ void dg_zero_kernel() {
    int i = blockIdx.x * 256 + threadIdx.x;
    if (i < 8192) {
        (&g_sum[0][0])[i] = 0.0;
        (&g_sqs[0][0])[i] = 0.0;
        g_hmaxEnc[i] = 0u;
        g_hminEnc[i] = 0xFFFFFFFFu;
    }
}

// ---------------- kNN on raw xyz (R7-proven smem version) -------------------
__global__ __launch_bounds__(256) void dg_knn_small(const float* __restrict__ x) {
    int q = blockIdx.x;
    int b = q >> 12, i = q & 4095;
    const float* xb = x + (size_t)b * 3 * NP;
    __shared__ float sd[NP];
    __shared__ float rv[8];
    __shared__ int   ri[8];
    int tid = threadIdx.x, lane = tid & 31, wid = tid >> 5;
    float qx = xb[i], qy = xb[NP + i], qz = xb[2 * NP + i];
    for (int j = tid; j < NP; j += 256) {
        float dx = xb[j] - qx, dy = xb[NP + j] - qy, dz = xb[2 * NP + j] - qz;
        sd[j] = -(dx * dx + dy * dy + dz * dz);
    }
    __syncthreads();
    for (int r = 0; r < KNN; r++) {
        float bv = -3.4e38f; int bi = 0x7fffffff;
        for (int j = tid; j < NP; j += 256) {
            float v = sd[j];
            if (v > bv) { bv = v; bi = j; }
        }
        for (int s = 16; s > 0; s >>= 1) {
            float ov = __shfl_xor_sync(0xffffffffu, bv, s);
            int   oi = __shfl_xor_sync(0xffffffffu, bi, s);
            if (ov > bv || (ov == bv && oi < bi)) { bv = ov; bi = oi; }
        }
        if (lane == 0) { rv[wid] = bv; ri[wid] = bi; }
        __syncthreads();
        if (tid == 0) {
            float bbv = rv[0]; int bbi = ri[0];
            for (int w = 1; w < 8; w++)
                if (rv[w] > bbv || (rv[w] == bbv && ri[w] < bbi)) { bbv = rv[w]; bbi = ri[w]; }
            g_idx[q * KNN + r] = bbi;
            sd[bbi] = -3.4e38f;
        }
        __syncthreads();
    }
}

// ---------------- top-k selection from precomputed neg_d (R7 version) -------
__global__ __launch_bounds__(256) void dg_select_kernel() {
    int q = blockIdx.x;
    __shared__ float sd[NP];
    __shared__ float rv[8];
    __shared__ int   ri[8];
    const float* row = g_negd + (size_t)q * NP;
    int tid = threadIdx.x, lane = tid & 31, wid = tid >> 5;
    for (int j = tid; j < NP; j += 256) sd[j] = row[j];
    __syncthreads();
    for (int r = 0; r < KNN; r++) {
        float bv = -3.4e38f; int bi = 0x7fffffff;
        for (int j = tid; j < NP; j += 256) {
            float v = sd[j];
            if (v > bv) { bv = v; bi = j; }
        }
        for (int s = 16; s > 0; s >>= 1) {
            float ov = __shfl_xor_sync(0xffffffffu, bv, s);
            int   oi = __shfl_xor_sync(0xffffffffu, bi, s);
            if (ov > bv || (ov == bv && oi < bi)) { bv = ov; bi = oi; }
        }
        if (lane == 0) { rv[wid] = bv; ri[wid] = bi; }
        __syncthreads();
        if (tid == 0) {
            float bbv = rv[0]; int bbi = ri[0];
            for (int w = 1; w < 8; w++)
                if (rv[w] > bbv || (rv[w] == bbv && ri[w] < bbi)) { bbv = rv[w]; bbi = ri[w]; }
            g_idx[q * KNN + r] = bbi;
            sd[bbi] = -3.4e38f;
        }
        __syncthreads();
    }
}

// ---------------- pairwise -||a-b||^2, 128x128 tile, f32x2 (R7 version) ------
__global__ __launch_bounds__(256) void dg_sqdist128(const float* __restrict__ X,
                                                    float* __restrict__ C) {
    int bz = blockIdx.z;
    const float* A = X + (size_t)bz * NP * 64;
    float* Cb = C + (size_t)bz * NP * NP;
    float* As = dsm;              // [64][132]
    float* Bs = dsm + 64 * 132;   // [64][132] (negated)
    int m0 = blockIdx.y * 128, n0 = blockIdx.x * 128;
    int tid = threadIdx.x;
    {
        int r = tid >> 1, cb = (tid & 1) * 32;
        const float4* pa = (const float4*)(A + (size_t)(m0 + r) * 64 + cb);
        const float4* pb = (const float4*)(A + (size_t)(n0 + r) * 64 + cb);
        #pragma unroll
        for (int i = 0; i < 8; i++) {
            float4 va = pa[i], vb = pb[i];
            int c = cb + i * 4;
            As[(c+0)*132 + r] = va.x; As[(c+1)*132 + r] = va.y;
            As[(c+2)*132 + r] = va.z; As[(c+3)*132 + r] = va.w;
            Bs[(c+0)*132 + r] = -vb.x; Bs[(c+1)*132 + r] = -vb.y;
            Bs[(c+2)*132 + r] = -vb.z; Bs[(c+3)*132 + r] = -vb.w;
        }
    }
    __syncthreads();
    int tx = tid & 15, ty = tid >> 4;
    ull acc2[8][4] = {};
    const ull* BsU = (const ull*)Bs;
    #pragma unroll 4
    for (int k = 0; k < 64; k++) {
        float4 a0 = *(const float4*)&As[k*132 + ty*8];
        float4 a1 = *(const float4*)&As[k*132 + ty*8 + 4];
        const longlong2* pb = (const longlong2*)(BsU + (size_t)k*66 + tx*4);
        longlong2 nbA = pb[0], nbB = pb[1];
        ull nb[4] = {(ull)nbA.x, (ull)nbA.y, (ull)nbB.x, (ull)nbB.y};
        float a[8] = {a0.x, a0.y, a0.z, a0.w, a1.x, a1.y, a1.z, a1.w};
        #pragma unroll
        for (int i = 0; i < 8; i++) {
            ull ad = dup2(a[i]);
            #pragma unroll
            for (int j = 0; j < 4; j++) {
                ull d = add2(ad, nb[j]);
                fma2(acc2[i][j], d, d);
            }
        }
    }
    #pragma unroll
    for (int i = 0; i < 8; i++) {
        float v[8];
        #pragma unroll
        for (int j = 0; j < 4; j++) unpack2(acc2[i][j], v[2*j], v[2*j+1]);
        size_t rowOff = (size_t)(m0 + ty*8 + i) * NP + n0 + tx*8;
        *(float4*)&Cb[rowOff]     = make_float4(-v[0], -v[1], -v[2], -v[3]);
        *(float4*)&Cb[rowOff + 4] = make_float4(-v[4], -v[5], -v[6], -v[7]);
    }
}

// ---------------- conv1 stats-only (no store) ---------------------------------
__global__ __launch_bounds__(256) void dg_conv1s(const float* __restrict__ x,
                                                 const float* __restrict__ W1) {
    __shared__ float fS[6 * 132];
    __shared__ float Ws[6 * 68];
    __shared__ int qS[128], nbS[128];
    __shared__ float redS[1024], redQ[1024];
    int e0 = blockIdx.x * 128;
    int tid = threadIdx.x;
    if (tid < 128) { int e = e0 + tid; qS[tid] = e / KNN; nbS[tid] = g_idx[e]; }
    for (int l = tid; l < 384; l += 256) {
        int o = l / 6, c = l % 6;
        Ws[c * 68 + o] = W1[l];
    }
    __syncthreads();
    for (int l = tid; l < 1024; l += 256) {
        int r = l >> 3, c = l & 7;
        if (c < 6) {
            int q = qS[r], nb = nbS[r];
            const float* xb = x + (size_t)(q >> 12) * 3 * NP;
            int qi = q & 4095;
            float v = (c < 3) ? (xb[c * NP + nb] - xb[c * NP + qi])
                              : xb[(c - 3) * NP + qi];
            fS[c * 132 + r] = v;
        }
    }
    __syncthreads();
    int tx = tid & 15, ty = tid >> 4;
    float acc[8][4] = {};
    #pragma unroll
    for (int k = 0; k < 6; k++) {
        float a[8], bb[4];
        #pragma unroll
        for (int i = 0; i < 8; i++) a[i] = fS[k*132 + ty*8 + i];
        float4 bv = *(const float4*)&Ws[k*68 + tx*4];
        bb[0]=bv.x; bb[1]=bv.y; bb[2]=bv.z; bb[3]=bv.w;
        #pragma unroll
        for (int i = 0; i < 8; i++)
            #pragma unroll
            for (int j = 0; j < 4; j++)
                acc[i][j] += a[i] * bb[j];
    }
    float s[4] = {}, sq[4] = {};
    #pragma unroll
    for (int i = 0; i < 8; i++)
        #pragma unroll
        for (int j = 0; j < 4; j++) { s[j] += acc[i][j]; sq[j] += acc[i][j]*acc[i][j]; }
    #pragma unroll
    for (int j = 0; j < 4; j++) { redS[ty*64 + tx*4 + j] = s[j]; redQ[ty*64 + tx*4 + j] = sq[j]; }
    __syncthreads();
    if (tid < 64) {
        float S = 0.f, Q = 0.f;
        #pragma unroll
        for (int t = 0; t < 16; t++) { S += redS[t*64 + tid]; Q += redQ[t*64 + tid]; }
        atomicAdd(&g_sum[0][tid], (double)S);
        atomicAdd(&g_sqs[0][tid], (double)Q);
    }
}

// ---------------- fused conv1 -> act0(fin fused) -> econv64(W2) --------------
__global__ __launch_bounds__(256) void dg_econv64f1(const float* __restrict__ x,
                                                    const float* __restrict__ W1,
                                                    const float* __restrict__ W2,
                                                    float* __restrict__ out,
                                                    double invE,
                                                    const float* __restrict__ G1,
                                                    const float* __restrict__ B1) {
    float* fS = dsm;              // [64][132]
    float* Ws = dsm + 64 * 132;   // [64][68]
    __shared__ float fS6[6 * 132];
    __shared__ float Ws1[6 * 68];
    __shared__ int qS[128], nbS[128];
    __shared__ float scS[64], shS[64];
    int e0 = blockIdx.x * 128;
    int tid = threadIdx.x;
    if (tid < 128) { int e = e0 + tid; qS[tid] = e / KNN; nbS[tid] = g_idx[e]; }
    if (tid < 64) {
        double m = g_sum[0][tid] * invE;
        double vv = g_sqs[0][tid] * invE - m * m;
        float sc = G1[tid] * rsqrtf((float)vv + 1e-5f);
        scS[tid] = sc; shS[tid] = B1[tid] - (float)m * sc;
    }
    for (int l = tid; l < 384; l += 256) {
        int o = l / 6, c = l % 6;
        Ws1[c * 68 + o] = W1[l];
    }
    for (int l = tid; l < 4096; l += 256) {
        int c = l >> 6, n = l & 63;
        Ws[c * 68 + n] = W2[n * 64 + c];
    }
    __syncthreads();
    for (int l = tid; l < 1024; l += 256) {
        int r = l >> 3, c = l & 7;
        if (c < 6) {
            int q = qS[r], nb = nbS[r];
            const float* xb = x + (size_t)(q >> 12) * 3 * NP;
            int qi = q & 4095;
            float v = (c < 3) ? (xb[c * NP + nb] - xb[c * NP + qi])
                              : xb[(c - 3) * NP + qi];
            fS6[c * 132 + r] = v;
        }
    }
    __syncthreads();
    int tx = tid & 15, ty = tid >> 4;
    float h[8][4] = {};
    #pragma unroll
    for (int k = 0; k < 6; k++) {
        float a[8], bb[4];
        #pragma unroll
        for (int i = 0; i < 8; i++) a[i] = fS6[k*132 + ty*8 + i];
        float4 bv = *(const float4*)&Ws1[k*68 + tx*4];
        bb[0]=bv.x; bb[1]=bv.y; bb[2]=bv.z; bb[3]=bv.w;
        #pragma unroll
        for (int i = 0; i < 8; i++)
            #pragma unroll
            for (int j = 0; j < 4; j++)
                h[i][j] += a[i] * bb[j];
    }
    #pragma unroll
    for (int i = 0; i < 8; i++)
        #pragma unroll
        for (int j = 0; j < 4; j++) {
            int col = tx*4 + j, row = ty*8 + i;
            fS[col*132 + row] = lrelu(scS[col]*h[i][j] + shS[col]);
        }
    __syncthreads();
    ull acc2[8][2] = {};
    const ull* WsU = (const ull*)Ws;
    #pragma unroll 4
    for (int k = 0; k < 64; k++) {
        float4 a0 = *(const float4*)&fS[k*132 + ty*8];
        float4 a1 = *(const float4*)&fS[k*132 + ty*8 + 4];
        longlong2 wb = *(const longlong2*)(WsU + (size_t)k*34 + tx*2);
        ull b0 = (ull)wb.x, b1 = (ull)wb.y;
        float a[8] = {a0.x, a0.y, a0.z, a0.w, a1.x, a1.y, a1.z, a1.w};
        #pragma unroll
        for (int i = 0; i < 8; i++) {
            ull ad = dup2(a[i]);
            fma2(acc2[i][0], ad, b0);
            fma2(acc2[i][1], ad, b1);
        }
    }
    float s[4] = {}, sq[4] = {};
    #pragma unroll
    for (int i = 0; i < 8; i++) {
        float v[4];
        unpack2(acc2[i][0], v[0], v[1]);
        unpack2(acc2[i][1], v[2], v[3]);
        size_t rowOff = (size_t)(e0 + ty*8 + i) * 64 + tx*4;
        *(float4*)&out[rowOff] = make_float4(v[0], v[1], v[2], v[3]);
        #pragma unroll
        for (int j = 0; j < 4; j++) { s[j] += v[j]; sq[j] += v[j]*v[j]; }
    }
    __syncthreads();
    float* redS = fS;
    float* redQ = fS + 1024;
    #pragma unroll
    for (int j = 0; j < 4; j++) { redS[ty*64 + tx*4 + j] = s[j]; redQ[ty*64 + tx*4 + j] = sq[j]; }
    __syncthreads();
    if (tid < 64) {
        float S = 0.f, Q = 0.f;
        #pragma unroll
        for (int t = 0; t < 16; t++) { S += redS[t*64 + tid]; Q += redQ[t*64 + tid]; }
        atomicAdd(&g_sum[1][tid], (double)S);
        atomicAdd(&g_sqs[1][tid], (double)Q);
    }
}

// ---------------- edge conv 64 -> 64 (act w/ fused finalize; f32x2 core) -----
__global__ __launch_bounds__(256) void dg_econv64(const float* __restrict__ in,
                                                  float* __restrict__ out,
                                                  const float* __restrict__ W,
                                                  int sIn, int sOut, double invE,
                                                  const float* __restrict__ Gi,
                                                  const float* __restrict__ Bi) {
    float* fS = dsm;
    float* Ws = dsm + 64 * 132;
    __shared__ float scS[64], shS[64];
    int e0 = blockIdx.x * 128;
    int tid = threadIdx.x;
    if (tid < 64) {
        double m = g_sum[sIn][tid] * invE;
        double vv = g_sqs[sIn][tid] * invE - m * m;
        float sc = Gi[tid] * rsqrtf((float)vv + 1e-5f);
        scS[tid] = sc; shS[tid] = Bi[tid] - (float)m * sc;
    }
    for (int l = tid; l < 4096; l += 256) {
        int c = l >> 6, n = l & 63;
        Ws[c * 68 + n] = W[n * 64 + c];
    }
    __syncthreads();
    {
        int r = tid >> 1, cb = (tid & 1) * 32;
        const float4* p = (const float4*)(in + (size_t)(e0 + r) * 64 + cb);
        #pragma unroll
        for (int i = 0; i < 8; i++) {
            float4 v = p[i];
            int c = cb + i * 4;
            fS[(c+0)*132 + r] = lrelu(scS[c+0]*v.x + shS[c+0]);
            fS[(c+1)*132 + r] = lrelu(scS[c+1]*v.y + shS[c+1]);
            fS[(c+2)*132 + r] = lrelu(scS[c+2]*v.z + shS[c+2]);
            fS[(c+3)*132 + r] = lrelu(scS[c+3]*v.w + shS[c+3]);
        }
    }
    __syncthreads();
    int tx = tid & 15, ty = tid >> 4;
    ull acc2[8][2] = {};
    const ull* WsU = (const ull*)Ws;
    #pragma unroll 4
    for (int k = 0; k < 64; k++) {
        float4 a0 = *(const float4*)&fS[k*132 + ty*8];
        float4 a1 = *(const float4*)&fS[k*132 + ty*8 + 4];
        longlong2 wb = *(const longlong2*)(WsU + (size_t)k*34 + tx*2);
        ull b0 = (ull)wb.x, b1 = (ull)wb.y;
        float a[8] = {a0.x, a0.y, a0.z, a0.w, a1.x, a1.y, a1.z, a1.w};
        #pragma unroll
        for (int i = 0; i < 8; i++) {
            ull ad = dup2(a[i]);
            fma2(acc2[i][0], ad, b0);
            fma2(acc2[i][1], ad, b1);
        }
    }
    float s[4] = {}, sq[4] = {};
    #pragma unroll
    for (int i = 0; i < 8; i++) {
        float v[4];
        unpack2(acc2[i][0], v[0], v[1]);
        unpack2(acc2[i][1], v[2], v[3]);
        size_t rowOff = (size_t)(e0 + ty*8 + i) * 64 + tx*4;
        *(float4*)&out[rowOff] = make_float4(v[0], v[1], v[2], v[3]);
        #pragma unroll
        for (int j = 0; j < 4; j++) { s[j] += v[j]; sq[j] += v[j]*v[j]; }
    }
    __syncthreads();
    float* redS = fS;
    float* redQ = fS + 1024;
    #pragma unroll
    for (int j = 0; j < 4; j++) { redS[ty*64 + tx*4 + j] = s[j]; redQ[ty*64 + tx*4 + j] = sq[j]; }
    __syncthreads();
    if (tid < 64) {
        float S = 0.f, Q = 0.f;
        #pragma unroll
        for (int t = 0; t < 16; t++) { S += redS[t*64 + tid]; Q += redQ[t*64 + tid]; }
        atomicAdd(&g_sum[sOut][tid], (double)S);
        atomicAdd(&g_sqs[sOut][tid], (double)Q);
    }
}

// ---------------- edge conv 128 -> 64 as GEMM, gather, f32x2 core ------------
__global__ __launch_bounds__(256) void dg_econv128(const float* __restrict__ xin,
                                                   float* __restrict__ out,
                                                   const float* __restrict__ W,
                                                   int sOut) {
    float* fS = dsm;
    float* Ws = dsm + 64 * 132;
    __shared__ int qS[128], nbS[128];
    int e0 = blockIdx.x * 128;
    int tid = threadIdx.x;
    if (tid < 128) {
        int e = e0 + tid;
        int q = e / KNN;
        qS[tid] = q;
        nbS[tid] = (q >> 12) * NP + g_idx[e];
    }
    __syncthreads();
    int tx = tid & 15, ty = tid >> 4;
    ull acc2[8][2] = {};
    const ull* WsU = (const ull*)Ws;
    for (int kt = 0; kt < 2; kt++) {
        int r = tid >> 1, cb = (tid & 1) * 32;
        int q = qS[r];
        const float4* pq = (const float4*)(xin + (size_t)q * 64 + cb);
        if (kt == 0) {
            const float4* pn = (const float4*)(xin + (size_t)nbS[r] * 64 + cb);
            #pragma unroll
            for (int i = 0; i < 8; i++) {
                float4 vn = pn[i], vq = pq[i];
                int c = cb + i * 4;
                fS[(c+0)*132 + r] = vn.x - vq.x;
                fS[(c+1)*132 + r] = vn.y - vq.y;
                fS[(c+2)*132 + r] = vn.z - vq.z;
                fS[(c+3)*132 + r] = vn.w - vq.w;
            }
        } else {
            #pragma unroll
            for (int i = 0; i < 8; i++) {
                float4 vq = pq[i];
                int c = cb + i * 4;
                fS[(c+0)*132 + r] = vq.x;
                fS[(c+1)*132 + r] = vq.y;
                fS[(c+2)*132 + r] = vq.z;
                fS[(c+3)*132 + r] = vq.w;
            }
        }
        for (int l = tid; l < 4096; l += 256) {
            int c = l >> 6, n = l & 63;
            Ws[c * 68 + n] = W[n * 128 + kt * 64 + c];
        }
        __syncthreads();
        #pragma unroll 4
        for (int k = 0; k < 64; k++) {
            float4 a0 = *(const float4*)&fS[k*132 + ty*8];
            float4 a1 = *(const float4*)&fS[k*132 + ty*8 + 4];
            longlong2 wb = *(const longlong2*)(WsU + (size_t)k*34 + tx*2);
            ull b0 = (ull)wb.x, b1 = (ull)wb.y;
            float a[8] = {a0.x, a0.y, a0.z, a0.w, a1.x, a1.y, a1.z, a1.w};
            #pragma unroll
            for (int i = 0; i < 8; i++) {
                ull ad = dup2(a[i]);
                fma2(acc2[i][0], ad, b0);
                fma2(acc2[i][1], ad, b1);
            }
        }
        __syncthreads();
    }
    float s[4] = {}, sq[4] = {};
    #pragma unroll
    for (int i = 0; i < 8; i++) {
        float v[4];
        unpack2(acc2[i][0], v[0], v[1]);
        unpack2(acc2[i][1], v[2], v[3]);
        size_t rowOff = (size_t)(e0 + ty*8 + i) * 64 + tx*4;
        *(float4*)&out[rowOff] = make_float4(v[0], v[1], v[2], v[3]);
        #pragma unroll
        for (int j = 0; j < 4; j++) { s[j] += v[j]; sq[j] += v[j]*v[j]; }
    }
    float* redS = fS;
    float* redQ = fS + 1024;
    #pragma unroll
    for (int j = 0; j < 4; j++) { redS[ty*64 + tx*4 + j] = s[j]; redQ[ty*64 + tx*4 + j] = sq[j]; }
    __syncthreads();
    if (tid < 64) {
        float S = 0.f, Q = 0.f;
        #pragma unroll
        for (int t = 0; t < 16; t++) { S += redS[t*64 + tid]; Q += redQ[t*64 + tid]; }
        atomicAdd(&g_sum[sOut][tid], (double)S);
        atomicAdd(&g_sqs[sOut][tid], (double)Q);
    }
}

// ---------------- max over k neighbors (finalize fused) ----------------------
__global__ __launch_bounds__(256) void dg_maxk(const float* __restrict__ hraw,
                                               float* __restrict__ xout, int stage,
                                               double invE,
                                               const float* __restrict__ Gi,
                                               const float* __restrict__ Bi) {
    __shared__ float scS[64], shS[64];
    int tid = threadIdx.x;
    if (tid < 64) {
        double m = g_sum[stage][tid] * invE;
        double vv = g_sqs[stage][tid] * invE - m * m;
        float sc = Gi[tid] * rsqrtf((float)vv + 1e-5f);
        scS[tid] = sc; shS[tid] = Bi[tid] - (float)m * sc;
    }
    __syncthreads();
    int t = tid & 63;
    int q = blockIdx.x * 4 + (tid >> 6);
    float s = scS[t], sh = shS[t];
    float m = -3.4e38f;
    for (int j = 0; j < KNN; j++) {
        float v = lrelu(hraw[((size_t)q * KNN + j) * 64 + t] * s + sh);
        m = fmaxf(m, v);
    }
    xout[(size_t)q * 64 + t] = m;
}

// ---------------- concat x1|x2|x3 --------------------------------------------
__global__ void dg_cat_kernel() {
    int i = blockIdx.x * 256 + threadIdx.x;
    if (i >= ROWS * 192) return;
    int r = i / 192, c = i % 192;
    float v = (c < 64)  ? g_x1[(size_t)r * 64 + c]
            : (c < 128) ? g_x2[(size_t)r * 64 + c - 64]
                        : g_x3[(size_t)r * 64 + c - 128];
    g_cat[i] = v;
}

// ---------------- 128x128 tiled GEMM, f32x2 core, fused epilogues ------------
// MODE bit0: act(actStage, finalize fused) on A; bit1: +gterm;
// bit2: stats(statStage); bit3: per-(batch,ch) raw max/min; bit4: skip C store.
template <int MODE>
__global__ __launch_bounds__(256) void dg_gemm128(
    const float* __restrict__ A,
    const float* __restrict__ W, int ldw,
    float* __restrict__ C,
    int Nn, int Kk, int actStage, int statStage,
    double invAct, const float* __restrict__ Ga, const float* __restrict__ Ba) {
    __shared__ float As[32 * 132];
    __shared__ float Ws2[32 * 132];
    __shared__ float scA[512], shA[512];
    int m0 = blockIdx.y * 128, n0 = blockIdx.x * 128;
    int tid = threadIdx.x, tx = tid & 15, ty = tid >> 4;
    if (MODE & 1) {
        for (int c = tid; c < Kk; c += 256) {
            double m = g_sum[actStage][c] * invAct;
            double vv = g_sqs[actStage][c] * invAct - m * m;
            float sc = Ga[c] * rsqrtf((float)vv + 1e-5f);
            scA[c] = sc; shA[c] = Ba[c] - (float)m * sc;
        }
        __syncthreads();
    }
    ull acc2[8][4] = {};
    const ull* WsU = (const ull*)Ws2;
    for (int k0 = 0; k0 < Kk; k0 += 32) {
        int r = tid >> 1, cb = (tid & 1) * 16;
        const float4* pa = (const float4*)(A + (size_t)(m0 + r) * Kk + k0 + cb);
        const float4* pw = (const float4*)(W + (size_t)(n0 + r) * ldw + k0 + cb);
        #pragma unroll
        for (int i = 0; i < 4; i++) {
            float4 v = pa[i];
            int c = cb + i * 4;
            if (MODE & 1) {
                v.x = lrelu(scA[k0+c+0]*v.x + shA[k0+c+0]);
                v.y = lrelu(scA[k0+c+1]*v.y + shA[k0+c+1]);
                v.z = lrelu(scA[k0+c+2]*v.z + shA[k0+c+2]);
                v.w = lrelu(scA[k0+c+3]*v.w + shA[k0+c+3]);
            }
            As[(c+0)*132 + r] = v.x; As[(c+1)*132 + r] = v.y;
            As[(c+2)*132 + r] = v.z; As[(c+3)*132 + r] = v.w;
            float4 w = pw[i];
            Ws2[(c+0)*132 + r] = w.x; Ws2[(c+1)*132 + r] = w.y;
            Ws2[(c+2)*132 + r] = w.z; Ws2[(c+3)*132 + r] = w.w;
        }
        __syncthreads();
        #pragma unroll 4
        for (int k = 0; k < 32; k++) {
            float4 a0 = *(const float4*)&As[k*132 + ty*8];
            float4 a1 = *(const float4*)&As[k*132 + ty*8 + 4];
            const longlong2* pb = (const longlong2*)(WsU + (size_t)k*66 + tx*4);
            longlong2 wbA = pb[0], wbB = pb[1];
            ull wb[4] = {(ull)wbA.x, (ull)wbA.y, (ull)wbB.x, (ull)wbB.y};
            float a[8] = {a0.x, a0.y, a0.z, a0.w, a1.x, a1.y, a1.z, a1.w};
            #pragma unroll
            for (int i = 0; i < 8; i++) {
                ull ad = dup2(a[i]);
                #pragma unroll
                for (int j = 0; j < 4; j++) fma2(acc2[i][j], ad, wb[j]);
            }
        }
        __syncthreads();
    }
    float colS[8] = {}, colQ[8] = {};
    float colMx[8], colMn[8];
    #pragma unroll
    for (int j = 0; j < 8; j++) { colMx[j] = -3.4e38f; colMn[j] = 3.4e38f; }
    #pragma unroll
    for (int i = 0; i < 8; i++) {
        int m = m0 + ty*8 + i;
        float v[8];
        #pragma unroll
        for (int j = 0; j < 4; j++) unpack2(acc2[i][j], v[2*j], v[2*j+1]);
        if (MODE & 2) {
            #pragma unroll
            for (int j = 0; j < 8; j++) v[j] += g_gterm[(m >> 12) * Nn + n0 + tx*8 + j];
        }
        if (!(MODE & 16)) {
            size_t rowOff = (size_t)m * Nn + n0 + tx*8;
            *(float4*)&C[rowOff]     = make_float4(v[0], v[1], v[2], v[3]);
            *(float4*)&C[rowOff + 4] = make_float4(v[4], v[5], v[6], v[7]);
        }
        #pragma unroll
        for (int j = 0; j < 8; j++) {
            colS[j] += v[j]; colQ[j] += v[j]*v[j];
            colMx[j] = fmaxf(colMx[j], v[j]);
            colMn[j] = fminf(colMn[j], v[j]);
        }
    }
    if (MODE & 4) {
        __syncthreads();
        #pragma unroll
        for (int j = 0; j < 8; j++) {
            As[ty*128 + tx*8 + j]  = colS[j];
            Ws2[ty*128 + tx*8 + j] = colQ[j];
        }
        __syncthreads();
        if (tid < 128) {
            float S = 0.f, Q = 0.f;
            #pragma unroll
            for (int t = 0; t < 16; t++) { S += As[t*128 + tid]; Q += Ws2[t*128 + tid]; }
            atomicAdd(&g_sum[statStage][n0 + tid], (double)S);
            atomicAdd(&g_sqs[statStage][n0 + tid], (double)Q);
        }
        if (MODE & 8) {
            __syncthreads();
            #pragma unroll
            for (int j = 0; j < 8; j++) {
                As[ty*128 + tx*8 + j]  = colMx[j];
                Ws2[ty*128 + tx*8 + j] = colMn[j];
            }
            __syncthreads();
            if (tid < 128) {
                float Mx = -3.4e38f, Mn = 3.4e38f;
                #pragma unroll
                for (int t = 0; t < 16; t++) {
                    Mx = fmaxf(Mx, As[t*128 + tid]);
                    Mn = fminf(Mn, Ws2[t*128 + tid]);
                }
                int b = m0 >> 12;
                atomicMax(&g_hmaxEnc[b * 1024 + n0 + tid], fenc(Mx));
                atomicMin(&g_hminEnc[b * 1024 + n0 + tid], fenc(Mn));
            }
        }
    }
}

// ---------------- global-max finalize (fin5 fused) ---------------------------
__global__ __launch_bounds__(1024) void dg_gmaxfin(double invR,
                                                   const float* __restrict__ G6,
                                                   const float* __restrict__ B6) {
    int b = blockIdx.x, e = threadIdx.x;
    double m = g_sum[5][e] * invR;
    double vv = g_sqs[5][e] * invR - m * m;
    float s = G6[e] * rsqrtf((float)vv + 1e-5f);
    float t = B6[e] - (float)m * s;
    float mx = fdec(g_hmaxEnc[b * 1024 + e]);
    float mn = fdec(g_hminEnc[b * 1024 + e]);
    g_gmaxv[b * 1024 + e] = lrelu(s * (s >= 0.f ? mx : mn) + t);
}

// ---------------- gterm[b,o] = sum_e gmax[b,e] * W7[o,e] ---------------------
__global__ __launch_bounds__(512) void dg_gterm_kernel(const float* __restrict__ W7) {
    int b = blockIdx.x, o = threadIdx.x;
    float acc = 0.f;
    for (int e = 0; e < 1024; e++)
        acc += g_gmaxv[b * 1024 + e] * W7[(size_t)o * 1216 + e];
    g_gterm[b * 512 + o] = acc;
}

// ---------------- final classifier (fin7 fused) ------------------------------
__global__ __launch_bounds__(288) void dg_final(const float* __restrict__ W9,
                                                float* __restrict__ out,
                                                double invR,
                                                const float* __restrict__ G8,
                                                const float* __restrict__ B8) {
    __shared__ float a[32 * 257];
    __shared__ float w[9 * 259];
    __shared__ float scS[256], shS[256];
    int tid = threadIdx.x;
    if (tid < 256) {
        double m = g_sum[7][tid] * invR;
        double vv = g_sqs[7][tid] * invR - m * m;
        float sc = G8[tid] * rsqrtf((float)vv + 1e-5f);
        scS[tid] = sc; shS[tid] = B8[tid] - (float)m * sc;
    }
    for (int l = tid; l < 2304; l += 288) {
        int o = l / 256, c = l % 256;
        w[o * 259 + c] = W9[l];
    }
    __syncthreads();
    int r0 = blockIdx.x * 32;
    for (int l = tid; l < 32 * 256; l += 288) {
        int rr = l / 256, c = l % 256;
        float v = g_hB[(size_t)(r0 + rr) * 256 + c];
        a[rr * 257 + c] = lrelu(scS[c] * v + shS[c]);
    }
    __syncthreads();
    int rr = tid / 9, o = tid % 9;
    float acc = 0.f;
    #pragma unroll 16
    for (int c = 0; c < 256; c++) acc += a[rr * 257 + c] * w[o * 259 + c];
    out[(size_t)(r0 + rr) * 9 + o] = acc;
}

// ---------------- host orchestration -----------------------------------------
extern "C" void kernel_launch(void* const* d_in, const int* in_sizes, int n_in,
                              void* d_out, int out_size) {
    const float* x = (const float*)d_in[0];
    const float* W[10] = {0};
    const float* G[9] = {0};
    const float* Bp[9] = {0};
    if (n_in >= 27 && in_sizes[1] == 1) {
        for (int i = 1; i <= 9; i++) W[i] = (const float*)d_in[1 + i];
        for (int i = 1; i <= 8; i++) {
            G[i]  = (const float*)d_in[11 + 2 * (i - 1)];
            Bp[i] = (const float*)d_in[12 + 2 * (i - 1)];
        }
    } else {
        for (int i = 1; i <= 9; i++) W[i] = (const float*)d_in[i];
        for (int i = 1; i <= 8; i++) {
            G[i]  = (const float*)d_in[10 + 2 * (i - 1)];
            Bp[i] = (const float*)d_in[11 + 2 * (i - 1)];
        }
    }
    float* out = (float*)d_out;

    void* tmp;
    cudaGetSymbolAddress(&tmp, g_negd);  float* negd = (float*)tmp;
    cudaGetSymbolAddress(&tmp, g_hA);    float* hA   = (float*)tmp;
    cudaGetSymbolAddress(&tmp, g_hB);    float* hB   = (float*)tmp;
    cudaGetSymbolAddress(&tmp, g_x1);    float* x1   = (float*)tmp;
    cudaGetSymbolAddress(&tmp, g_x2);    float* x2   = (float*)tmp;
    cudaGetSymbolAddress(&tmp, g_x3);    float* x3   = (float*)tmp;
    cudaGetSymbolAddress(&tmp, g_cat);   float* cat  = (float*)tmp;

    const int SQ_SMEM = 2 * 64 * 132 * 4;                 // 67584
    const int EC_SMEM = (64 * 132 + 64 * 68) * 4;         // 51200
    cudaFuncSetAttribute(dg_sqdist128, cudaFuncAttributeMaxDynamicSharedMemorySize, SQ_SMEM);
    cudaFuncSetAttribute(dg_econv64,   cudaFuncAttributeMaxDynamicSharedMemorySize, EC_SMEM);
    cudaFuncSetAttribute(dg_econv64f1, cudaFuncAttributeMaxDynamicSharedMemorySize, EC_SMEM);
    cudaFuncSetAttribute(dg_econv128,  cudaFuncAttributeMaxDynamicSharedMemorySize, EC_SMEM);

    const double invE = 1.0 / (double)EDGES;
    const double invR = 1.0 / (double)ROWS;
    const int EB = EDGES / 128;

    dg_zero_kernel<<<32, 256>>>();

    // ---- block 1 (xyz) ----
    dg_knn_small<<<ROWS, 256>>>(x);
    dg_conv1s<<<EB, 256>>>(x, W[1]);
    dg_econv64f1<<<EB, 256, EC_SMEM>>>(x, W[1], W[2], hB, invE, G[1], Bp[1]);
    dg_maxk<<<ROWS / 4, 256>>>(hB, x1, 1, invE, G[2], Bp[2]);

    // ---- block 2 (x1) ----
    dg_sqdist128<<<dim3(NP / 128, NP / 128, BB), 256, SQ_SMEM>>>(x1, negd);
    dg_select_kernel<<<ROWS, 256>>>();
    dg_econv128<<<EB, 256, EC_SMEM>>>(x1, hA, W[3], 2);
    dg_econv64<<<EB, 256, EC_SMEM>>>(hA, hB, W[4], 2, 3, invE, G[3], Bp[3]);
    dg_maxk<<<ROWS / 4, 256>>>(hB, x2, 3, invE, G[4], Bp[4]);

    // ---- block 3 (x2) ----
    dg_sqdist128<<<dim3(NP / 128, NP / 128, BB), 256, SQ_SMEM>>>(x2, negd);
    dg_select_kernel<<<ROWS, 256>>>();
    dg_econv128<<<EB, 256, EC_SMEM>>>(x2, hA, W[5], 4);
    dg_maxk<<<ROWS / 4, 256>>>(hA, x3, 4, invE, G[5], Bp[5]);

    // ---- point MLPs ----
    dg_cat_kernel<<<(ROWS * 192 + 255) / 256, 256>>>();
    dg_gemm128<4|8|16><<<dim3(8, ROWS / 128), 256>>>(
        cat, W[6], 192, hA, 1024, 192, -1, 5, 0.0, 0, 0);
    dg_gmaxfin<<<BB, 1024>>>(invR, G[6], Bp[6]);
    dg_gterm_kernel<<<BB, 512>>>(W[7]);
    dg_gemm128<2|4><<<dim3(4, ROWS / 128), 256>>>(
        cat, W[7] + 1024, 1216, hA, 512, 192, -1, 6, 0.0, 0, 0);
    dg_gemm128<1|4><<<dim3(2, ROWS / 128), 256>>>(
        hA, W[8], 512, hB, 256, 512, 6, 7, invR, G[7], Bp[7]);
    dg_final<<<ROWS / 32, 288>>>(W[9], out, invR, G[8], Bp[8]);
}

// round 13
// speedup vs baseline: 1.3507x; 1.0390x over previous
#include <cuda_runtime.h>

#define BB 8
#define NP 4096
#define KNN 20
#define ROWS (BB*NP)          // 32768
#define EDGES (ROWS*KNN)      // 655360

typedef unsigned long long ull;

// ---------------- scratch (device globals; no allocations allowed) ----------
static __device__ float    g_negd[(size_t)BB * NP * NP];        // 512 MB
static __device__ int      g_idx[ROWS * KNN];
static __device__ float    g_hA[(size_t)EDGES * 64];            // 160 MB
static __device__ float    g_hB[(size_t)EDGES * 64];            // 160 MB
static __device__ float    g_x1[(size_t)ROWS * 64];
static __device__ float    g_x2[(size_t)ROWS * 64];
static __device__ float    g_x3[(size_t)ROWS * 64];
static __device__ unsigned g_hmaxEnc[BB * 1024];
static __device__ unsigned g_hminEnc[BB * 1024];
static __device__ float    g_gmaxv[BB * 1024];
static __device__ float    g_gterm[BB * 512];
static __device__ double   g_sum[8][1024];
static __device__ double   g_sqs[8][1024];

__device__ __forceinline__ float lrelu(float v) { return v > 0.f ? v : 0.2f * v; }
__device__ __forceinline__ unsigned fenc(float f) {
    unsigned u = __float_as_uint(f);
    return (u & 0x80000000u) ? ~u : (u | 0x80000000u);
}
__device__ __forceinline__ float fdec(unsigned u) {
    return (u & 0x80000000u) ? __uint_as_float(u & 0x7fffffffu) : __uint_as_float(~u);
}

// ---- packed f32x2 helpers ----------------------------------------------------
__device__ __forceinline__ ull dup2(float v) {
    ull r; asm("mov.b64 %0, {%1, %1};" : "=l"(r) : "f"(v)); return r;
}
__device__ __forceinline__ ull add2(ull a, ull b) {
    ull r; asm("add.rn.f32x2 %0, %1, %2;" : "=l"(r) : "l"(a), "l"(b)); return r;
}
__device__ __forceinline__ void fma2(ull& d, ull a, ull b) {
    asm("fma.rn.f32x2 %0, %1, %2, %0;" : "+l"(d) : "l"(a), "l"(b));
}
__device__ __forceinline__ void unpack2(ull p, float& lo, float& hi) {
    asm("mov.b64 {%0, %1}, %2;" : "=f"(lo), "=f"(hi) : "l"(p));
}

extern __shared__ float dsm[];

// ---------------- zero stats/atomics (must run every replay) ----------------
__global__ void dg_zero_kernel() {
    int i = blockIdx.x * 256 + threadIdx.x;
    if (i < 8192) {
        (&g_sum[0][0])[i] = 0.0;
        (&g_sqs[0][0])[i] = 0.0;
        g_hmaxEnc[i] = 0u;
        g_hminEnc[i] = 0xFFFFFFFFu;
    }
}

// ---------------- kNN on raw xyz: winner-only-rescan top-20 -----------------
// Values register-resident; per-thread local argmax cached across rounds.
// Tie rule: (neg_d desc, idx asc) — identical to proven smem version.
__global__ __launch_bounds__(256) void dg_knn_small(const float* __restrict__ x) {
    int q = blockIdx.x, b = q >> 12, i = q & 4095;
    const float* xb = x + (size_t)b * 3 * NP;
    int tid = threadIdx.x, lane = tid & 31, wid = tid >> 5;
    float qx = xb[i], qy = xb[NP + i], qz = xb[2 * NP + i];
    float v[16];
    #pragma unroll
    for (int u = 0; u < 16; u++) {
        int j = u * 256 + tid;
        float dx = xb[j] - qx, dy = xb[NP + j] - qy, dz = xb[2 * NP + j] - qz;
        v[u] = -(dx * dx + dy * dy + dz * dz);
    }
    float bv = -3.4e38f; int bi = 0x7fffffff;
    #pragma unroll
    for (int u = 0; u < 16; u++) {
        int j = u * 256 + tid;
        if (v[u] > bv) { bv = v[u]; bi = j; }
    }
    __shared__ float rv[8];
    __shared__ int   ri[8];
    __shared__ int   winS;
    for (int r = 0; r < KNN; r++) {
        float wv = bv; int wi = bi;
        #pragma unroll
        for (int s = 16; s > 0; s >>= 1) {
            float ov = __shfl_xor_sync(0xffffffffu, wv, s);
            int   oi = __shfl_xor_sync(0xffffffffu, wi, s);
            if (ov > wv || (ov == wv && oi < wi)) { wv = ov; wi = oi; }
        }
        if (lane == 0) { rv[wid] = wv; ri[wid] = wi; }
        __syncthreads();
        if (tid == 0) {
            float bbv = rv[0]; int bbi = ri[0];
            #pragma unroll
            for (int w = 1; w < 8; w++)
                if (rv[w] > bbv || (rv[w] == bbv && ri[w] < bbi)) { bbv = rv[w]; bbi = ri[w]; }
            g_idx[q * KNN + r] = bbi;
            winS = bbi;
        }
        __syncthreads();
        int wn = winS;
        if ((wn & 255) == tid) {
            v[wn >> 8] = -3.4e38f;
            bv = -3.4e38f; bi = 0x7fffffff;
            #pragma unroll
            for (int u = 0; u < 16; u++) {
                int j = u * 256 + tid;
                if (v[u] > bv) { bv = v[u]; bi = j; }
            }
        }
        __syncthreads();
    }
}

// ---------------- top-20 select: winner-only rescan, float4 loads -----------
// mapping: j = u*1024 + tid*4 + e ; slot = u*4+e ; owner = (j>>2)&255
__global__ __launch_bounds__(256) void dg_select_kernel() {
    size_t q = blockIdx.x;
    const float* row = g_negd + q * NP;
    int tid = threadIdx.x, lane = tid & 31, wid = tid >> 5;
    float v[16];
    #pragma unroll
    for (int u = 0; u < 4; u++) {
        float4 t = *(const float4*)(row + u * 1024 + tid * 4);
        v[u*4+0] = t.x; v[u*4+1] = t.y; v[u*4+2] = t.z; v[u*4+3] = t.w;
    }
    float bv = -3.4e38f; int bi = 0x7fffffff;
    #pragma unroll
    for (int u = 0; u < 4; u++)
        #pragma unroll
        for (int e = 0; e < 4; e++) {
            int j = u * 1024 + tid * 4 + e;
            if (v[u*4+e] > bv) { bv = v[u*4+e]; bi = j; }
        }
    __shared__ float rv[8];
    __shared__ int   ri[8];
    __shared__ int   winS;
    for (int r = 0; r < KNN; r++) {
        float wv = bv; int wi = bi;
        #pragma unroll
        for (int s = 16; s > 0; s >>= 1) {
            float ov = __shfl_xor_sync(0xffffffffu, wv, s);
            int   oi = __shfl_xor_sync(0xffffffffu, wi, s);
            if (ov > wv || (ov == wv && oi < wi)) { wv = ov; wi = oi; }
        }
        if (lane == 0) { rv[wid] = wv; ri[wid] = wi; }
        __syncthreads();
        if (tid == 0) {
            float bbv = rv[0]; int bbi = ri[0];
            #pragma unroll
            for (int w = 1; w < 8; w++)
                if (rv[w] > bbv || (rv[w] == bbv && ri[w] < bbi)) { bbv = rv[w]; bbi = ri[w]; }
            g_idx[q * KNN + r] = bbi;
            winS = bbi;
        }
        __syncthreads();
        int wn = winS;
        if (((wn >> 2) & 255) == tid) {
            int slot = ((wn >> 10) << 2) | (wn & 3);
            v[slot] = -3.4e38f;
            bv = -3.4e38f; bi = 0x7fffffff;
            #pragma unroll
            for (int u = 0; u < 4; u++)
                #pragma unroll
                for (int e = 0; e < 4; e++) {
                    int j = u * 1024 + tid * 4 + e;
                    if (v[u*4+e] > bv) { bv = v[u*4+e]; bi = j; }
                }
        }
        __syncthreads();
    }
}

// ---------------- pairwise -||a-b||^2, 128x128 tile, f32x2 (proven) ----------
__global__ __launch_bounds__(256) void dg_sqdist128(const float* __restrict__ X,
                                                    float* __restrict__ C) {
    int bz = blockIdx.z;
    const float* A = X + (size_t)bz * NP * 64;
    float* Cb = C + (size_t)bz * NP * NP;
    float* As = dsm;              // [64][132]
    float* Bs = dsm + 64 * 132;   // [64][132] (negated)
    int m0 = blockIdx.y * 128, n0 = blockIdx.x * 128;
    int tid = threadIdx.x;
    {
        int r = tid >> 1, cb = (tid & 1) * 32;
        const float4* pa = (const float4*)(A + (size_t)(m0 + r) * 64 + cb);
        const float4* pb = (const float4*)(A + (size_t)(n0 + r) * 64 + cb);
        #pragma unroll
        for (int i = 0; i < 8; i++) {
            float4 va = pa[i], vb = pb[i];
            int c = cb + i * 4;
            As[(c+0)*132 + r] = va.x; As[(c+1)*132 + r] = va.y;
            As[(c+2)*132 + r] = va.z; As[(c+3)*132 + r] = va.w;
            Bs[(c+0)*132 + r] = -vb.x; Bs[(c+1)*132 + r] = -vb.y;
            Bs[(c+2)*132 + r] = -vb.z; Bs[(c+3)*132 + r] = -vb.w;
        }
    }
    __syncthreads();
    int tx = tid & 15, ty = tid >> 4;
    ull acc2[8][4] = {};
    const ull* BsU = (const ull*)Bs;
    #pragma unroll 4
    for (int k = 0; k < 64; k++) {
        float4 a0 = *(const float4*)&As[k*132 + ty*8];
        float4 a1 = *(const float4*)&As[k*132 + ty*8 + 4];
        const longlong2* pb = (const longlong2*)(BsU + (size_t)k*66 + tx*4);
        longlong2 nbA = pb[0], nbB = pb[1];
        ull nb[4] = {(ull)nbA.x, (ull)nbA.y, (ull)nbB.x, (ull)nbB.y};
        float a[8] = {a0.x, a0.y, a0.z, a0.w, a1.x, a1.y, a1.z, a1.w};
        #pragma unroll
        for (int i = 0; i < 8; i++) {
            ull ad = dup2(a[i]);
            #pragma unroll
            for (int j = 0; j < 4; j++) {
                ull d = add2(ad, nb[j]);
                fma2(acc2[i][j], d, d);
            }
        }
    }
    #pragma unroll
    for (int i = 0; i < 8; i++) {
        float v[8];
        #pragma unroll
        for (int j = 0; j < 4; j++) unpack2(acc2[i][j], v[2*j], v[2*j+1]);
        size_t rowOff = (size_t)(m0 + ty*8 + i) * NP + n0 + tx*8;
        *(float4*)&Cb[rowOff]     = make_float4(-v[0], -v[1], -v[2], -v[3]);
        *(float4*)&Cb[rowOff + 4] = make_float4(-v[4], -v[5], -v[6], -v[7]);
    }
}

// ---------------- conv1 stats-only (no store) ---------------------------------
__global__ __launch_bounds__(256) void dg_conv1s(const float* __restrict__ x,
                                                 const float* __restrict__ W1) {
    __shared__ float fS[6 * 132];
    __shared__ float Ws[6 * 68];
    __shared__ int qS[128], nbS[128];
    __shared__ float redS[1024], redQ[1024];
    int e0 = blockIdx.x * 128;
    int tid = threadIdx.x;
    if (tid < 128) { int e = e0 + tid; qS[tid] = e / KNN; nbS[tid] = g_idx[e]; }
    for (int l = tid; l < 384; l += 256) {
        int o = l / 6, c = l % 6;
        Ws[c * 68 + o] = W1[l];
    }
    __syncthreads();
    for (int l = tid; l < 1024; l += 256) {
        int r = l >> 3, c = l & 7;
        if (c < 6) {
            int q = qS[r], nb = nbS[r];
            const float* xb = x + (size_t)(q >> 12) * 3 * NP;
            int qi = q & 4095;
            float v = (c < 3) ? (xb[c * NP + nb] - xb[c * NP + qi])
                              : xb[(c - 3) * NP + qi];
            fS[c * 132 + r] = v;
        }
    }
    __syncthreads();
    int tx = tid & 15, ty = tid >> 4;
    float acc[8][4] = {};
    #pragma unroll
    for (int k = 0; k < 6; k++) {
        float a[8], bb[4];
        #pragma unroll
        for (int i = 0; i < 8; i++) a[i] = fS[k*132 + ty*8 + i];
        float4 bv = *(const float4*)&Ws[k*68 + tx*4];
        bb[0]=bv.x; bb[1]=bv.y; bb[2]=bv.z; bb[3]=bv.w;
        #pragma unroll
        for (int i = 0; i < 8; i++)
            #pragma unroll
            for (int j = 0; j < 4; j++)
                acc[i][j] += a[i] * bb[j];
    }
    float s[4] = {}, sq[4] = {};
    #pragma unroll
    for (int i = 0; i < 8; i++)
        #pragma unroll
        for (int j = 0; j < 4; j++) { s[j] += acc[i][j]; sq[j] += acc[i][j]*acc[i][j]; }
    #pragma unroll
    for (int j = 0; j < 4; j++) { redS[ty*64 + tx*4 + j] = s[j]; redQ[ty*64 + tx*4 + j] = sq[j]; }
    __syncthreads();
    if (tid < 64) {
        float S = 0.f, Q = 0.f;
        #pragma unroll
        for (int t = 0; t < 16; t++) { S += redS[t*64 + tid]; Q += redQ[t*64 + tid]; }
        atomicAdd(&g_sum[0][tid], (double)S);
        atomicAdd(&g_sqs[0][tid], (double)Q);
    }
}

// ---------------- fused conv1 -> act0(fin fused) -> econv64(W2) --------------
__global__ __launch_bounds__(256) void dg_econv64f1(const float* __restrict__ x,
                                                    const float* __restrict__ W1,
                                                    const float* __restrict__ W2,
                                                    float* __restrict__ out,
                                                    double invE,
                                                    const float* __restrict__ G1,
                                                    const float* __restrict__ B1) {
    float* fS = dsm;              // [64][132]
    float* Ws = dsm + 64 * 132;   // [64][68]
    __shared__ float fS6[6 * 132];
    __shared__ float Ws1[6 * 68];
    __shared__ int qS[128], nbS[128];
    __shared__ float scS[64], shS[64];
    int e0 = blockIdx.x * 128;
    int tid = threadIdx.x;
    if (tid < 128) { int e = e0 + tid; qS[tid] = e / KNN; nbS[tid] = g_idx[e]; }
    if (tid < 64) {
        double m = g_sum[0][tid] * invE;
        double vv = g_sqs[0][tid] * invE - m * m;
        float sc = G1[tid] * rsqrtf((float)vv + 1e-5f);
        scS[tid] = sc; shS[tid] = B1[tid] - (float)m * sc;
    }
    for (int l = tid; l < 384; l += 256) {
        int o = l / 6, c = l % 6;
        Ws1[c * 68 + o] = W1[l];
    }
    for (int l = tid; l < 4096; l += 256) {
        int c = l >> 6, n = l & 63;
        Ws[c * 68 + n] = W2[n * 64 + c];
    }
    __syncthreads();
    for (int l = tid; l < 1024; l += 256) {
        int r = l >> 3, c = l & 7;
        if (c < 6) {
            int q = qS[r], nb = nbS[r];
            const float* xb = x + (size_t)(q >> 12) * 3 * NP;
            int qi = q & 4095;
            float v = (c < 3) ? (xb[c * NP + nb] - xb[c * NP + qi])
                              : xb[(c - 3) * NP + qi];
            fS6[c * 132 + r] = v;
        }
    }
    __syncthreads();
    int tx = tid & 15, ty = tid >> 4;
    float h[8][4] = {};
    #pragma unroll
    for (int k = 0; k < 6; k++) {
        float a[8], bb[4];
        #pragma unroll
        for (int i = 0; i < 8; i++) a[i] = fS6[k*132 + ty*8 + i];
        float4 bv = *(const float4*)&Ws1[k*68 + tx*4];
        bb[0]=bv.x; bb[1]=bv.y; bb[2]=bv.z; bb[3]=bv.w;
        #pragma unroll
        for (int i = 0; i < 8; i++)
            #pragma unroll
            for (int j = 0; j < 4; j++)
                h[i][j] += a[i] * bb[j];
    }
    #pragma unroll
    for (int i = 0; i < 8; i++)
        #pragma unroll
        for (int j = 0; j < 4; j++) {
            int col = tx*4 + j, row = ty*8 + i;
            fS[col*132 + row] = lrelu(scS[col]*h[i][j] + shS[col]);
        }
    __syncthreads();
    ull acc2[8][2] = {};
    const ull* WsU = (const ull*)Ws;
    #pragma unroll 4
    for (int k = 0; k < 64; k++) {
        float4 a0 = *(const float4*)&fS[k*132 + ty*8];
        float4 a1 = *(const float4*)&fS[k*132 + ty*8 + 4];
        longlong2 wb = *(const longlong2*)(WsU + (size_t)k*34 + tx*2);
        ull b0 = (ull)wb.x, b1 = (ull)wb.y;
        float a[8] = {a0.x, a0.y, a0.z, a0.w, a1.x, a1.y, a1.z, a1.w};
        #pragma unroll
        for (int i = 0; i < 8; i++) {
            ull ad = dup2(a[i]);
            fma2(acc2[i][0], ad, b0);
            fma2(acc2[i][1], ad, b1);
        }
    }
    float s[4] = {}, sq[4] = {};
    #pragma unroll
    for (int i = 0; i < 8; i++) {
        float v[4];
        unpack2(acc2[i][0], v[0], v[1]);
        unpack2(acc2[i][1], v[2], v[3]);
        size_t rowOff = (size_t)(e0 + ty*8 + i) * 64 + tx*4;
        *(float4*)&out[rowOff] = make_float4(v[0], v[1], v[2], v[3]);
        #pragma unroll
        for (int j = 0; j < 4; j++) { s[j] += v[j]; sq[j] += v[j]*v[j]; }
    }
    __syncthreads();
    float* redS = fS;
    float* redQ = fS + 1024;
    #pragma unroll
    for (int j = 0; j < 4; j++) { redS[ty*64 + tx*4 + j] = s[j]; redQ[ty*64 + tx*4 + j] = sq[j]; }
    __syncthreads();
    if (tid < 64) {
        float S = 0.f, Q = 0.f;
        #pragma unroll
        for (int t = 0; t < 16; t++) { S += redS[t*64 + tid]; Q += redQ[t*64 + tid]; }
        atomicAdd(&g_sum[1][tid], (double)S);
        atomicAdd(&g_sqs[1][tid], (double)Q);
    }
}

// ---------------- edge conv 64 -> 64 (act w/ fused finalize; f32x2 core) -----
__global__ __launch_bounds__(256) void dg_econv64(const float* __restrict__ in,
                                                  float* __restrict__ out,
                                                  const float* __restrict__ W,
                                                  int sIn, int sOut, double invE,
                                                  const float* __restrict__ Gi,
                                                  const float* __restrict__ Bi) {
    float* fS = dsm;
    float* Ws = dsm + 64 * 132;
    __shared__ float scS[64], shS[64];
    int e0 = blockIdx.x * 128;
    int tid = threadIdx.x;
    if (tid < 64) {
        double m = g_sum[sIn][tid] * invE;
        double vv = g_sqs[sIn][tid] * invE - m * m;
        float sc = Gi[tid] * rsqrtf((float)vv + 1e-5f);
        scS[tid] = sc; shS[tid] = Bi[tid] - (float)m * sc;
    }
    for (int l = tid; l < 4096; l += 256) {
        int c = l >> 6, n = l & 63;
        Ws[c * 68 + n] = W[n * 64 + c];
    }
    __syncthreads();
    {
        int r = tid >> 1, cb = (tid & 1) * 32;
        const float4* p = (const float4*)(in + (size_t)(e0 + r) * 64 + cb);
        #pragma unroll
        for (int i = 0; i < 8; i++) {
            float4 v = p[i];
            int c = cb + i * 4;
            fS[(c+0)*132 + r] = lrelu(scS[c+0]*v.x + shS[c+0]);
            fS[(c+1)*132 + r] = lrelu(scS[c+1]*v.y + shS[c+1]);
            fS[(c+2)*132 + r] = lrelu(scS[c+2]*v.z + shS[c+2]);
            fS[(c+3)*132 + r] = lrelu(scS[c+3]*v.w + shS[c+3]);
        }
    }
    __syncthreads();
    int tx = tid & 15, ty = tid >> 4;
    ull acc2[8][2] = {};
    const ull* WsU = (const ull*)Ws;
    #pragma unroll 4
    for (int k = 0; k < 64; k++) {
        float4 a0 = *(const float4*)&fS[k*132 + ty*8];
        float4 a1 = *(const float4*)&fS[k*132 + ty*8 + 4];
        longlong2 wb = *(const longlong2*)(WsU + (size_t)k*34 + tx*2);
        ull b0 = (ull)wb.x, b1 = (ull)wb.y;
        float a[8] = {a0.x, a0.y, a0.z, a0.w, a1.x, a1.y, a1.z, a1.w};
        #pragma unroll
        for (int i = 0; i < 8; i++) {
            ull ad = dup2(a[i]);
            fma2(acc2[i][0], ad, b0);
            fma2(acc2[i][1], ad, b1);
        }
    }
    float s[4] = {}, sq[4] = {};
    #pragma unroll
    for (int i = 0; i < 8; i++) {
        float v[4];
        unpack2(acc2[i][0], v[0], v[1]);
        unpack2(acc2[i][1], v[2], v[3]);
        size_t rowOff = (size_t)(e0 + ty*8 + i) * 64 + tx*4;
        *(float4*)&out[rowOff] = make_float4(v[0], v[1], v[2], v[3]);
        #pragma unroll
        for (int j = 0; j < 4; j++) { s[j] += v[j]; sq[j] += v[j]*v[j]; }
    }
    __syncthreads();
    float* redS = fS;
    float* redQ = fS + 1024;
    #pragma unroll
    for (int j = 0; j < 4; j++) { redS[ty*64 + tx*4 + j] = s[j]; redQ[ty*64 + tx*4 + j] = sq[j]; }
    __syncthreads();
    if (tid < 64) {
        float S = 0.f, Q = 0.f;
        #pragma unroll
        for (int t = 0; t < 16; t++) { S += redS[t*64 + tid]; Q += redQ[t*64 + tid]; }
        atomicAdd(&g_sum[sOut][tid], (double)S);
        atomicAdd(&g_sqs[sOut][tid], (double)Q);
    }
}

// ---------------- edge conv 128 -> 64 as GEMM, gather, f32x2 core ------------
__global__ __launch_bounds__(256) void dg_econv128(const float* __restrict__ xin,
                                                   float* __restrict__ out,
                                                   const float* __restrict__ W,
                                                   int sOut) {
    float* fS = dsm;
    float* Ws = dsm + 64 * 132;
    __shared__ int qS[128], nbS[128];
    int e0 = blockIdx.x * 128;
    int tid = threadIdx.x;
    if (tid < 128) {
        int e = e0 + tid;
        int q = e / KNN;
        qS[tid] = q;
        nbS[tid] = (q >> 12) * NP + g_idx[e];
    }
    __syncthreads();
    int tx = tid & 15, ty = tid >> 4;
    ull acc2[8][2] = {};
    const ull* WsU = (const ull*)Ws;
    for (int kt = 0; kt < 2; kt++) {
        int r = tid >> 1, cb = (tid & 1) * 32;
        int q = qS[r];
        const float4* pq = (const float4*)(xin + (size_t)q * 64 + cb);
        if (kt == 0) {
            const float4* pn = (const float4*)(xin + (size_t)nbS[r] * 64 + cb);
            #pragma unroll
            for (int i = 0; i < 8; i++) {
                float4 vn = pn[i], vq = pq[i];
                int c = cb + i * 4;
                fS[(c+0)*132 + r] = vn.x - vq.x;
                fS[(c+1)*132 + r] = vn.y - vq.y;
                fS[(c+2)*132 + r] = vn.z - vq.z;
                fS[(c+3)*132 + r] = vn.w - vq.w;
            }
        } else {
            #pragma unroll
            for (int i = 0; i < 8; i++) {
                float4 vq = pq[i];
                int c = cb + i * 4;
                fS[(c+0)*132 + r] = vq.x;
                fS[(c+1)*132 + r] = vq.y;
                fS[(c+2)*132 + r] = vq.z;
                fS[(c+3)*132 + r] = vq.w;
            }
        }
        for (int l = tid; l < 4096; l += 256) {
            int c = l >> 6, n = l & 63;
            Ws[c * 68 + n] = W[n * 128 + kt * 64 + c];
        }
        __syncthreads();
        #pragma unroll 4
        for (int k = 0; k < 64; k++) {
            float4 a0 = *(const float4*)&fS[k*132 + ty*8];
            float4 a1 = *(const float4*)&fS[k*132 + ty*8 + 4];
            longlong2 wb = *(const longlong2*)(WsU + (size_t)k*34 + tx*2);
            ull b0 = (ull)wb.x, b1 = (ull)wb.y;
            float a[8] = {a0.x, a0.y, a0.z, a0.w, a1.x, a1.y, a1.z, a1.w};
            #pragma unroll
            for (int i = 0; i < 8; i++) {
                ull ad = dup2(a[i]);
                fma2(acc2[i][0], ad, b0);
                fma2(acc2[i][1], ad, b1);
            }
        }
        __syncthreads();
    }
    float s[4] = {}, sq[4] = {};
    #pragma unroll
    for (int i = 0; i < 8; i++) {
        float v[4];
        unpack2(acc2[i][0], v[0], v[1]);
        unpack2(acc2[i][1], v[2], v[3]);
        size_t rowOff = (size_t)(e0 + ty*8 + i) * 64 + tx*4;
        *(float4*)&out[rowOff] = make_float4(v[0], v[1], v[2], v[3]);
        #pragma unroll
        for (int j = 0; j < 4; j++) { s[j] += v[j]; sq[j] += v[j]*v[j]; }
    }
    float* redS = fS;
    float* redQ = fS + 1024;
    #pragma unroll
    for (int j = 0; j < 4; j++) { redS[ty*64 + tx*4 + j] = s[j]; redQ[ty*64 + tx*4 + j] = sq[j]; }
    __syncthreads();
    if (tid < 64) {
        float S = 0.f, Q = 0.f;
        #pragma unroll
        for (int t = 0; t < 16; t++) { S += redS[t*64 + tid]; Q += redQ[t*64 + tid]; }
        atomicAdd(&g_sum[sOut][tid], (double)S);
        atomicAdd(&g_sqs[sOut][tid], (double)Q);
    }
}

// ---------------- max over k neighbors (finalize fused) ----------------------
__global__ __launch_bounds__(256) void dg_maxk(const float* __restrict__ hraw,
                                               float* __restrict__ xout, int stage,
                                               double invE,
                                               const float* __restrict__ Gi,
                                               const float* __restrict__ Bi) {
    __shared__ float scS[64], shS[64];
    int tid = threadIdx.x;
    if (tid < 64) {
        double m = g_sum[stage][tid] * invE;
        double vv = g_sqs[stage][tid] * invE - m * m;
        float sc = Gi[tid] * rsqrtf((float)vv + 1e-5f);
        scS[tid] = sc; shS[tid] = Bi[tid] - (float)m * sc;
    }
    __syncthreads();
    int t = tid & 63;
    int q = blockIdx.x * 4 + (tid >> 6);
    float s = scS[t], sh = shS[t];
    float m = -3.4e38f;
    for (int j = 0; j < KNN; j++) {
        float v = lrelu(hraw[((size_t)q * KNN + j) * 64 + t] * s + sh);
        m = fmaxf(m, v);
    }
    xout[(size_t)q * 64 + t] = m;
}

// ---------------- 128x128 tiled GEMM, f32x2 core, fused epilogues ------------
// MODE bit0: act(actStage, finalize fused) on A; bit1: +gterm;
// bit2: stats(statStage); bit3: per-(batch,ch) raw max/min; bit4: skip C store;
// bit5: A = concat(x1|x2|x3) per 64-col block (Kk must be 192).
template <int MODE>
__global__ __launch_bounds__(256) void dg_gemm128(
    const float* __restrict__ A,
    const float* __restrict__ W, int ldw,
    float* __restrict__ C,
    int Nn, int Kk, int actStage, int statStage,
    double invAct, const float* __restrict__ Ga, const float* __restrict__ Ba,
    const float* __restrict__ X1, const float* __restrict__ X2,
    const float* __restrict__ X3) {
    __shared__ float As[32 * 132];
    __shared__ float Ws2[32 * 132];
    __shared__ float scA[512], shA[512];
    int m0 = blockIdx.y * 128, n0 = blockIdx.x * 128;
    int tid = threadIdx.x, tx = tid & 15, ty = tid >> 4;
    if (MODE & 1) {
        for (int c = tid; c < Kk; c += 256) {
            double m = g_sum[actStage][c] * invAct;
            double vv = g_sqs[actStage][c] * invAct - m * m;
            float sc = Ga[c] * rsqrtf((float)vv + 1e-5f);
            scA[c] = sc; shA[c] = Ba[c] - (float)m * sc;
        }
        __syncthreads();
    }
    ull acc2[8][4] = {};
    const ull* WsU = (const ull*)Ws2;
    for (int k0 = 0; k0 < Kk; k0 += 32) {
        int r = tid >> 1, cb = (tid & 1) * 16;
        const float4* pa;
        if (MODE & 32) {
            int kk = k0 + cb;   // 16-chunk never straddles a 64 boundary
            const float* src = (kk < 64) ? X1 : (kk < 128) ? X2 : X3;
            pa = (const float4*)(src + (size_t)(m0 + r) * 64 + (kk & 63));
        } else {
            pa = (const float4*)(A + (size_t)(m0 + r) * Kk + k0 + cb);
        }
        const float4* pw = (const float4*)(W + (size_t)(n0 + r) * ldw + k0 + cb);
        #pragma unroll
        for (int i = 0; i < 4; i++) {
            float4 v = pa[i];
            int c = cb + i * 4;
            if (MODE & 1) {
                v.x = lrelu(scA[k0+c+0]*v.x + shA[k0+c+0]);
                v.y = lrelu(scA[k0+c+1]*v.y + shA[k0+c+1]);
                v.z = lrelu(scA[k0+c+2]*v.z + shA[k0+c+2]);
                v.w = lrelu(scA[k0+c+3]*v.w + shA[k0+c+3]);
            }
            As[(c+0)*132 + r] = v.x; As[(c+1)*132 + r] = v.y;
            As[(c+2)*132 + r] = v.z; As[(c+3)*132 + r] = v.w;
            float4 w = pw[i];
            Ws2[(c+0)*132 + r] = w.x; Ws2[(c+1)*132 + r] = w.y;
            Ws2[(c+2)*132 + r] = w.z; Ws2[(c+3)*132 + r] = w.w;
        }
        __syncthreads();
        #pragma unroll 4
        for (int k = 0; k < 32; k++) {
            float4 a0 = *(const float4*)&As[k*132 + ty*8];
            float4 a1 = *(const float4*)&As[k*132 + ty*8 + 4];
            const longlong2* pb = (const longlong2*)(WsU + (size_t)k*66 + tx*4);
            longlong2 wbA = pb[0], wbB = pb[1];
            ull wb[4] = {(ull)wbA.x, (ull)wbA.y, (ull)wbB.x, (ull)wbB.y};
            float a[8] = {a0.x, a0.y, a0.z, a0.w, a1.x, a1.y, a1.z, a1.w};
            #pragma unroll
            for (int i = 0; i < 8; i++) {
                ull ad = dup2(a[i]);
                #pragma unroll
                for (int j = 0; j < 4; j++) fma2(acc2[i][j], ad, wb[j]);
            }
        }
        __syncthreads();
    }
    float colS[8] = {}, colQ[8] = {};
    float colMx[8], colMn[8];
    #pragma unroll
    for (int j = 0; j < 8; j++) { colMx[j] = -3.4e38f; colMn[j] = 3.4e38f; }
    #pragma unroll
    for (int i = 0; i < 8; i++) {
        int m = m0 + ty*8 + i;
        float v[8];
        #pragma unroll
        for (int j = 0; j < 4; j++) unpack2(acc2[i][j], v[2*j], v[2*j+1]);
        if (MODE & 2) {
            #pragma unroll
            for (int j = 0; j < 8; j++) v[j] += g_gterm[(m >> 12) * Nn + n0 + tx*8 + j];
        }
        if (!(MODE & 16)) {
            size_t rowOff = (size_t)m * Nn + n0 + tx*8;
            *(float4*)&C[rowOff]     = make_float4(v[0], v[1], v[2], v[3]);
            *(float4*)&C[rowOff + 4] = make_float4(v[4], v[5], v[6], v[7]);
        }
        #pragma unroll
        for (int j = 0; j < 8; j++) {
            colS[j] += v[j]; colQ[j] += v[j]*v[j];
            colMx[j] = fmaxf(colMx[j], v[j]);
            colMn[j] = fminf(colMn[j], v[j]);
        }
    }
    if (MODE & 4) {
        __syncthreads();
        #pragma unroll
        for (int j = 0; j < 8; j++) {
            As[ty*128 + tx*8 + j]  = colS[j];
            Ws2[ty*128 + tx*8 + j] = colQ[j];
        }
        __syncthreads();
        if (tid < 128) {
            float S = 0.f, Q = 0.f;
            #pragma unroll
            for (int t = 0; t < 16; t++) { S += As[t*128 + tid]; Q += Ws2[t*128 + tid]; }
            atomicAdd(&g_sum[statStage][n0 + tid], (double)S);
            atomicAdd(&g_sqs[statStage][n0 + tid], (double)Q);
        }
        if (MODE & 8) {
            __syncthreads();
            #pragma unroll
            for (int j = 0; j < 8; j++) {
                As[ty*128 + tx*8 + j]  = colMx[j];
                Ws2[ty*128 + tx*8 + j] = colMn[j];
            }
            __syncthreads();
            if (tid < 128) {
                float Mx = -3.4e38f, Mn = 3.4e38f;
                #pragma unroll
                for (int t = 0; t < 16; t++) {
                    Mx = fmaxf(Mx, As[t*128 + tid]);
                    Mn = fminf(Mn, Ws2[t*128 + tid]);
                }
                int b = m0 >> 12;
                atomicMax(&g_hmaxEnc[b * 1024 + n0 + tid], fenc(Mx));
                atomicMin(&g_hminEnc[b * 1024 + n0 + tid], fenc(Mn));
            }
        }
    }
}

// ---------------- global-max finalize (fin5 fused) ---------------------------
__global__ __launch_bounds__(1024) void dg_gmaxfin(double invR,
                                                   const float* __restrict__ G6,
                                                   const float* __restrict__ B6) {
    int b = blockIdx.x, e = threadIdx.x;
    double m = g_sum[5][e] * invR;
    double vv = g_sqs[5][e] * invR - m * m;
    float s = G6[e] * rsqrtf((float)vv + 1e-5f);
    float t = B6[e] - (float)m * s;
    float mx = fdec(g_hmaxEnc[b * 1024 + e]);
    float mn = fdec(g_hminEnc[b * 1024 + e]);
    g_gmaxv[b * 1024 + e] = lrelu(s * (s >= 0.f ? mx : mn) + t);
}

// ---------------- gterm[b,o] = sum_e gmax[b,e] * W7[o,e] ---------------------
__global__ __launch_bounds__(512) void dg_gterm_kernel(const float* __restrict__ W7) {
    int b = blockIdx.x, o = threadIdx.x;
    float acc = 0.f;
    for (int e = 0; e < 1024; e++)
        acc += g_gmaxv[b * 1024 + e] * W7[(size_t)o * 1216 + e];
    g_gterm[b * 512 + o] = acc;
}

// ---------------- final classifier (fin7 fused) ------------------------------
__global__ __launch_bounds__(288) void dg_final(const float* __restrict__ W9,
                                                float* __restrict__ out,
                                                double invR,
                                                const float* __restrict__ G8,
                                                const float* __restrict__ B8) {
    __shared__ float a[32 * 257];
    __shared__ float w[9 * 259];
    __shared__ float scS[256], shS[256];
    int tid = threadIdx.x;
    if (tid < 256) {
        double m = g_sum[7][tid] * invR;
        double vv = g_sqs[7][tid] * invR - m * m;
        float sc = G8[tid] * rsqrtf((float)vv + 1e-5f);
        scS[tid] = sc; shS[tid] = B8[tid] - (float)m * sc;
    }
    for (int l = tid; l < 2304; l += 288) {
        int o = l / 256, c = l % 256;
        w[o * 259 + c] = W9[l];
    }
    __syncthreads();
    int r0 = blockIdx.x * 32;
    for (int l = tid; l < 32 * 256; l += 288) {
        int rr = l / 256, c = l % 256;
        float v = g_hB[(size_t)(r0 + rr) * 256 + c];
        a[rr * 257 + c] = lrelu(scS[c] * v + shS[c]);
    }
    __syncthreads();
    int rr = tid / 9, o = tid % 9;
    float acc = 0.f;
    #pragma unroll 16
    for (int c = 0; c < 256; c++) acc += a[rr * 257 + c] * w[o * 259 + c];
    out[(size_t)(r0 + rr) * 9 + o] = acc;
}

// ---------------- host orchestration -----------------------------------------
extern "C" void kernel_launch(void* const* d_in, const int* in_sizes, int n_in,
                              void* d_out, int out_size) {
    const float* x = (const float*)d_in[0];
    const float* W[10] = {0};
    const float* G[9] = {0};
    const float* Bp[9] = {0};
    if (n_in >= 27 && in_sizes[1] == 1) {
        for (int i = 1; i <= 9; i++) W[i] = (const float*)d_in[1 + i];
        for (int i = 1; i <= 8; i++) {
            G[i]  = (const float*)d_in[11 + 2 * (i - 1)];
            Bp[i] = (const float*)d_in[12 + 2 * (i - 1)];
        }
    } else {
        for (int i = 1; i <= 9; i++) W[i] = (const float*)d_in[i];
        for (int i = 1; i <= 8; i++) {
            G[i]  = (const float*)d_in[10 + 2 * (i - 1)];
            Bp[i] = (const float*)d_in[11 + 2 * (i - 1)];
        }
    }
    float* out = (float*)d_out;

    void* tmp;
    cudaGetSymbolAddress(&tmp, g_negd);  float* negd = (float*)tmp;
    cudaGetSymbolAddress(&tmp, g_hA);    float* hA   = (float*)tmp;
    cudaGetSymbolAddress(&tmp, g_hB);    float* hB   = (float*)tmp;
    cudaGetSymbolAddress(&tmp, g_x1);    float* x1   = (float*)tmp;
    cudaGetSymbolAddress(&tmp, g_x2);    float* x2   = (float*)tmp;
    cudaGetSymbolAddress(&tmp, g_x3);    float* x3   = (float*)tmp;

    const int SQ_SMEM = 2 * 64 * 132 * 4;                 // 67584
    const int EC_SMEM = (64 * 132 + 64 * 68) * 4;         // 51200
    cudaFuncSetAttribute(dg_sqdist128, cudaFuncAttributeMaxDynamicSharedMemorySize, SQ_SMEM);
    cudaFuncSetAttribute(dg_econv64,   cudaFuncAttributeMaxDynamicSharedMemorySize, EC_SMEM);
    cudaFuncSetAttribute(dg_econv64f1, cudaFuncAttributeMaxDynamicSharedMemorySize, EC_SMEM);
    cudaFuncSetAttribute(dg_econv128,  cudaFuncAttributeMaxDynamicSharedMemorySize, EC_SMEM);

    const double invE = 1.0 / (double)EDGES;
    const double invR = 1.0 / (double)ROWS;
    const int EB = EDGES / 128;

    dg_zero_kernel<<<32, 256>>>();

    // ---- block 1 (xyz) ----
    dg_knn_small<<<ROWS, 256>>>(x);
    dg_conv1s<<<EB, 256>>>(x, W[1]);
    dg_econv64f1<<<EB, 256, EC_SMEM>>>(x, W[1], W[2], hB, invE, G[1], Bp[1]);
    dg_maxk<<<ROWS / 4, 256>>>(hB, x1, 1, invE, G[2], Bp[2]);

    // ---- block 2 (x1) ----
    dg_sqdist128<<<dim3(NP / 128, NP / 128, BB), 256, SQ_SMEM>>>(x1, negd);
    dg_select_kernel<<<ROWS, 256>>>();
    dg_econv128<<<EB, 256, EC_SMEM>>>(x1, hA, W[3], 2);
    dg_econv64<<<EB, 256, EC_SMEM>>>(hA, hB, W[4], 2, 3, invE, G[3], Bp[3]);
    dg_maxk<<<ROWS / 4, 256>>>(hB, x2, 3, invE, G[4], Bp[4]);

    // ---- block 3 (x2) ----
    dg_sqdist128<<<dim3(NP / 128, NP / 128, BB), 256, SQ_SMEM>>>(x2, negd);
    dg_select_kernel<<<ROWS, 256>>>();
    dg_econv128<<<EB, 256, EC_SMEM>>>(x2, hA, W[5], 4);
    dg_maxk<<<ROWS / 4, 256>>>(hA, x3, 4, invE, G[5], Bp[5]);

    // ---- point MLPs (cat fused into A loads) ----
    dg_gemm128<4|8|16|32><<<dim3(8, ROWS / 128), 256>>>(
        nullptr, W[6], 192, hA, 1024, 192, -1, 5, 0.0, 0, 0, x1, x2, x3);
    dg_gmaxfin<<<BB, 1024>>>(invR, G[6], Bp[6]);
    dg_gterm_kernel<<<BB, 512>>>(W[7]);
    dg_gemm128<2|4|32><<<dim3(4, ROWS / 128), 256>>>(
        nullptr, W[7] + 1024, 1216, hA, 512, 192, -1, 6, 0.0, 0, 0, x1, x2, x3);
    dg_gemm128<1|4><<<dim3(2, ROWS / 128), 256>>>(
        hA, W[8], 512, hB, 256, 512, 6, 7, invR, G[7], Bp[7], 0, 0, 0);
    dg_final<<<ROWS / 32, 288>>>(W[9], out, invR, G[8], Bp[8]);
}

// round 15
// speedup vs baseline: 1.3846x; 1.0251x over previous
#include <cuda_runtime.h>

#define BB 8
#define NP 4096
#define KNN 20
#define ROWS (BB*NP)          // 32768
#define EDGES (ROWS*KNN)      // 655360

typedef unsigned long long ull;

// ---------------- scratch (device globals; no allocations allowed) ----------
static __device__ float    g_negd[(size_t)BB * NP * NP];        // 512 MB
static __device__ int      g_idx[ROWS * KNN];
static __device__ float    g_hA[(size_t)EDGES * 64];            // 160 MB
static __device__ float    g_hB[(size_t)EDGES * 64];            // 160 MB
static __device__ float    g_x1[(size_t)ROWS * 64];
static __device__ float    g_x2[(size_t)ROWS * 64];
static __device__ float    g_x3[(size_t)ROWS * 64];
static __device__ unsigned g_hmaxEnc[BB * 1024];
static __device__ unsigned g_hminEnc[BB * 1024];
static __device__ float    g_gmaxv[BB * 1024];
static __device__ float    g_gterm[BB * 512];
static __device__ double   g_sum[8][1024];
static __device__ double   g_sqs[8][1024];

__device__ __forceinline__ float lrelu(float v) { return v > 0.f ? v : 0.2f * v; }
__device__ __forceinline__ unsigned fenc(float f) {
    unsigned u = __float_as_uint(f);
    return (u & 0x80000000u) ? ~u : (u | 0x80000000u);
}
__device__ __forceinline__ float fdec(unsigned u) {
    return (u & 0x80000000u) ? __uint_as_float(u & 0x7fffffffu) : __uint_as_float(~u);
}

// ---- packed f32x2 helpers ----------------------------------------------------
__device__ __forceinline__ ull dup2(float v) {
    ull r; asm("mov.b64 %0, {%1, %1};" : "=l"(r) : "f"(v)); return r;
}
__device__ __forceinline__ ull add2(ull a, ull b) {
    ull r; asm("add.rn.f32x2 %0, %1, %2;" : "=l"(r) : "l"(a), "l"(b)); return r;
}
__device__ __forceinline__ void fma2(ull& d, ull a, ull b) {
    asm("fma.rn.f32x2 %0, %1, %2, %0;" : "+l"(d) : "l"(a), "l"(b));
}
__device__ __forceinline__ void unpack2(ull p, float& lo, float& hi) {
    asm("mov.b64 {%0, %1}, %2;" : "=f"(lo), "=f"(hi) : "l"(p));
}

extern __shared__ float dsm[];

// ---------------- zero stats/atomics (must run every replay) ----------------
__global__ void dg_zero_kernel() {
    int i = blockIdx.x * 256 + threadIdx.x;
    if (i < 8192) {
        (&g_sum[0][0])[i] = 0.0;
        (&g_sqs[0][0])[i] = 0.0;
        g_hmaxEnc[i] = 0u;
        g_hminEnc[i] = 0xFFFFFFFFu;
    }
}

// ---------------- kNN on raw xyz: winner-only-rescan top-20 (proven) --------
__global__ __launch_bounds__(256) void dg_knn_small(const float* __restrict__ x) {
    int q = blockIdx.x, b = q >> 12, i = q & 4095;
    const float* xb = x + (size_t)b * 3 * NP;
    int tid = threadIdx.x, lane = tid & 31, wid = tid >> 5;
    float qx = xb[i], qy = xb[NP + i], qz = xb[2 * NP + i];
    float v[16];
    #pragma unroll
    for (int u = 0; u < 16; u++) {
        int j = u * 256 + tid;
        float dx = xb[j] - qx, dy = xb[NP + j] - qy, dz = xb[2 * NP + j] - qz;
        v[u] = -(dx * dx + dy * dy + dz * dz);
    }
    float bv = -3.4e38f; int bi = 0x7fffffff;
    #pragma unroll
    for (int u = 0; u < 16; u++) {
        int j = u * 256 + tid;
        if (v[u] > bv) { bv = v[u]; bi = j; }
    }
    __shared__ float rv[8];
    __shared__ int   ri[8];
    __shared__ int   winS;
    for (int r = 0; r < KNN; r++) {
        float wv = bv; int wi = bi;
        #pragma unroll
        for (int s = 16; s > 0; s >>= 1) {
            float ov = __shfl_xor_sync(0xffffffffu, wv, s);
            int   oi = __shfl_xor_sync(0xffffffffu, wi, s);
            if (ov > wv || (ov == wv && oi < wi)) { wv = ov; wi = oi; }
        }
        if (lane == 0) { rv[wid] = wv; ri[wid] = wi; }
        __syncthreads();
        if (tid == 0) {
            float bbv = rv[0]; int bbi = ri[0];
            #pragma unroll
            for (int w = 1; w < 8; w++)
                if (rv[w] > bbv || (rv[w] == bbv && ri[w] < bbi)) { bbv = rv[w]; bbi = ri[w]; }
            g_idx[q * KNN + r] = bbi;
            winS = bbi;
        }
        __syncthreads();
        int wn = winS;
        if ((wn & 255) == tid) {
            v[wn >> 8] = -3.4e38f;
            bv = -3.4e38f; bi = 0x7fffffff;
            #pragma unroll
            for (int u = 0; u < 16; u++) {
                int j = u * 256 + tid;
                if (v[u] > bv) { bv = v[u]; bi = j; }
            }
        }
        __syncthreads();
    }
}

// ---------------- top-20 select: 2 queries per 512-thread block --------------
// Per-query algorithm identical to proven winner-rescan version.
__global__ __launch_bounds__(512) void dg_select_kernel() {
    int g = threadIdx.x >> 8;              // query group 0/1
    int tid = threadIdx.x & 255;
    size_t q = (size_t)blockIdx.x * 2 + g;
    const float* row = g_negd + q * NP;
    int lane = tid & 31, wid = tid >> 5;
    float v[16];
    #pragma unroll
    for (int u = 0; u < 4; u++) {
        float4 t = *(const float4*)(row + u * 1024 + tid * 4);
        v[u*4+0] = t.x; v[u*4+1] = t.y; v[u*4+2] = t.z; v[u*4+3] = t.w;
    }
    float bv = -3.4e38f; int bi = 0x7fffffff;
    #pragma unroll
    for (int u = 0; u < 4; u++)
        #pragma unroll
        for (int e = 0; e < 4; e++) {
            int j = u * 1024 + tid * 4 + e;
            if (v[u*4+e] > bv) { bv = v[u*4+e]; bi = j; }
        }
    __shared__ float rv[2][8];
    __shared__ int   ri[2][8];
    __shared__ int   winS[2];
    for (int r = 0; r < KNN; r++) {
        float wv = bv; int wi = bi;
        #pragma unroll
        for (int s = 16; s > 0; s >>= 1) {
            float ov = __shfl_xor_sync(0xffffffffu, wv, s);
            int   oi = __shfl_xor_sync(0xffffffffu, wi, s);
            if (ov > wv || (ov == wv && oi < wi)) { wv = ov; wi = oi; }
        }
        if (lane == 0) { rv[g][wid] = wv; ri[g][wid] = wi; }
        __syncthreads();
        if (tid == 0) {
            float bbv = rv[g][0]; int bbi = ri[g][0];
            #pragma unroll
            for (int w = 1; w < 8; w++)
                if (rv[g][w] > bbv || (rv[g][w] == bbv && ri[g][w] < bbi)) { bbv = rv[g][w]; bbi = ri[g][w]; }
            g_idx[q * KNN + r] = bbi;
            winS[g] = bbi;
        }
        __syncthreads();
        int wn = winS[g];
        if (((wn >> 2) & 255) == tid) {
            int slot = ((wn >> 10) << 2) | (wn & 3);
            v[slot] = -3.4e38f;
            bv = -3.4e38f; bi = 0x7fffffff;
            #pragma unroll
            for (int u = 0; u < 4; u++)
                #pragma unroll
                for (int e = 0; e < 4; e++) {
                    int j = u * 1024 + tid * 4 + e;
                    if (v[u*4+e] > bv) { bv = v[u*4+e]; bi = j; }
                }
        }
        __syncthreads();
    }
}

// ---------------- symmetric pairwise -||a-b||^2 ------------------------------
// Computes only tiles bx >= by; mirror tile written via smem transpose.
// Mirrored values are bit-identical to direct computation ((-d)*(-d) == d*d).
__global__ __launch_bounds__(256) void dg_sqdist128sym(const float* __restrict__ X,
                                                       float* __restrict__ C) {
    int bx = blockIdx.x, by = blockIdx.y;
    if (bx < by) return;
    int bz = blockIdx.z;
    const float* A = X + (size_t)bz * NP * 64;
    float* Cb = C + (size_t)bz * NP * NP;
    float* As = dsm;              // [64][132]
    float* Bs = dsm + 64 * 132;   // [64][132] (negated)
    int m0 = by * 128, n0 = bx * 128;
    int tid = threadIdx.x;
    {
        int r = tid >> 1, cb = (tid & 1) * 32;
        const float4* pa = (const float4*)(A + (size_t)(m0 + r) * 64 + cb);
        const float4* pb = (const float4*)(A + (size_t)(n0 + r) * 64 + cb);
        #pragma unroll
        for (int i = 0; i < 8; i++) {
            float4 va = pa[i], vb = pb[i];
            int c = cb + i * 4;
            As[(c+0)*132 + r] = va.x; As[(c+1)*132 + r] = va.y;
            As[(c+2)*132 + r] = va.z; As[(c+3)*132 + r] = va.w;
            Bs[(c+0)*132 + r] = -vb.x; Bs[(c+1)*132 + r] = -vb.y;
            Bs[(c+2)*132 + r] = -vb.z; Bs[(c+3)*132 + r] = -vb.w;
        }
    }
    __syncthreads();
    int tx = tid & 15, ty = tid >> 4;
    ull acc2[8][4] = {};
    const ull* BsU = (const ull*)Bs;
    #pragma unroll 4
    for (int k = 0; k < 64; k++) {
        float4 a0 = *(const float4*)&As[k*132 + ty*8];
        float4 a1 = *(const float4*)&As[k*132 + ty*8 + 4];
        const longlong2* pb = (const longlong2*)(BsU + (size_t)k*66 + tx*4);
        longlong2 nbA = pb[0], nbB = pb[1];
        ull nb[4] = {(ull)nbA.x, (ull)nbA.y, (ull)nbB.x, (ull)nbB.y};
        float a[8] = {a0.x, a0.y, a0.z, a0.w, a1.x, a1.y, a1.z, a1.w};
        #pragma unroll
        for (int i = 0; i < 8; i++) {
            ull ad = dup2(a[i]);
            #pragma unroll
            for (int j = 0; j < 4; j++) {
                ull d = add2(ad, nb[j]);
                fma2(acc2[i][j], d, d);
            }
        }
    }
    // normal tile store (rows m, cols n)
    #pragma unroll
    for (int i = 0; i < 8; i++) {
        float v[8];
        #pragma unroll
        for (int j = 0; j < 4; j++) unpack2(acc2[i][j], v[2*j], v[2*j+1]);
        size_t rowOff = (size_t)(m0 + ty*8 + i) * NP + n0 + tx*8;
        *(float4*)&Cb[rowOff]     = make_float4(-v[0], -v[1], -v[2], -v[3]);
        *(float4*)&Cb[rowOff + 4] = make_float4(-v[4], -v[5], -v[6], -v[7]);
    }
    if (bx == by) return;
    // mirror tile (rows n, cols m) via smem transpose (reuses As/Bs region)
    __syncthreads();
    float* T = dsm;               // [128][133]
    #pragma unroll
    for (int i = 0; i < 8; i++) {
        float v[8];
        #pragma unroll
        for (int j = 0; j < 4; j++) unpack2(acc2[i][j], v[2*j], v[2*j+1]);
        #pragma unroll
        for (int j = 0; j < 8; j++)
            T[(tx*8 + j) * 133 + ty*8 + i] = -v[j];
    }
    __syncthreads();
    {
        int col = tid & 127, rbase = tid >> 7;   // 2 rows per pass
        for (int chunk = 0; chunk < 64; chunk++) {
            int r = chunk * 2 + rbase;
            Cb[(size_t)(n0 + r) * NP + m0 + col] = T[r * 133 + col];
        }
    }
}

// ---------------- conv1 stats-only (no store) ---------------------------------
__global__ __launch_bounds__(256) void dg_conv1s(const float* __restrict__ x,
                                                 const float* __restrict__ W1) {
    __shared__ float fS[6 * 132];
    __shared__ float Ws[6 * 68];
    __shared__ int qS[128], nbS[128];
    __shared__ float redS[1024], redQ[1024];
    int e0 = blockIdx.x * 128;
    int tid = threadIdx.x;
    if (tid < 128) { int e = e0 + tid; qS[tid] = e / KNN; nbS[tid] = g_idx[e]; }
    for (int l = tid; l < 384; l += 256) {
        int o = l / 6, c = l % 6;
        Ws[c * 68 + o] = W1[l];
    }
    __syncthreads();
    for (int l = tid; l < 1024; l += 256) {
        int r = l >> 3, c = l & 7;
        if (c < 6) {
            int q = qS[r], nb = nbS[r];
            const float* xb = x + (size_t)(q >> 12) * 3 * NP;
            int qi = q & 4095;
            float v = (c < 3) ? (xb[c * NP + nb] - xb[c * NP + qi])
                              : xb[(c - 3) * NP + qi];
            fS[c * 132 + r] = v;
        }
    }
    __syncthreads();
    int tx = tid & 15, ty = tid >> 4;
    float acc[8][4] = {};
    #pragma unroll
    for (int k = 0; k < 6; k++) {
        float a[8], bb[4];
        #pragma unroll
        for (int i = 0; i < 8; i++) a[i] = fS[k*132 + ty*8 + i];
        float4 bv = *(const float4*)&Ws[k*68 + tx*4];
        bb[0]=bv.x; bb[1]=bv.y; bb[2]=bv.z; bb[3]=bv.w;
        #pragma unroll
        for (int i = 0; i < 8; i++)
            #pragma unroll
            for (int j = 0; j < 4; j++)
                acc[i][j] += a[i] * bb[j];
    }
    float s[4] = {}, sq[4] = {};
    #pragma unroll
    for (int i = 0; i < 8; i++)
        #pragma unroll
        for (int j = 0; j < 4; j++) { s[j] += acc[i][j]; sq[j] += acc[i][j]*acc[i][j]; }
    #pragma unroll
    for (int j = 0; j < 4; j++) { redS[ty*64 + tx*4 + j] = s[j]; redQ[ty*64 + tx*4 + j] = sq[j]; }
    __syncthreads();
    if (tid < 64) {
        float S = 0.f, Q = 0.f;
        #pragma unroll
        for (int t = 0; t < 16; t++) { S += redS[t*64 + tid]; Q += redQ[t*64 + tid]; }
        atomicAdd(&g_sum[0][tid], (double)S);
        atomicAdd(&g_sqs[0][tid], (double)Q);
    }
}

// ---------------- fused conv1 -> act0(fin fused) -> econv64(W2) --------------
__global__ __launch_bounds__(256) void dg_econv64f1(const float* __restrict__ x,
                                                    const float* __restrict__ W1,
                                                    const float* __restrict__ W2,
                                                    float* __restrict__ out,
                                                    double invE,
                                                    const float* __restrict__ G1,
                                                    const float* __restrict__ B1) {
    float* fS = dsm;              // [64][132]
    float* Ws = dsm + 64 * 132;   // [64][68]
    __shared__ float fS6[6 * 132];
    __shared__ float Ws1[6 * 68];
    __shared__ int qS[128], nbS[128];
    __shared__ float scS[64], shS[64];
    int e0 = blockIdx.x * 128;
    int tid = threadIdx.x;
    if (tid < 128) { int e = e0 + tid; qS[tid] = e / KNN; nbS[tid] = g_idx[e]; }
    if (tid < 64) {
        double m = g_sum[0][tid] * invE;
        double vv = g_sqs[0][tid] * invE - m * m;
        float sc = G1[tid] * rsqrtf((float)vv + 1e-5f);
        scS[tid] = sc; shS[tid] = B1[tid] - (float)m * sc;
    }
    for (int l = tid; l < 384; l += 256) {
        int o = l / 6, c = l % 6;
        Ws1[c * 68 + o] = W1[l];
    }
    for (int l = tid; l < 4096; l += 256) {
        int c = l >> 6, n = l & 63;
        Ws[c * 68 + n] = W2[n * 64 + c];
    }
    __syncthreads();
    for (int l = tid; l < 1024; l += 256) {
        int r = l >> 3, c = l & 7;
        if (c < 6) {
            int q = qS[r], nb = nbS[r];
            const float* xb = x + (size_t)(q >> 12) * 3 * NP;
            int qi = q & 4095;
            float v = (c < 3) ? (xb[c * NP + nb] - xb[c * NP + qi])
                              : xb[(c - 3) * NP + qi];
            fS6[c * 132 + r] = v;
        }
    }
    __syncthreads();
    int tx = tid & 15, ty = tid >> 4;
    float h[8][4] = {};
    #pragma unroll
    for (int k = 0; k < 6; k++) {
        float a[8], bb[4];
        #pragma unroll
        for (int i = 0; i < 8; i++) a[i] = fS6[k*132 + ty*8 + i];
        float4 bv = *(const float4*)&Ws1[k*68 + tx*4];
        bb[0]=bv.x; bb[1]=bv.y; bb[2]=bv.z; bb[3]=bv.w;
        #pragma unroll
        for (int i = 0; i < 8; i++)
            #pragma unroll
            for (int j = 0; j < 4; j++)
                h[i][j] += a[i] * bb[j];
    }
    #pragma unroll
    for (int i = 0; i < 8; i++)
        #pragma unroll
        for (int j = 0; j < 4; j++) {
            int col = tx*4 + j, row = ty*8 + i;
            fS[col*132 + row] = lrelu(scS[col]*h[i][j] + shS[col]);
        }
    __syncthreads();
    ull acc2[8][2] = {};
    const ull* WsU = (const ull*)Ws;
    #pragma unroll 4
    for (int k = 0; k < 64; k++) {
        float4 a0 = *(const float4*)&fS[k*132 + ty*8];
        float4 a1 = *(const float4*)&fS[k*132 + ty*8 + 4];
        longlong2 wb = *(const longlong2*)(WsU + (size_t)k*34 + tx*2);
        ull b0 = (ull)wb.x, b1 = (ull)wb.y;
        float a[8] = {a0.x, a0.y, a0.z, a0.w, a1.x, a1.y, a1.z, a1.w};
        #pragma unroll
        for (int i = 0; i < 8; i++) {
            ull ad = dup2(a[i]);
            fma2(acc2[i][0], ad, b0);
            fma2(acc2[i][1], ad, b1);
        }
    }
    float s[4] = {}, sq[4] = {};
    #pragma unroll
    for (int i = 0; i < 8; i++) {
        float v[4];
        unpack2(acc2[i][0], v[0], v[1]);
        unpack2(acc2[i][1], v[2], v[3]);
        size_t rowOff = (size_t)(e0 + ty*8 + i) * 64 + tx*4;
        *(float4*)&out[rowOff] = make_float4(v[0], v[1], v[2], v[3]);
        #pragma unroll
        for (int j = 0; j < 4; j++) { s[j] += v[j]; sq[j] += v[j]*v[j]; }
    }
    __syncthreads();
    float* redS = fS;
    float* redQ = fS + 1024;
    #pragma unroll
    for (int j = 0; j < 4; j++) { redS[ty*64 + tx*4 + j] = s[j]; redQ[ty*64 + tx*4 + j] = sq[j]; }
    __syncthreads();
    if (tid < 64) {
        float S = 0.f, Q = 0.f;
        #pragma unroll
        for (int t = 0; t < 16; t++) { S += redS[t*64 + tid]; Q += redQ[t*64 + tid]; }
        atomicAdd(&g_sum[1][tid], (double)S);
        atomicAdd(&g_sqs[1][tid], (double)Q);
    }
}

// ---------------- edge conv 64 -> 64 (act w/ fused finalize; f32x2 core) -----
__global__ __launch_bounds__(256) void dg_econv64(const float* __restrict__ in,
                                                  float* __restrict__ out,
                                                  const float* __restrict__ W,
                                                  int sIn, int sOut, double invE,
                                                  const float* __restrict__ Gi,
                                                  const float* __restrict__ Bi) {
    float* fS = dsm;
    float* Ws = dsm + 64 * 132;
    __shared__ float scS[64], shS[64];
    int e0 = blockIdx.x * 128;
    int tid = threadIdx.x;
    if (tid < 64) {
        double m = g_sum[sIn][tid] * invE;
        double vv = g_sqs[sIn][tid] * invE - m * m;
        float sc = Gi[tid] * rsqrtf((float)vv + 1e-5f);
        scS[tid] = sc; shS[tid] = Bi[tid] - (float)m * sc;
    }
    for (int l = tid; l < 4096; l += 256) {
        int c = l >> 6, n = l & 63;
        Ws[c * 68 + n] = W[n * 64 + c];
    }
    __syncthreads();
    {
        int r = tid >> 1, cb = (tid & 1) * 32;
        const float4* p = (const float4*)(in + (size_t)(e0 + r) * 64 + cb);
        #pragma unroll
        for (int i = 0; i < 8; i++) {
            float4 v = p[i];
            int c = cb + i * 4;
            fS[(c+0)*132 + r] = lrelu(scS[c+0]*v.x + shS[c+0]);
            fS[(c+1)*132 + r] = lrelu(scS[c+1]*v.y + shS[c+1]);
            fS[(c+2)*132 + r] = lrelu(scS[c+2]*v.z + shS[c+2]);
            fS[(c+3)*132 + r] = lrelu(scS[c+3]*v.w + shS[c+3]);
        }
    }
    __syncthreads();
    int tx = tid & 15, ty = tid >> 4;
    ull acc2[8][2] = {};
    const ull* WsU = (const ull*)Ws;
    #pragma unroll 4
    for (int k = 0; k < 64; k++) {
        float4 a0 = *(const float4*)&fS[k*132 + ty*8];
        float4 a1 = *(const float4*)&fS[k*132 + ty*8 + 4];
        longlong2 wb = *(const longlong2*)(WsU + (size_t)k*34 + tx*2);
        ull b0 = (ull)wb.x, b1 = (ull)wb.y;
        float a[8] = {a0.x, a0.y, a0.z, a0.w, a1.x, a1.y, a1.z, a1.w};
        #pragma unroll
        for (int i = 0; i < 8; i++) {
            ull ad = dup2(a[i]);
            fma2(acc2[i][0], ad, b0);
            fma2(acc2[i][1], ad, b1);
        }
    }
    float s[4] = {}, sq[4] = {};
    #pragma unroll
    for (int i = 0; i < 8; i++) {
        float v[4];
        unpack2(acc2[i][0], v[0], v[1]);
        unpack2(acc2[i][1], v[2], v[3]);
        size_t rowOff = (size_t)(e0 + ty*8 + i) * 64 + tx*4;
        *(float4*)&out[rowOff] = make_float4(v[0], v[1], v[2], v[3]);
        #pragma unroll
        for (int j = 0; j < 4; j++) { s[j] += v[j]; sq[j] += v[j]*v[j]; }
    }
    __syncthreads();
    float* redS = fS;
    float* redQ = fS + 1024;
    #pragma unroll
    for (int j = 0; j < 4; j++) { redS[ty*64 + tx*4 + j] = s[j]; redQ[ty*64 + tx*4 + j] = sq[j]; }
    __syncthreads();
    if (tid < 64) {
        float S = 0.f, Q = 0.f;
        #pragma unroll
        for (int t = 0; t < 16; t++) { S += redS[t*64 + tid]; Q += redQ[t*64 + tid]; }
        atomicAdd(&g_sum[sOut][tid], (double)S);
        atomicAdd(&g_sqs[sOut][tid], (double)Q);
    }
}

// ---------------- edge conv 128 -> 64 as GEMM, gather, f32x2 core ------------
__global__ __launch_bounds__(256) void dg_econv128(const float* __restrict__ xin,
                                                   float* __restrict__ out,
                                                   const float* __restrict__ W,
                                                   int sOut) {
    float* fS = dsm;
    float* Ws = dsm + 64 * 132;
    __shared__ int qS[128], nbS[128];
    int e0 = blockIdx.x * 128;
    int tid = threadIdx.x;
    if (tid < 128) {
        int e = e0 + tid;
        int q = e / KNN;
        qS[tid] = q;
        nbS[tid] = (q >> 12) * NP + g_idx[e];
    }
    __syncthreads();
    int tx = tid & 15, ty = tid >> 4;
    ull acc2[8][2] = {};
    const ull* WsU = (const ull*)Ws;
    for (int kt = 0; kt < 2; kt++) {
        int r = tid >> 1, cb = (tid & 1) * 32;
        int q = qS[r];
        const float4* pq = (const float4*)(xin + (size_t)q * 64 + cb);
        if (kt == 0) {
            const float4* pn = (const float4*)(xin + (size_t)nbS[r] * 64 + cb);
            #pragma unroll
            for (int i = 0; i < 8; i++) {
                float4 vn = pn[i], vq = pq[i];
                int c = cb + i * 4;
                fS[(c+0)*132 + r] = vn.x - vq.x;
                fS[(c+1)*132 + r] = vn.y - vq.y;
                fS[(c+2)*132 + r] = vn.z - vq.z;
                fS[(c+3)*132 + r] = vn.w - vq.w;
            }
        } else {
            #pragma unroll
            for (int i = 0; i < 8; i++) {
                float4 vq = pq[i];
                int c = cb + i * 4;
                fS[(c+0)*132 + r] = vq.x;
                fS[(c+1)*132 + r] = vq.y;
                fS[(c+2)*132 + r] = vq.z;
                fS[(c+3)*132 + r] = vq.w;
            }
        }
        for (int l = tid; l < 4096; l += 256) {
            int c = l >> 6, n = l & 63;
            Ws[c * 68 + n] = W[n * 128 + kt * 64 + c];
        }
        __syncthreads();
        #pragma unroll 4
        for (int k = 0; k < 64; k++) {
            float4 a0 = *(const float4*)&fS[k*132 + ty*8];
            float4 a1 = *(const float4*)&fS[k*132 + ty*8 + 4];
            longlong2 wb = *(const longlong2*)(WsU + (size_t)k*34 + tx*2);
            ull b0 = (ull)wb.x, b1 = (ull)wb.y;
            float a[8] = {a0.x, a0.y, a0.z, a0.w, a1.x, a1.y, a1.z, a1.w};
            #pragma unroll
            for (int i = 0; i < 8; i++) {
                ull ad = dup2(a[i]);
                fma2(acc2[i][0], ad, b0);
                fma2(acc2[i][1], ad, b1);
            }
        }
        __syncthreads();
    }
    float s[4] = {}, sq[4] = {};
    #pragma unroll
    for (int i = 0; i < 8; i++) {
        float v[4];
        unpack2(acc2[i][0], v[0], v[1]);
        unpack2(acc2[i][1], v[2], v[3]);
        size_t rowOff = (size_t)(e0 + ty*8 + i) * 64 + tx*4;
        *(float4*)&out[rowOff] = make_float4(v[0], v[1], v[2], v[3]);
        #pragma unroll
        for (int j = 0; j < 4; j++) { s[j] += v[j]; sq[j] += v[j]*v[j]; }
    }
    float* redS = fS;
    float* redQ = fS + 1024;
    #pragma unroll
    for (int j = 0; j < 4; j++) { redS[ty*64 + tx*4 + j] = s[j]; redQ[ty*64 + tx*4 + j] = sq[j]; }
    __syncthreads();
    if (tid < 64) {
        float S = 0.f, Q = 0.f;
        #pragma unroll
        for (int t = 0; t < 16; t++) { S += redS[t*64 + tid]; Q += redQ[t*64 + tid]; }
        atomicAdd(&g_sum[sOut][tid], (double)S);
        atomicAdd(&g_sqs[sOut][tid], (double)Q);
    }
}

// ---------------- max over k neighbors (finalize fused) ----------------------
__global__ __launch_bounds__(256) void dg_maxk(const float* __restrict__ hraw,
                                               float* __restrict__ xout, int stage,
                                               double invE,
                                               const float* __restrict__ Gi,
                                               const float* __restrict__ Bi) {
    __shared__ float scS[64], shS[64];
    int tid = threadIdx.x;
    if (tid < 64) {
        double m = g_sum[stage][tid] * invE;
        double vv = g_sqs[stage][tid] * invE - m * m;
        float sc = Gi[tid] * rsqrtf((float)vv + 1e-5f);
        scS[tid] = sc; shS[tid] = Bi[tid] - (float)m * sc;
    }
    __syncthreads();
    int t = tid & 63;
    int q = blockIdx.x * 4 + (tid >> 6);
    float s = scS[t], sh = shS[t];
    float m = -3.4e38f;
    for (int j = 0; j < KNN; j++) {
        float v = lrelu(hraw[((size_t)q * KNN + j) * 64 + t] * s + sh);
        m = fmaxf(m, v);
    }
    xout[(size_t)q * 64 + t] = m;
}

// ---------------- 128x128 tiled GEMM, f32x2 core, fused epilogues ------------
// MODE bit0: act(actStage, finalize fused) on A; bit1: +gterm;
// bit2: stats(statStage); bit3: per-(batch,ch) raw max/min; bit4: skip C store;
// bit5: A = concat(x1|x2|x3) per 64-col block (Kk must be 192).
template <int MODE>
__global__ __launch_bounds__(256) void dg_gemm128(
    const float* __restrict__ A,
    const float* __restrict__ W, int ldw,
    float* __restrict__ C,
    int Nn, int Kk, int actStage, int statStage,
    double invAct, const float* __restrict__ Ga, const float* __restrict__ Ba,
    const float* __restrict__ X1, const float* __restrict__ X2,
    const float* __restrict__ X3) {
    __shared__ float As[32 * 132];
    __shared__ float Ws2[32 * 132];
    __shared__ float scA[512], shA[512];
    int m0 = blockIdx.y * 128, n0 = blockIdx.x * 128;
    int tid = threadIdx.x, tx = tid & 15, ty = tid >> 4;
    if (MODE & 1) {
        for (int c = tid; c < Kk; c += 256) {
            double m = g_sum[actStage][c] * invAct;
            double vv = g_sqs[actStage][c] * invAct - m * m;
            float sc = Ga[c] * rsqrtf((float)vv + 1e-5f);
            scA[c] = sc; shA[c] = Ba[c] - (float)m * sc;
        }
        __syncthreads();
    }
    ull acc2[8][4] = {};
    const ull* WsU = (const ull*)Ws2;
    for (int k0 = 0; k0 < Kk; k0 += 32) {
        int r = tid >> 1, cb = (tid & 1) * 16;
        const float4* pa;
        if (MODE & 32) {
            int kk = k0 + cb;
            const float* src = (kk < 64) ? X1 : (kk < 128) ? X2 : X3;
            pa = (const float4*)(src + (size_t)(m0 + r) * 64 + (kk & 63));
        } else {
            pa = (const float4*)(A + (size_t)(m0 + r) * Kk + k0 + cb);
        }
        const float4* pw = (const float4*)(W + (size_t)(n0 + r) * ldw + k0 + cb);
        #pragma unroll
        for (int i = 0; i < 4; i++) {
            float4 v = pa[i];
            int c = cb + i * 4;
            if (MODE & 1) {
                v.x = lrelu(scA[k0+c+0]*v.x + shA[k0+c+0]);
                v.y = lrelu(scA[k0+c+1]*v.y + shA[k0+c+1]);
                v.z = lrelu(scA[k0+c+2]*v.z + shA[k0+c+2]);
                v.w = lrelu(scA[k0+c+3]*v.w + shA[k0+c+3]);
            }
            As[(c+0)*132 + r] = v.x; As[(c+1)*132 + r] = v.y;
            As[(c+2)*132 + r] = v.z; As[(c+3)*132 + r] = v.w;
            float4 w = pw[i];
            Ws2[(c+0)*132 + r] = w.x; Ws2[(c+1)*132 + r] = w.y;
            Ws2[(c+2)*132 + r] = w.z; Ws2[(c+3)*132 + r] = w.w;
        }
        __syncthreads();
        #pragma unroll 4
        for (int k = 0; k < 32; k++) {
            float4 a0 = *(const float4*)&As[k*132 + ty*8];
            float4 a1 = *(const float4*)&As[k*132 + ty*8 + 4];
            const longlong2* pb = (const longlong2*)(WsU + (size_t)k*66 + tx*4);
            longlong2 wbA = pb[0], wbB = pb[1];
            ull wb[4] = {(ull)wbA.x, (ull)wbA.y, (ull)wbB.x, (ull)wbB.y};
            float a[8] = {a0.x, a0.y, a0.z, a0.w, a1.x, a1.y, a1.z, a1.w};
            #pragma unroll
            for (int i = 0; i < 8; i++) {
                ull ad = dup2(a[i]);
                #pragma unroll
                for (int j = 0; j < 4; j++) fma2(acc2[i][j], ad, wb[j]);
            }
        }
        __syncthreads();
    }
    float colS[8] = {}, colQ[8] = {};
    float colMx[8], colMn[8];
    #pragma unroll
    for (int j = 0; j < 8; j++) { colMx[j] = -3.4e38f; colMn[j] = 3.4e38f; }
    #pragma unroll
    for (int i = 0; i < 8; i++) {
        int m = m0 + ty*8 + i;
        float v[8];
        #pragma unroll
        for (int j = 0; j < 4; j++) unpack2(acc2[i][j], v[2*j], v[2*j+1]);
        if (MODE & 2) {
            #pragma unroll
            for (int j = 0; j < 8; j++) v[j] += g_gterm[(m >> 12) * Nn + n0 + tx*8 + j];
        }
        if (!(MODE & 16)) {
            size_t rowOff = (size_t)m * Nn + n0 + tx*8;
            *(float4*)&C[rowOff]     = make_float4(v[0], v[1], v[2], v[3]);
            *(float4*)&C[rowOff + 4] = make_float4(v[4], v[5], v[6], v[7]);
        }
        #pragma unroll
        for (int j = 0; j < 8; j++) {
            colS[j] += v[j]; colQ[j] += v[j]*v[j];
            colMx[j] = fmaxf(colMx[j], v[j]);
            colMn[j] = fminf(colMn[j], v[j]);
        }
    }
    if (MODE & 4) {
        __syncthreads();
        #pragma unroll
        for (int j = 0; j < 8; j++) {
            As[ty*128 + tx*8 + j]  = colS[j];
            Ws2[ty*128 + tx*8 + j] = colQ[j];
        }
        __syncthreads();
        if (tid < 128) {
            float S = 0.f, Q = 0.f;
            #pragma unroll
            for (int t = 0; t < 16; t++) { S += As[t*128 + tid]; Q += Ws2[t*128 + tid]; }
            atomicAdd(&g_sum[statStage][n0 + tid], (double)S);
            atomicAdd(&g_sqs[statStage][n0 + tid], (double)Q);
        }
        if (MODE & 8) {
            __syncthreads();
            #pragma unroll
            for (int j = 0; j < 8; j++) {
                As[ty*128 + tx*8 + j]  = colMx[j];
                Ws2[ty*128 + tx*8 + j] = colMn[j];
            }
            __syncthreads();
            if (tid < 128) {
                float Mx = -3.4e38f, Mn = 3.4e38f;
                #pragma unroll
                for (int t = 0; t < 16; t++) {
                    Mx = fmaxf(Mx, As[t*128 + tid]);
                    Mn = fminf(Mn, Ws2[t*128 + tid]);
                }
                int b = m0 >> 12;
                atomicMax(&g_hmaxEnc[b * 1024 + n0 + tid], fenc(Mx));
                atomicMin(&g_hminEnc[b * 1024 + n0 + tid], fenc(Mn));
            }
        }
    }
}

// ---------------- global-max finalize (fin5 fused) ---------------------------
__global__ __launch_bounds__(1024) void dg_gmaxfin(double invR,
                                                   const float* __restrict__ G6,
                                                   const float* __restrict__ B6) {
    int b = blockIdx.x, e = threadIdx.x;
    double m = g_sum[5][e] * invR;
    double vv = g_sqs[5][e] * invR - m * m;
    float s = G6[e] * rsqrtf((float)vv + 1e-5f);
    float t = B6[e] - (float)m * s;
    float mx = fdec(g_hmaxEnc[b * 1024 + e]);
    float mn = fdec(g_hminEnc[b * 1024 + e]);
    g_gmaxv[b * 1024 + e] = lrelu(s * (s >= 0.f ? mx : mn) + t);
}

// ---------------- gterm[b,o] = sum_e gmax[b,e] * W7[o,e] ---------------------
__global__ __launch_bounds__(512) void dg_gterm_kernel(const float* __restrict__ W7) {
    int b = blockIdx.x, o = threadIdx.x;
    float acc = 0.f;
    for (int e = 0; e < 1024; e++)
        acc += g_gmaxv[b * 1024 + e] * W7[(size_t)o * 1216 + e];
    g_gterm[b * 512 + o] = acc;
}

// ---------------- final classifier (fin7 fused) ------------------------------
__global__ __launch_bounds__(288) void dg_final(const float* __restrict__ W9,
                                                float* __restrict__ out,
                                                double invR,
                                                const float* __restrict__ G8,
                                                const float* __restrict__ B8) {
    __shared__ float a[32 * 257];
    __shared__ float w[9 * 259];
    __shared__ float scS[256], shS[256];
    int tid = threadIdx.x;
    if (tid < 256) {
        double m = g_sum[7][tid] * invR;
        double vv = g_sqs[7][tid] * invR - m * m;
        float sc = G8[tid] * rsqrtf((float)vv + 1e-5f);
        scS[tid] = sc; shS[tid] = B8[tid] - (float)m * sc;
    }
    for (int l = tid; l < 2304; l += 288) {
        int o = l / 256, c = l % 256;
        w[o * 259 + c] = W9[l];
    }
    __syncthreads();
    int r0 = blockIdx.x * 32;
    for (int l = tid; l < 32 * 256; l += 288) {
        int rr = l / 256, c = l % 256;
        float v = g_hB[(size_t)(r0 + rr) * 256 + c];
        a[rr * 257 + c] = lrelu(scS[c] * v + shS[c]);
    }
    __syncthreads();
    int rr = tid / 9, o = tid % 9;
    float acc = 0.f;
    #pragma unroll 16
    for (int c = 0; c < 256; c++) acc += a[rr * 257 + c] * w[o * 259 + c];
    out[(size_t)(r0 + rr) * 9 + o] = acc;
}

// ---------------- host orchestration -----------------------------------------
extern "C" void kernel_launch(void* const* d_in, const int* in_sizes, int n_in,
                              void* d_out, int out_size) {
    const float* x = (const float*)d_in[0];
    const float* W[10] = {0};
    const float* G[9] = {0};
    const float* Bp[9] = {0};
    if (n_in >= 27 && in_sizes[1] == 1) {
        for (int i = 1; i <= 9; i++) W[i] = (const float*)d_in[1 + i];
        for (int i = 1; i <= 8; i++) {
            G[i]  = (const float*)d_in[11 + 2 * (i - 1)];
            Bp[i] = (const float*)d_in[12 + 2 * (i - 1)];
        }
    } else {
        for (int i = 1; i <= 9; i++) W[i] = (const float*)d_in[i];
        for (int i = 1; i <= 8; i++) {
            G[i]  = (const float*)d_in[10 + 2 * (i - 1)];
            Bp[i] = (const float*)d_in[11 + 2 * (i - 1)];
        }
    }
    float* out = (float*)d_out;

    void* tmp;
    cudaGetSymbolAddress(&tmp, g_negd);  float* negd = (float*)tmp;
    cudaGetSymbolAddress(&tmp, g_hA);    float* hA   = (float*)tmp;
    cudaGetSymbolAddress(&tmp, g_hB);    float* hB   = (float*)tmp;
    cudaGetSymbolAddress(&tmp, g_x1);    float* x1   = (float*)tmp;
    cudaGetSymbolAddress(&tmp, g_x2);    float* x2   = (float*)tmp;
    cudaGetSymbolAddress(&tmp, g_x3);    float* x3   = (float*)tmp;

    const int SQ_SMEM = 128 * 133 * 4;                    // 68096 (max of tiles / transpose)
    const int EC_SMEM = (64 * 132 + 64 * 68) * 4;         // 51200
    cudaFuncSetAttribute(dg_sqdist128sym, cudaFuncAttributeMaxDynamicSharedMemorySize, SQ_SMEM);
    cudaFuncSetAttribute(dg_econv64,   cudaFuncAttributeMaxDynamicSharedMemorySize, EC_SMEM);
    cudaFuncSetAttribute(dg_econv64f1, cudaFuncAttributeMaxDynamicSharedMemorySize, EC_SMEM);
    cudaFuncSetAttribute(dg_econv128,  cudaFuncAttributeMaxDynamicSharedMemorySize, EC_SMEM);

    const double invE = 1.0 / (double)EDGES;
    const double invR = 1.0 / (double)ROWS;
    const int EB = EDGES / 128;

    dg_zero_kernel<<<32, 256>>>();

    // ---- block 1 (xyz) ----
    dg_knn_small<<<ROWS, 256>>>(x);
    dg_conv1s<<<EB, 256>>>(x, W[1]);
    dg_econv64f1<<<EB, 256, EC_SMEM>>>(x, W[1], W[2], hB, invE, G[1], Bp[1]);
    dg_maxk<<<ROWS / 4, 256>>>(hB, x1, 1, invE, G[2], Bp[2]);

    // ---- block 2 (x1) ----
    dg_sqdist128sym<<<dim3(NP / 128, NP / 128, BB), 256, SQ_SMEM>>>(x1, negd);
    dg_select_kernel<<<ROWS / 2, 512>>>();
    dg_econv128<<<EB, 256, EC_SMEM>>>(x1, hA, W[3], 2);
    dg_econv64<<<EB, 256, EC_SMEM>>>(hA, hB, W[4], 2, 3, invE, G[3], Bp[3]);
    dg_maxk<<<ROWS / 4, 256>>>(hB, x2, 3, invE, G[4], Bp[4]);

    // ---- block 3 (x2) ----
    dg_sqdist128sym<<<dim3(NP / 128, NP / 128, BB), 256, SQ_SMEM>>>(x2, negd);
    dg_select_kernel<<<ROWS / 2, 512>>>();
    dg_econv128<<<EB, 256, EC_SMEM>>>(x2, hA, W[5], 4);
    dg_maxk<<<ROWS / 4, 256>>>(hA, x3, 4, invE, G[5], Bp[5]);

    // ---- point MLPs (cat fused into A loads) ----
    dg_gemm128<4|8|16|32><<<dim3(8, ROWS / 128), 256>>>(
        nullptr, W[6], 192, hA, 1024, 192, -1, 5, 0.0, 0, 0, x1, x2, x3);
    dg_gmaxfin<<<BB, 1024>>>(invR, G[6], Bp[6]);
    dg_gterm_kernel<<<BB, 512>>>(W[7]);
    dg_gemm128<2|4|32><<<dim3(4, ROWS / 128), 256>>>(
        nullptr, W[7] + 1024, 1216, hA, 512, 192, -1, 6, 0.0, 0, 0, x1, x2, x3);
    dg_gemm128<1|4><<<dim3(2, ROWS / 128), 256>>>(
        hA, W[8], 512, hB, 256, 512, 6, 7, invR, G[7], Bp[7], 0, 0, 0);
    dg_final<<<ROWS / 32, 288>>>(W[9], out, invR, G[8], Bp[8]);
}

// round 16
// speedup vs baseline: 1.4233x; 1.0280x over previous
#include <cuda_runtime.h>

#define BB 8
#define NP 4096
#define KNN 20
#define ROWS (BB*NP)          // 32768
#define EDGES (ROWS*KNN)      // 655360

typedef unsigned long long ull;

// ---------------- scratch (device globals; no allocations allowed) ----------
static __device__ float    g_negd[(size_t)BB * NP * NP];        // 512 MB
static __device__ int      g_idx[ROWS * KNN];
static __device__ float    g_hA[(size_t)EDGES * 64];            // 160 MB
static __device__ float    g_hB[(size_t)EDGES * 64];            // 160 MB
static __device__ float    g_x1[(size_t)ROWS * 64];
static __device__ float    g_x2[(size_t)ROWS * 64];
static __device__ float    g_x3[(size_t)ROWS * 64];
static __device__ unsigned g_hmaxEnc[BB * 1024];
static __device__ unsigned g_hminEnc[BB * 1024];
static __device__ float    g_gmaxv[BB * 1024];
static __device__ float    g_gterm[BB * 512];
static __device__ double   g_sum[8][1024];
static __device__ double   g_sqs[8][1024];

__device__ __forceinline__ float lrelu(float v) { return v > 0.f ? v : 0.2f * v; }
__device__ __forceinline__ unsigned fenc(float f) {
    unsigned u = __float_as_uint(f);
    return (u & 0x80000000u) ? ~u : (u | 0x80000000u);
}
__device__ __forceinline__ float fdec(unsigned u) {
    return (u & 0x80000000u) ? __uint_as_float(u & 0x7fffffffu) : __uint_as_float(~u);
}

// ---- packed f32x2 helpers ----------------------------------------------------
__device__ __forceinline__ ull dup2(float v) {
    ull r; asm("mov.b64 %0, {%1, %1};" : "=l"(r) : "f"(v)); return r;
}
__device__ __forceinline__ ull add2(ull a, ull b) {
    ull r; asm("add.rn.f32x2 %0, %1, %2;" : "=l"(r) : "l"(a), "l"(b)); return r;
}
__device__ __forceinline__ void fma2(ull& d, ull a, ull b) {
    asm("fma.rn.f32x2 %0, %1, %2, %0;" : "+l"(d) : "l"(a), "l"(b));
}
__device__ __forceinline__ void unpack2(ull p, float& lo, float& hi) {
    asm("mov.b64 {%0, %1}, %2;" : "=f"(lo), "=f"(hi) : "l"(p));
}

extern __shared__ float dsm[];

// ---------------- zero stats/atomics (must run every replay) ----------------
__global__ void dg_zero_kernel() {
    int i = blockIdx.x * 256 + threadIdx.x;
    if (i < 8192) {
        (&g_sum[0][0])[i] = 0.0;
        (&g_sqs[0][0])[i] = 0.0;
        g_hmaxEnc[i] = 0u;
        g_hminEnc[i] = 0xFFFFFFFFu;
    }
}

// ---------------- kNN on raw xyz: winner-only-rescan top-20 (proven) --------
__global__ __launch_bounds__(256) void dg_knn_small(const float* __restrict__ x) {
    int q = blockIdx.x, b = q >> 12, i = q & 4095;
    const float* xb = x + (size_t)b * 3 * NP;
    int tid = threadIdx.x, lane = tid & 31, wid = tid >> 5;
    float qx = xb[i], qy = xb[NP + i], qz = xb[2 * NP + i];
    float v[16];
    #pragma unroll
    for (int u = 0; u < 16; u++) {
        int j = u * 256 + tid;
        float dx = xb[j] - qx, dy = xb[NP + j] - qy, dz = xb[2 * NP + j] - qz;
        v[u] = -(dx * dx + dy * dy + dz * dz);
    }
    float bv = -3.4e38f; int bi = 0x7fffffff;
    #pragma unroll
    for (int u = 0; u < 16; u++) {
        int j = u * 256 + tid;
        if (v[u] > bv) { bv = v[u]; bi = j; }
    }
    __shared__ float rv[8];
    __shared__ int   ri[8];
    __shared__ int   winS;
    for (int r = 0; r < KNN; r++) {
        float wv = bv; int wi = bi;
        #pragma unroll
        for (int s = 16; s > 0; s >>= 1) {
            float ov = __shfl_xor_sync(0xffffffffu, wv, s);
            int   oi = __shfl_xor_sync(0xffffffffu, wi, s);
            if (ov > wv || (ov == wv && oi < wi)) { wv = ov; wi = oi; }
        }
        if (lane == 0) { rv[wid] = wv; ri[wid] = wi; }
        __syncthreads();
        if (tid == 0) {
            float bbv = rv[0]; int bbi = ri[0];
            #pragma unroll
            for (int w = 1; w < 8; w++)
                if (rv[w] > bbv || (rv[w] == bbv && ri[w] < bbi)) { bbv = rv[w]; bbi = ri[w]; }
            g_idx[q * KNN + r] = bbi;
            winS = bbi;
        }
        __syncthreads();
        int wn = winS;
        if ((wn & 255) == tid) {
            v[wn >> 8] = -3.4e38f;
            bv = -3.4e38f; bi = 0x7fffffff;
            #pragma unroll
            for (int u = 0; u < 16; u++) {
                int j = u * 256 + tid;
                if (v[u] > bv) { bv = v[u]; bi = j; }
            }
        }
        __syncthreads();
    }
}

// ---------------- top-20 select: 2 queries per 512-thread block (proven) -----
__global__ __launch_bounds__(512) void dg_select_kernel() {
    int g = threadIdx.x >> 8;
    int tid = threadIdx.x & 255;
    size_t q = (size_t)blockIdx.x * 2 + g;
    const float* row = g_negd + q * NP;
    int lane = tid & 31, wid = tid >> 5;
    float v[16];
    #pragma unroll
    for (int u = 0; u < 4; u++) {
        float4 t = *(const float4*)(row + u * 1024 + tid * 4);
        v[u*4+0] = t.x; v[u*4+1] = t.y; v[u*4+2] = t.z; v[u*4+3] = t.w;
    }
    float bv = -3.4e38f; int bi = 0x7fffffff;
    #pragma unroll
    for (int u = 0; u < 4; u++)
        #pragma unroll
        for (int e = 0; e < 4; e++) {
            int j = u * 1024 + tid * 4 + e;
            if (v[u*4+e] > bv) { bv = v[u*4+e]; bi = j; }
        }
    __shared__ float rv[2][8];
    __shared__ int   ri[2][8];
    __shared__ int   winS[2];
    for (int r = 0; r < KNN; r++) {
        float wv = bv; int wi = bi;
        #pragma unroll
        for (int s = 16; s > 0; s >>= 1) {
            float ov = __shfl_xor_sync(0xffffffffu, wv, s);
            int   oi = __shfl_xor_sync(0xffffffffu, wi, s);
            if (ov > wv || (ov == wv && oi < wi)) { wv = ov; wi = oi; }
        }
        if (lane == 0) { rv[g][wid] = wv; ri[g][wid] = wi; }
        __syncthreads();
        if (tid == 0) {
            float bbv = rv[g][0]; int bbi = ri[g][0];
            #pragma unroll
            for (int w = 1; w < 8; w++)
                if (rv[g][w] > bbv || (rv[g][w] == bbv && ri[g][w] < bbi)) { bbv = rv[g][w]; bbi = ri[g][w]; }
            g_idx[q * KNN + r] = bbi;
            winS[g] = bbi;
        }
        __syncthreads();
        int wn = winS[g];
        if (((wn >> 2) & 255) == tid) {
            int slot = ((wn >> 10) << 2) | (wn & 3);
            v[slot] = -3.4e38f;
            bv = -3.4e38f; bi = 0x7fffffff;
            #pragma unroll
            for (int u = 0; u < 4; u++)
                #pragma unroll
                for (int e = 0; e < 4; e++) {
                    int j = u * 1024 + tid * 4 + e;
                    if (v[u*4+e] > bv) { bv = v[u*4+e]; bi = j; }
                }
        }
        __syncthreads();
    }
}

// ---------------- symmetric pairwise -||a-b||^2 (proven) ---------------------
__global__ __launch_bounds__(256) void dg_sqdist128sym(const float* __restrict__ X,
                                                       float* __restrict__ C) {
    int bx = blockIdx.x, by = blockIdx.y;
    if (bx < by) return;
    int bz = blockIdx.z;
    const float* A = X + (size_t)bz * NP * 64;
    float* Cb = C + (size_t)bz * NP * NP;
    float* As = dsm;              // [64][132]
    float* Bs = dsm + 64 * 132;   // [64][132] (negated)
    int m0 = by * 128, n0 = bx * 128;
    int tid = threadIdx.x;
    {
        int r = tid >> 1, cb = (tid & 1) * 32;
        const float4* pa = (const float4*)(A + (size_t)(m0 + r) * 64 + cb);
        const float4* pb = (const float4*)(A + (size_t)(n0 + r) * 64 + cb);
        #pragma unroll
        for (int i = 0; i < 8; i++) {
            float4 va = pa[i], vb = pb[i];
            int c = cb + i * 4;
            As[(c+0)*132 + r] = va.x; As[(c+1)*132 + r] = va.y;
            As[(c+2)*132 + r] = va.z; As[(c+3)*132 + r] = va.w;
            Bs[(c+0)*132 + r] = -vb.x; Bs[(c+1)*132 + r] = -vb.y;
            Bs[(c+2)*132 + r] = -vb.z; Bs[(c+3)*132 + r] = -vb.w;
        }
    }
    __syncthreads();
    int tx = tid & 15, ty = tid >> 4;
    ull acc2[8][4] = {};
    const ull* BsU = (const ull*)Bs;
    #pragma unroll 4
    for (int k = 0; k < 64; k++) {
        float4 a0 = *(const float4*)&As[k*132 + ty*8];
        float4 a1 = *(const float4*)&As[k*132 + ty*8 + 4];
        const longlong2* pb = (const longlong2*)(BsU + (size_t)k*66 + tx*4);
        longlong2 nbA = pb[0], nbB = pb[1];
        ull nb[4] = {(ull)nbA.x, (ull)nbA.y, (ull)nbB.x, (ull)nbB.y};
        float a[8] = {a0.x, a0.y, a0.z, a0.w, a1.x, a1.y, a1.z, a1.w};
        #pragma unroll
        for (int i = 0; i < 8; i++) {
            ull ad = dup2(a[i]);
            #pragma unroll
            for (int j = 0; j < 4; j++) {
                ull d = add2(ad, nb[j]);
                fma2(acc2[i][j], d, d);
            }
        }
    }
    #pragma unroll
    for (int i = 0; i < 8; i++) {
        float v[8];
        #pragma unroll
        for (int j = 0; j < 4; j++) unpack2(acc2[i][j], v[2*j], v[2*j+1]);
        size_t rowOff = (size_t)(m0 + ty*8 + i) * NP + n0 + tx*8;
        *(float4*)&Cb[rowOff]     = make_float4(-v[0], -v[1], -v[2], -v[3]);
        *(float4*)&Cb[rowOff + 4] = make_float4(-v[4], -v[5], -v[6], -v[7]);
    }
    if (bx == by) return;
    __syncthreads();
    float* T = dsm;               // [128][133]
    #pragma unroll
    for (int i = 0; i < 8; i++) {
        float v[8];
        #pragma unroll
        for (int j = 0; j < 4; j++) unpack2(acc2[i][j], v[2*j], v[2*j+1]);
        #pragma unroll
        for (int j = 0; j < 8; j++)
            T[(tx*8 + j) * 133 + ty*8 + i] = -v[j];
    }
    __syncthreads();
    {
        int col = tid & 127, rbase = tid >> 7;
        for (int chunk = 0; chunk < 64; chunk++) {
            int r = chunk * 2 + rbase;
            Cb[(size_t)(n0 + r) * NP + m0 + col] = T[r * 133 + col];
        }
    }
}

// ---------------- conv1 stats-only (proven, 128-edge tile) -------------------
__global__ __launch_bounds__(256) void dg_conv1s(const float* __restrict__ x,
                                                 const float* __restrict__ W1) {
    __shared__ float fS[6 * 132];
    __shared__ float Ws[6 * 68];
    __shared__ int qS[128], nbS[128];
    __shared__ float redS[1024], redQ[1024];
    int e0 = blockIdx.x * 128;
    int tid = threadIdx.x;
    if (tid < 128) { int e = e0 + tid; qS[tid] = e / KNN; nbS[tid] = g_idx[e]; }
    for (int l = tid; l < 384; l += 256) {
        int o = l / 6, c = l % 6;
        Ws[c * 68 + o] = W1[l];
    }
    __syncthreads();
    for (int l = tid; l < 1024; l += 256) {
        int r = l >> 3, c = l & 7;
        if (c < 6) {
            int q = qS[r], nb = nbS[r];
            const float* xb = x + (size_t)(q >> 12) * 3 * NP;
            int qi = q & 4095;
            float v = (c < 3) ? (xb[c * NP + nb] - xb[c * NP + qi])
                              : xb[(c - 3) * NP + qi];
            fS[c * 132 + r] = v;
        }
    }
    __syncthreads();
    int tx = tid & 15, ty = tid >> 4;
    float acc[8][4] = {};
    #pragma unroll
    for (int k = 0; k < 6; k++) {
        float a[8], bb[4];
        #pragma unroll
        for (int i = 0; i < 8; i++) a[i] = fS[k*132 + ty*8 + i];
        float4 bv = *(const float4*)&Ws[k*68 + tx*4];
        bb[0]=bv.x; bb[1]=bv.y; bb[2]=bv.z; bb[3]=bv.w;
        #pragma unroll
        for (int i = 0; i < 8; i++)
            #pragma unroll
            for (int j = 0; j < 4; j++)
                acc[i][j] += a[i] * bb[j];
    }
    float s[4] = {}, sq[4] = {};
    #pragma unroll
    for (int i = 0; i < 8; i++)
        #pragma unroll
        for (int j = 0; j < 4; j++) { s[j] += acc[i][j]; sq[j] += acc[i][j]*acc[i][j]; }
    #pragma unroll
    for (int j = 0; j < 4; j++) { redS[ty*64 + tx*4 + j] = s[j]; redQ[ty*64 + tx*4 + j] = sq[j]; }
    __syncthreads();
    if (tid < 64) {
        float S = 0.f, Q = 0.f;
        #pragma unroll
        for (int t = 0; t < 16; t++) { S += redS[t*64 + tid]; Q += redQ[t*64 + tid]; }
        atomicAdd(&g_sum[0][tid], (double)S);
        atomicAdd(&g_sqs[0][tid], (double)Q);
    }
}

// ======== edge convs: 256-edge x 64-out tile, 8x8 per thread (LSU-balanced) ==
#define EPAD 260   // row pad for 256-wide edge dimension (1040B = 16B-aligned rows)

// ---------------- fused conv1 -> act0 -> econv64(W2), 256-edge tile ----------
__global__ __launch_bounds__(256) void dg_econv64f1(const float* __restrict__ x,
                                                    const float* __restrict__ W1,
                                                    const float* __restrict__ W2,
                                                    float* __restrict__ out,
                                                    double invE,
                                                    const float* __restrict__ G1,
                                                    const float* __restrict__ B1) {
    float* fS  = dsm;                    // [64][EPAD]
    float* Ws  = dsm + 64 * EPAD;        // [64][68]
    float* fS6 = Ws + 64 * 68;           // [6][EPAD]
    float* Ws1 = fS6 + 6 * EPAD;         // [6][68]
    __shared__ int qS[256], nbS[256];
    __shared__ float scS[64], shS[64];
    int e0 = blockIdx.x * 256;
    int tid = threadIdx.x;
    { int e = e0 + tid; qS[tid] = e / KNN; nbS[tid] = g_idx[e]; }
    if (tid < 64) {
        double m = g_sum[0][tid] * invE;
        double vv = g_sqs[0][tid] * invE - m * m;
        float sc = G1[tid] * rsqrtf((float)vv + 1e-5f);
        scS[tid] = sc; shS[tid] = B1[tid] - (float)m * sc;
    }
    for (int l = tid; l < 384; l += 256) {
        int o = l / 6, c = l % 6;
        Ws1[c * 68 + o] = W1[l];
    }
    for (int l = tid; l < 4096; l += 256) {
        int c = l >> 6, n = l & 63;
        Ws[c * 68 + n] = W2[n * 64 + c];
    }
    __syncthreads();
    {   // each thread builds its own edge's 6 features
        int r = tid;
        int q = qS[r], nb = nbS[r];
        const float* xb = x + (size_t)(q >> 12) * 3 * NP;
        int qi = q & 4095;
        #pragma unroll
        for (int c = 0; c < 3; c++) {
            fS6[c * EPAD + r]       = xb[c * NP + nb] - xb[c * NP + qi];
            fS6[(c + 3) * EPAD + r] = xb[c * NP + qi];
        }
    }
    __syncthreads();
    int tx = tid & 7, ty = tid >> 3;     // 8 col-groups, 32 row-groups
    float h[8][8] = {};
    #pragma unroll
    for (int k = 0; k < 6; k++) {
        float a[8], bb[8];
        #pragma unroll
        for (int i = 0; i < 8; i++) a[i] = fS6[k*EPAD + ty*8 + i];
        float4 b0 = *(const float4*)&Ws1[k*68 + tx*8];
        float4 b1 = *(const float4*)&Ws1[k*68 + tx*8 + 4];
        bb[0]=b0.x; bb[1]=b0.y; bb[2]=b0.z; bb[3]=b0.w;
        bb[4]=b1.x; bb[5]=b1.y; bb[6]=b1.z; bb[7]=b1.w;
        #pragma unroll
        for (int i = 0; i < 8; i++)
            #pragma unroll
            for (int j = 0; j < 8; j++)
                h[i][j] += a[i] * bb[j];
    }
    #pragma unroll
    for (int i = 0; i < 8; i++)
        #pragma unroll
        for (int j = 0; j < 8; j++) {
            int col = tx*8 + j, row = ty*8 + i;
            fS[col*EPAD + row] = lrelu(scS[col]*h[i][j] + shS[col]);
        }
    __syncthreads();
    ull acc2[8][4] = {};
    const ull* WsU = (const ull*)Ws;
    #pragma unroll 4
    for (int k = 0; k < 64; k++) {
        float4 a0 = *(const float4*)&fS[k*EPAD + ty*8];
        float4 a1 = *(const float4*)&fS[k*EPAD + ty*8 + 4];
        const longlong2* pb = (const longlong2*)(WsU + (size_t)k*34 + tx*4);
        longlong2 wbA = pb[0], wbB = pb[1];
        ull wb[4] = {(ull)wbA.x, (ull)wbA.y, (ull)wbB.x, (ull)wbB.y};
        float a[8] = {a0.x, a0.y, a0.z, a0.w, a1.x, a1.y, a1.z, a1.w};
        #pragma unroll
        for (int i = 0; i < 8; i++) {
            ull ad = dup2(a[i]);
            #pragma unroll
            for (int j = 0; j < 4; j++) fma2(acc2[i][j], ad, wb[j]);
        }
    }
    float s[8] = {}, sq[8] = {};
    #pragma unroll
    for (int i = 0; i < 8; i++) {
        float v[8];
        #pragma unroll
        for (int j = 0; j < 4; j++) unpack2(acc2[i][j], v[2*j], v[2*j+1]);
        size_t rowOff = (size_t)(e0 + ty*8 + i) * 64 + tx*8;
        *(float4*)&out[rowOff]     = make_float4(v[0], v[1], v[2], v[3]);
        *(float4*)&out[rowOff + 4] = make_float4(v[4], v[5], v[6], v[7]);
        #pragma unroll
        for (int j = 0; j < 8; j++) { s[j] += v[j]; sq[j] += v[j]*v[j]; }
    }
    __syncthreads();
    float* redS = fS;
    float* redQ = fS + 2048;
    #pragma unroll
    for (int j = 0; j < 8; j++) { redS[ty*64 + tx*8 + j] = s[j]; redQ[ty*64 + tx*8 + j] = sq[j]; }
    __syncthreads();
    if (tid < 64) {
        float S = 0.f, Q = 0.f;
        #pragma unroll
        for (int t = 0; t < 32; t++) { S += redS[t*64 + tid]; Q += redQ[t*64 + tid]; }
        atomicAdd(&g_sum[1][tid], (double)S);
        atomicAdd(&g_sqs[1][tid], (double)Q);
    }
}

// ---------------- edge conv 64 -> 64, 256-edge tile, 8x8 ---------------------
__global__ __launch_bounds__(256) void dg_econv64(const float* __restrict__ in,
                                                  float* __restrict__ out,
                                                  const float* __restrict__ W,
                                                  int sIn, int sOut, double invE,
                                                  const float* __restrict__ Gi,
                                                  const float* __restrict__ Bi) {
    float* fS = dsm;                     // [64][EPAD]
    float* Ws = dsm + 64 * EPAD;         // [64][68]
    __shared__ float scS[64], shS[64];
    int e0 = blockIdx.x * 256;
    int tid = threadIdx.x;
    if (tid < 64) {
        double m = g_sum[sIn][tid] * invE;
        double vv = g_sqs[sIn][tid] * invE - m * m;
        float sc = Gi[tid] * rsqrtf((float)vv + 1e-5f);
        scS[tid] = sc; shS[tid] = Bi[tid] - (float)m * sc;
    }
    for (int l = tid; l < 4096; l += 256) {
        int c = l >> 6, n = l & 63;
        Ws[c * 68 + n] = W[n * 64 + c];
    }
    __syncthreads();
    {   // one edge row per thread
        int r = tid;
        const float4* p = (const float4*)(in + (size_t)(e0 + r) * 64);
        #pragma unroll
        for (int i = 0; i < 16; i++) {
            float4 v = p[i];
            int c = i * 4;
            fS[(c+0)*EPAD + r] = lrelu(scS[c+0]*v.x + shS[c+0]);
            fS[(c+1)*EPAD + r] = lrelu(scS[c+1]*v.y + shS[c+1]);
            fS[(c+2)*EPAD + r] = lrelu(scS[c+2]*v.z + shS[c+2]);
            fS[(c+3)*EPAD + r] = lrelu(scS[c+3]*v.w + shS[c+3]);
        }
    }
    __syncthreads();
    int tx = tid & 7, ty = tid >> 3;
    ull acc2[8][4] = {};
    const ull* WsU = (const ull*)Ws;
    #pragma unroll 4
    for (int k = 0; k < 64; k++) {
        float4 a0 = *(const float4*)&fS[k*EPAD + ty*8];
        float4 a1 = *(const float4*)&fS[k*EPAD + ty*8 + 4];
        const longlong2* pb = (const longlong2*)(WsU + (size_t)k*34 + tx*4);
        longlong2 wbA = pb[0], wbB = pb[1];
        ull wb[4] = {(ull)wbA.x, (ull)wbA.y, (ull)wbB.x, (ull)wbB.y};
        float a[8] = {a0.x, a0.y, a0.z, a0.w, a1.x, a1.y, a1.z, a1.w};
        #pragma unroll
        for (int i = 0; i < 8; i++) {
            ull ad = dup2(a[i]);
            #pragma unroll
            for (int j = 0; j < 4; j++) fma2(acc2[i][j], ad, wb[j]);
        }
    }
    float s[8] = {}, sq[8] = {};
    #pragma unroll
    for (int i = 0; i < 8; i++) {
        float v[8];
        #pragma unroll
        for (int j = 0; j < 4; j++) unpack2(acc2[i][j], v[2*j], v[2*j+1]);
        size_t rowOff = (size_t)(e0 + ty*8 + i) * 64 + tx*8;
        *(float4*)&out[rowOff]     = make_float4(v[0], v[1], v[2], v[3]);
        *(float4*)&out[rowOff + 4] = make_float4(v[4], v[5], v[6], v[7]);
        #pragma unroll
        for (int j = 0; j < 8; j++) { s[j] += v[j]; sq[j] += v[j]*v[j]; }
    }
    __syncthreads();
    float* redS = fS;
    float* redQ = fS + 2048;
    #pragma unroll
    for (int j = 0; j < 8; j++) { redS[ty*64 + tx*8 + j] = s[j]; redQ[ty*64 + tx*8 + j] = sq[j]; }
    __syncthreads();
    if (tid < 64) {
        float S = 0.f, Q = 0.f;
        #pragma unroll
        for (int t = 0; t < 32; t++) { S += redS[t*64 + tid]; Q += redQ[t*64 + tid]; }
        atomicAdd(&g_sum[sOut][tid], (double)S);
        atomicAdd(&g_sqs[sOut][tid], (double)Q);
    }
}

// ---------------- edge conv 128 -> 64, 256-edge tile, 8x8, gather ------------
__global__ __launch_bounds__(256) void dg_econv128(const float* __restrict__ xin,
                                                   float* __restrict__ out,
                                                   const float* __restrict__ W,
                                                   int sOut) {
    float* fS = dsm;                     // [64][EPAD]
    float* Ws = dsm + 64 * EPAD;         // [64][68]
    __shared__ int qS[256], nbS[256];
    int e0 = blockIdx.x * 256;
    int tid = threadIdx.x;
    {
        int e = e0 + tid;
        int q = e / KNN;
        qS[tid] = q;
        nbS[tid] = (q >> 12) * NP + g_idx[e];
    }
    __syncthreads();
    int tx = tid & 7, ty = tid >> 3;
    ull acc2[8][4] = {};
    const ull* WsU = (const ull*)Ws;
    for (int kt = 0; kt < 2; kt++) {
        int r = tid;
        int q = qS[r];
        const float4* pq = (const float4*)(xin + (size_t)q * 64);
        if (kt == 0) {
            const float4* pn = (const float4*)(xin + (size_t)nbS[r] * 64);
            #pragma unroll
            for (int i = 0; i < 16; i++) {
                float4 vn = pn[i], vq = pq[i];
                int c = i * 4;
                fS[(c+0)*EPAD + r] = vn.x - vq.x;
                fS[(c+1)*EPAD + r] = vn.y - vq.y;
                fS[(c+2)*EPAD + r] = vn.z - vq.z;
                fS[(c+3)*EPAD + r] = vn.w - vq.w;
            }
        } else {
            #pragma unroll
            for (int i = 0; i < 16; i++) {
                float4 vq = pq[i];
                int c = i * 4;
                fS[(c+0)*EPAD + r] = vq.x;
                fS[(c+1)*EPAD + r] = vq.y;
                fS[(c+2)*EPAD + r] = vq.z;
                fS[(c+3)*EPAD + r] = vq.w;
            }
        }
        for (int l = tid; l < 4096; l += 256) {
            int c = l >> 6, n = l & 63;
            Ws[c * 68 + n] = W[n * 128 + kt * 64 + c];
        }
        __syncthreads();
        #pragma unroll 4
        for (int k = 0; k < 64; k++) {
            float4 a0 = *(const float4*)&fS[k*EPAD + ty*8];
            float4 a1 = *(const float4*)&fS[k*EPAD + ty*8 + 4];
            const longlong2* pb = (const longlong2*)(WsU + (size_t)k*34 + tx*4);
            longlong2 wbA = pb[0], wbB = pb[1];
            ull wb[4] = {(ull)wbA.x, (ull)wbA.y, (ull)wbB.x, (ull)wbB.y};
            float a[8] = {a0.x, a0.y, a0.z, a0.w, a1.x, a1.y, a1.z, a1.w};
            #pragma unroll
            for (int i = 0; i < 8; i++) {
                ull ad = dup2(a[i]);
                #pragma unroll
                for (int j = 0; j < 4; j++) fma2(acc2[i][j], ad, wb[j]);
            }
        }
        __syncthreads();
    }
    float s[8] = {}, sq[8] = {};
    #pragma unroll
    for (int i = 0; i < 8; i++) {
        float v[8];
        #pragma unroll
        for (int j = 0; j < 4; j++) unpack2(acc2[i][j], v[2*j], v[2*j+1]);
        size_t rowOff = (size_t)(e0 + ty*8 + i) * 64 + tx*8;
        *(float4*)&out[rowOff]     = make_float4(v[0], v[1], v[2], v[3]);
        *(float4*)&out[rowOff + 4] = make_float4(v[4], v[5], v[6], v[7]);
        #pragma unroll
        for (int j = 0; j < 8; j++) { s[j] += v[j]; sq[j] += v[j]*v[j]; }
    }
    float* redS = fS;
    float* redQ = fS + 2048;
    #pragma unroll
    for (int j = 0; j < 8; j++) { redS[ty*64 + tx*8 + j] = s[j]; redQ[ty*64 + tx*8 + j] = sq[j]; }
    __syncthreads();
    if (tid < 64) {
        float S = 0.f, Q = 0.f;
        #pragma unroll
        for (int t = 0; t < 32; t++) { S += redS[t*64 + tid]; Q += redQ[t*64 + tid]; }
        atomicAdd(&g_sum[sOut][tid], (double)S);
        atomicAdd(&g_sqs[sOut][tid], (double)Q);
    }
}

// ---------------- max over k neighbors (finalize fused) ----------------------
__global__ __launch_bounds__(256) void dg_maxk(const float* __restrict__ hraw,
                                               float* __restrict__ xout, int stage,
                                               double invE,
                                               const float* __restrict__ Gi,
                                               const float* __restrict__ Bi) {
    __shared__ float scS[64], shS[64];
    int tid = threadIdx.x;
    if (tid < 64) {
        double m = g_sum[stage][tid] * invE;
        double vv = g_sqs[stage][tid] * invE - m * m;
        float sc = Gi[tid] * rsqrtf((float)vv + 1e-5f);
        scS[tid] = sc; shS[tid] = Bi[tid] - (float)m * sc;
    }
    __syncthreads();
    int t = tid & 63;
    int q = blockIdx.x * 4 + (tid >> 6);
    float s = scS[t], sh = shS[t];
    float m = -3.4e38f;
    for (int j = 0; j < KNN; j++) {
        float v = lrelu(hraw[((size_t)q * KNN + j) * 64 + t] * s + sh);
        m = fmaxf(m, v);
    }
    xout[(size_t)q * 64 + t] = m;
}

// ---------------- 128x128 tiled GEMM, f32x2 core, fused epilogues ------------
template <int MODE>
__global__ __launch_bounds__(256) void dg_gemm128(
    const float* __restrict__ A,
    const float* __restrict__ W, int ldw,
    float* __restrict__ C,
    int Nn, int Kk, int actStage, int statStage,
    double invAct, const float* __restrict__ Ga, const float* __restrict__ Ba,
    const float* __restrict__ X1, const float* __restrict__ X2,
    const float* __restrict__ X3) {
    __shared__ float As[32 * 132];
    __shared__ float Ws2[32 * 132];
    __shared__ float scA[512], shA[512];
    int m0 = blockIdx.y * 128, n0 = blockIdx.x * 128;
    int tid = threadIdx.x, tx = tid & 15, ty = tid >> 4;
    if (MODE & 1) {
        for (int c = tid; c < Kk; c += 256) {
            double m = g_sum[actStage][c] * invAct;
            double vv = g_sqs[actStage][c] * invAct - m * m;
            float sc = Ga[c] * rsqrtf((float)vv + 1e-5f);
            scA[c] = sc; shA[c] = Ba[c] - (float)m * sc;
        }
        __syncthreads();
    }
    ull acc2[8][4] = {};
    const ull* WsU = (const ull*)Ws2;
    for (int k0 = 0; k0 < Kk; k0 += 32) {
        int r = tid >> 1, cb = (tid & 1) * 16;
        const float4* pa;
        if (MODE & 32) {
            int kk = k0 + cb;
            const float* src = (kk < 64) ? X1 : (kk < 128) ? X2 : X3;
            pa = (const float4*)(src + (size_t)(m0 + r) * 64 + (kk & 63));
        } else {
            pa = (const float4*)(A + (size_t)(m0 + r) * Kk + k0 + cb);
        }
        const float4* pw = (const float4*)(W + (size_t)(n0 + r) * ldw + k0 + cb);
        #pragma unroll
        for (int i = 0; i < 4; i++) {
            float4 v = pa[i];
            int c = cb + i * 4;
            if (MODE & 1) {
                v.x = lrelu(scA[k0+c+0]*v.x + shA[k0+c+0]);
                v.y = lrelu(scA[k0+c+1]*v.y + shA[k0+c+1]);
                v.z = lrelu(scA[k0+c+2]*v.z + shA[k0+c+2]);
                v.w = lrelu(scA[k0+c+3]*v.w + shA[k0+c+3]);
            }
            As[(c+0)*132 + r] = v.x; As[(c+1)*132 + r] = v.y;
            As[(c+2)*132 + r] = v.z; As[(c+3)*132 + r] = v.w;
            float4 w = pw[i];
            Ws2[(c+0)*132 + r] = w.x; Ws2[(c+1)*132 + r] = w.y;
            Ws2[(c+2)*132 + r] = w.z; Ws2[(c+3)*132 + r] = w.w;
        }
        __syncthreads();
        #pragma unroll 4
        for (int k = 0; k < 32; k++) {
            float4 a0 = *(const float4*)&As[k*132 + ty*8];
            float4 a1 = *(const float4*)&As[k*132 + ty*8 + 4];
            const longlong2* pb = (const longlong2*)(WsU + (size_t)k*66 + tx*4);
            longlong2 wbA = pb[0], wbB = pb[1];
            ull wb[4] = {(ull)wbA.x, (ull)wbA.y, (ull)wbB.x, (ull)wbB.y};
            float a[8] = {a0.x, a0.y, a0.z, a0.w, a1.x, a1.y, a1.z, a1.w};
            #pragma unroll
            for (int i = 0; i < 8; i++) {
                ull ad = dup2(a[i]);
                #pragma unroll
                for (int j = 0; j < 4; j++) fma2(acc2[i][j], ad, wb[j]);
            }
        }
        __syncthreads();
    }
    float colS[8] = {}, colQ[8] = {};
    float colMx[8], colMn[8];
    #pragma unroll
    for (int j = 0; j < 8; j++) { colMx[j] = -3.4e38f; colMn[j] = 3.4e38f; }
    #pragma unroll
    for (int i = 0; i < 8; i++) {
        int m = m0 + ty*8 + i;
        float v[8];
        #pragma unroll
        for (int j = 0; j < 4; j++) unpack2(acc2[i][j], v[2*j], v[2*j+1]);
        if (MODE & 2) {
            #pragma unroll
            for (int j = 0; j < 8; j++) v[j] += g_gterm[(m >> 12) * Nn + n0 + tx*8 + j];
        }
        if (!(MODE & 16)) {
            size_t rowOff = (size_t)m * Nn + n0 + tx*8;
            *(float4*)&C[rowOff]     = make_float4(v[0], v[1], v[2], v[3]);
            *(float4*)&C[rowOff + 4] = make_float4(v[4], v[5], v[6], v[7]);
        }
        #pragma unroll
        for (int j = 0; j < 8; j++) {
            colS[j] += v[j]; colQ[j] += v[j]*v[j];
            colMx[j] = fmaxf(colMx[j], v[j]);
            colMn[j] = fminf(colMn[j], v[j]);
        }
    }
    if (MODE & 4) {
        __syncthreads();
        #pragma unroll
        for (int j = 0; j < 8; j++) {
            As[ty*128 + tx*8 + j]  = colS[j];
            Ws2[ty*128 + tx*8 + j] = colQ[j];
        }
        __syncthreads();
        if (tid < 128) {
            float S = 0.f, Q = 0.f;
            #pragma unroll
            for (int t = 0; t < 16; t++) { S += As[t*128 + tid]; Q += Ws2[t*128 + tid]; }
            atomicAdd(&g_sum[statStage][n0 + tid], (double)S);
            atomicAdd(&g_sqs[statStage][n0 + tid], (double)Q);
        }
        if (MODE & 8) {
            __syncthreads();
            #pragma unroll
            for (int j = 0; j < 8; j++) {
                As[ty*128 + tx*8 + j]  = colMx[j];
                Ws2[ty*128 + tx*8 + j] = colMn[j];
            }
            __syncthreads();
            if (tid < 128) {
                float Mx = -3.4e38f, Mn = 3.4e38f;
                #pragma unroll
                for (int t = 0; t < 16; t++) {
                    Mx = fmaxf(Mx, As[t*128 + tid]);
                    Mn = fminf(Mn, Ws2[t*128 + tid]);
                }
                int b = m0 >> 12;
                atomicMax(&g_hmaxEnc[b * 1024 + n0 + tid], fenc(Mx));
                atomicMin(&g_hminEnc[b * 1024 + n0 + tid], fenc(Mn));
            }
        }
    }
}

// ---------------- global-max finalize (fin5 fused) ---------------------------
__global__ __launch_bounds__(1024) void dg_gmaxfin(double invR,
                                                   const float* __restrict__ G6,
                                                   const float* __restrict__ B6) {
    int b = blockIdx.x, e = threadIdx.x;
    double m = g_sum[5][e] * invR;
    double vv = g_sqs[5][e] * invR - m * m;
    float s = G6[e] * rsqrtf((float)vv + 1e-5f);
    float t = B6[e] - (float)m * s;
    float mx = fdec(g_hmaxEnc[b * 1024 + e]);
    float mn = fdec(g_hminEnc[b * 1024 + e]);
    g_gmaxv[b * 1024 + e] = lrelu(s * (s >= 0.f ? mx : mn) + t);
}

// ---------------- gterm[b,o] = sum_e gmax[b,e] * W7[o,e] ---------------------
__global__ __launch_bounds__(512) void dg_gterm_kernel(const float* __restrict__ W7) {
    int b = blockIdx.x, o = threadIdx.x;
    float acc = 0.f;
    for (int e = 0; e < 1024; e++)
        acc += g_gmaxv[b * 1024 + e] * W7[(size_t)o * 1216 + e];
    g_gterm[b * 512 + o] = acc;
}

// ---------------- final classifier (fin7 fused) ------------------------------
__global__ __launch_bounds__(288) void dg_final(const float* __restrict__ W9,
                                                float* __restrict__ out,
                                                double invR,
                                                const float* __restrict__ G8,
                                                const float* __restrict__ B8) {
    __shared__ float a[32 * 257];
    __shared__ float w[9 * 259];
    __shared__ float scS[256], shS[256];
    int tid = threadIdx.x;
    if (tid < 256) {
        double m = g_sum[7][tid] * invR;
        double vv = g_sqs[7][tid] * invR - m * m;
        float sc = G8[tid] * rsqrtf((float)vv + 1e-5f);
        scS[tid] = sc; shS[tid] = B8[tid] - (float)m * sc;
    }
    for (int l = tid; l < 2304; l += 288) {
        int o = l / 256, c = l % 256;
        w[o * 259 + c] = W9[l];
    }
    __syncthreads();
    int r0 = blockIdx.x * 32;
    for (int l = tid; l < 32 * 256; l += 288) {
        int rr = l / 256, c = l % 256;
        float v = g_hB[(size_t)(r0 + rr) * 256 + c];
        a[rr * 257 + c] = lrelu(scS[c] * v + shS[c]);
    }
    __syncthreads();
    int rr = tid / 9, o = tid % 9;
    float acc = 0.f;
    #pragma unroll 16
    for (int c = 0; c < 256; c++) acc += a[rr * 257 + c] * w[o * 259 + c];
    out[(size_t)(r0 + rr) * 9 + o] = acc;
}

// ---------------- host orchestration -----------------------------------------
extern "C" void kernel_launch(void* const* d_in, const int* in_sizes, int n_in,
                              void* d_out, int out_size) {
    const float* x = (const float*)d_in[0];
    const float* W[10] = {0};
    const float* G[9] = {0};
    const float* Bp[9] = {0};
    if (n_in >= 27 && in_sizes[1] == 1) {
        for (int i = 1; i <= 9; i++) W[i] = (const float*)d_in[1 + i];
        for (int i = 1; i <= 8; i++) {
            G[i]  = (const float*)d_in[11 + 2 * (i - 1)];
            Bp[i] = (const float*)d_in[12 + 2 * (i - 1)];
        }
    } else {
        for (int i = 1; i <= 9; i++) W[i] = (const float*)d_in[i];
        for (int i = 1; i <= 8; i++) {
            G[i]  = (const float*)d_in[10 + 2 * (i - 1)];
            Bp[i] = (const float*)d_in[11 + 2 * (i - 1)];
        }
    }
    float* out = (float*)d_out;

    void* tmp;
    cudaGetSymbolAddress(&tmp, g_negd);  float* negd = (float*)tmp;
    cudaGetSymbolAddress(&tmp, g_hA);    float* hA   = (float*)tmp;
    cudaGetSymbolAddress(&tmp, g_hB);    float* hB   = (float*)tmp;
    cudaGetSymbolAddress(&tmp, g_x1);    float* x1   = (float*)tmp;
    cudaGetSymbolAddress(&tmp, g_x2);    float* x2   = (float*)tmp;
    cudaGetSymbolAddress(&tmp, g_x3);    float* x3   = (float*)tmp;

    const int SQ_SMEM = 128 * 133 * 4;                       // 68096
    const int EC_SMEM = (64 * 260 + 64 * 68) * 4;            // 83968
    const int F1_SMEM = (64 * 260 + 64 * 68 + 6 * 260 + 6 * 68) * 4;  // 91840
    cudaFuncSetAttribute(dg_sqdist128sym, cudaFuncAttributeMaxDynamicSharedMemorySize, SQ_SMEM);
    cudaFuncSetAttribute(dg_econv64,   cudaFuncAttributeMaxDynamicSharedMemorySize, EC_SMEM);
    cudaFuncSetAttribute(dg_econv64f1, cudaFuncAttributeMaxDynamicSharedMemorySize, F1_SMEM);
    cudaFuncSetAttribute(dg_econv128,  cudaFuncAttributeMaxDynamicSharedMemorySize, EC_SMEM);

    const double invE = 1.0 / (double)EDGES;
    const double invR = 1.0 / (double)ROWS;
    const int EB  = EDGES / 128;   // conv1s tiles
    const int EB2 = EDGES / 256;   // econv tiles

    dg_zero_kernel<<<32, 256>>>();

    // ---- block 1 (xyz) ----
    dg_knn_small<<<ROWS, 256>>>(x);
    dg_conv1s<<<EB, 256>>>(x, W[1]);
    dg_econv64f1<<<EB2, 256, F1_SMEM>>>(x, W[1], W[2], hB, invE, G[1], Bp[1]);
    dg_maxk<<<ROWS / 4, 256>>>(hB, x1, 1, invE, G[2], Bp[2]);

    // ---- block 2 (x1) ----
    dg_sqdist128sym<<<dim3(NP / 128, NP / 128, BB), 256, SQ_SMEM>>>(x1, negd);
    dg_select_kernel<<<ROWS / 2, 512>>>();
    dg_econv128<<<EB2, 256, EC_SMEM>>>(x1, hA, W[3], 2);
    dg_econv64<<<EB2, 256, EC_SMEM>>>(hA, hB, W[4], 2, 3, invE, G[3], Bp[3]);
    dg_maxk<<<ROWS / 4, 256>>>(hB, x2, 3, invE, G[4], Bp[4]);

    // ---- block 3 (x2) ----
    dg_sqdist128sym<<<dim3(NP / 128, NP / 128, BB), 256, SQ_SMEM>>>(x2, negd);
    dg_select_kernel<<<ROWS / 2, 512>>>();
    dg_econv128<<<EB2, 256, EC_SMEM>>>(x2, hA, W[5], 4);
    dg_maxk<<<ROWS / 4, 256>>>(hA, x3, 4, invE, G[5], Bp[5]);

    // ---- point MLPs (cat fused into A loads) ----
    dg_gemm128<4|8|16|32><<<dim3(8, ROWS / 128), 256>>>(
        nullptr, W[6], 192, hA, 1024, 192, -1, 5, 0.0, 0, 0, x1, x2, x3);
    dg_gmaxfin<<<BB, 1024>>>(invR, G[6], Bp[6]);
    dg_gterm_kernel<<<BB, 512>>>(W[7]);
    dg_gemm128<2|4|32><<<dim3(4, ROWS / 128), 256>>>(
        nullptr, W[7] + 1024, 1216, hA, 512, 192, -1, 6, 0.0, 0, 0, x1, x2, x3);
    dg_gemm128<1|4><<<dim3(2, ROWS / 128), 256>>>(
        hA, W[8], 512, hB, 256, 512, 6, 7, invR, G[7], Bp[7], 0, 0, 0);
    dg_final<<<ROWS / 32, 288>>>(W[9], out, invR, G[8], Bp[8]);
}